// round 9
// baseline (speedup 1.0000x reference)
#include <cuda_runtime.h>
#include <cstdint>
#include <cmath>

#define B_SZ    32768
#define STATE_NN 64
#define HDIM    1024
#define KCODES  256
#define DDIM    128
#define GG      8
#define BG      (B_SZ*GG)      /* 262144 */
#define GD      (GG*DDIM)      /* 1024   */

#define DEC_OFF  1
#define PERP_OFF (1 + B_SZ*STATE_NN)       /* 2097153 */
#define IDX_OFF  (2 + B_SZ*STATE_NN)       /* 2097154 */

typedef unsigned long long u64;

// ---------------- device scratch (no allocations allowed) ----------------
__device__ float g_h1[(size_t)B_SZ*HDIM];
__device__ float g_t2[(size_t)B_SZ*HDIM];
__device__ float g_h2[(size_t)B_SZ*HDIM];
__device__ float g_z [(size_t)B_SZ*GD];
__device__ float g_S [(size_t)BG*KCODES];
__device__ float g_zq[(size_t)B_SZ*GD];
__device__ float g_zn[BG];
__device__ int   g_idx[BG];
__device__ int   g_hist[KCODES];
__device__ float g_cn[KCODES];
__device__ float g_cbT[DDIM*KCODES];
__device__ float g_loss[1];

// ---------------- packed f32x2 helpers ----------------
__device__ __forceinline__ u64 pack2(float lo, float hi){
    u64 r; asm("mov.b64 %0, {%1,%2};" : "=l"(r) : "f"(lo), "f"(hi)); return r;
}
__device__ __forceinline__ void unpack2(u64 v, float &lo, float &hi){
    asm("mov.b64 {%0,%1}, %2;" : "=f"(lo), "=f"(hi) : "l"(v));
}
__device__ __forceinline__ u64 ffma2(u64 a, u64 b, u64 c){
    u64 d; asm("fma.rn.f32x2 %0, %1, %2, %3;" : "=l"(d) : "l"(a), "l"(b), "l"(c)); return d;
}
__device__ __forceinline__ u64 fmul2(u64 a, u64 b){
    u64 d; asm("mul.rn.f32x2 %0, %1, %2;" : "=l"(d) : "l"(a), "l"(b)); return d;
}
__device__ __forceinline__ u64 fadd2(u64 a, u64 b){
    u64 d; asm("add.rn.f32x2 %0, %1, %2;" : "=l"(d) : "l"(a), "l"(b)); return d;
}

// =====================================================================
// fp32 GEMM, FFMA2, R6 fragment layout + 2-stage smem double buffering.
// Arithmetic (per-element k-order) identical to the R6 kernel.
// C = act( A[M,K] @ B[K,N] + bias );  ACT: 0 none, 1 relu.  VEC: float4 stores.
// =====================================================================
template<int BM,int BN,int BK,int TM,int TN,int ACT,int VEC>
__global__ void __launch_bounds__(256,2)
gemm2_k(const float* __restrict__ A, const float* __restrict__ Bm,
        const float* __restrict__ bias, float* __restrict__ C,
        int M, int N, int K)
{
    constexpr int MG = TM/4;                // A row groups
    constexpr int NG = TN/4;                // B col groups
    constexpr int ASTEP = (256/BM)*4;       // k-stride per thread for A loads
    constexpr int ANUM  = BK/ASTEP;         // float4 A loads per tile
    constexpr int BNUM  = (BK*BN)/(256*4);  // float4 B loads per tile

    __shared__ float As[2][BK][BM];         // transposed A tiles
    __shared__ float Bs[2][BK][BN];

    const int tid  = threadIdx.x;
    const int tcol = tid % (BN/TN);
    const int trow = tid / (BN/TN);
    const int aRow0 = blockIdx.y * BM;
    const int bCol0 = blockIdx.x * BN;

    // conflict-free A loader: thread owns row lr, k-offsets ls*4 + i*ASTEP
    const int lr = tid % BM;
    const int ls = tid / BM;

    u64 acc[TM][TN/2];
#pragma unroll
    for (int i=0;i<TM;i++)
#pragma unroll
        for (int j=0;j<TN/2;j++) acc[i][j] = 0ULL;

    // ---- prologue: tile 0 -> stage 0 ----
#pragma unroll
    for (int i=0;i<ANUM;i++) {
        int c0 = ls*4 + i*ASTEP;
        float4 v = *(const float4*)(A + (size_t)(aRow0+lr)*K + c0);
        As[0][c0+0][lr]=v.x; As[0][c0+1][lr]=v.y;
        As[0][c0+2][lr]=v.z; As[0][c0+3][lr]=v.w;
    }
#pragma unroll
    for (int it=0; it<BNUM; ++it) {
        int idx4 = (tid + it*256)*4;
        int r = idx4 / BN, c = idx4 % BN;
        *(float4*)&Bs[0][r][c] = *(const float4*)(Bm + (size_t)r*N + bCol0 + c);
    }
    __syncthreads();

    const int NIT = K/BK;
    for (int itk=0; itk<NIT; ++itk) {
        const int cur = itk & 1, nxt = cur ^ 1;
        const int k1 = (itk+1)*BK;
        float4 avp[ANUM], bvp[BNUM];
        if (itk+1 < NIT) {
#pragma unroll
            for (int i=0;i<ANUM;i++) {
                int c0 = ls*4 + i*ASTEP;
                avp[i] = *(const float4*)(A + (size_t)(aRow0+lr)*K + k1 + c0);
            }
#pragma unroll
            for (int it=0; it<BNUM; ++it) {
                int idx4 = (tid + it*256)*4;
                int r = idx4 / BN, c = idx4 % BN;
                bvp[it] = *(const float4*)(Bm + (size_t)(k1+r)*N + bCol0 + c);
            }
        }
        // ---- compute stage cur (R6-identical inner loop) ----
#pragma unroll
        for (int kk=0; kk<BK; kk++) {
            u64 ar2[TM], br2[TN/2];
#pragma unroll
            for (int h=0; h<MG; h++) {
                float4 av = *(const float4*)&As[cur][kk][h*(BM/2) + trow*4];
                ar2[h*4+0] = pack2(av.x, av.x);
                ar2[h*4+1] = pack2(av.y, av.y);
                ar2[h*4+2] = pack2(av.z, av.z);
                ar2[h*4+3] = pack2(av.w, av.w);
            }
#pragma unroll
            for (int g=0; g<NG; g++) {
                ulonglong2 bv = *(const ulonglong2*)&Bs[cur][kk][g*(BN/2) + tcol*4];
                br2[g*2+0] = bv.x;
                br2[g*2+1] = bv.y;
            }
#pragma unroll
            for (int i=0;i<TM;i++)
#pragma unroll
                for (int j=0;j<TN/2;j++)
                    acc[i][j] = ffma2(ar2[i], br2[j], acc[i][j]);
        }
        // ---- stage next tile ----
        if (itk+1 < NIT) {
#pragma unroll
            for (int i=0;i<ANUM;i++) {
                int c0 = ls*4 + i*ASTEP;
                As[nxt][c0+0][lr]=avp[i].x; As[nxt][c0+1][lr]=avp[i].y;
                As[nxt][c0+2][lr]=avp[i].z; As[nxt][c0+3][lr]=avp[i].w;
            }
#pragma unroll
            for (int it=0; it<BNUM; ++it) {
                int idx4 = (tid + it*256)*4;
                int r = idx4 / BN, c = idx4 % BN;
                *(float4*)&Bs[nxt][r][c] = bvp[it];
            }
        }
        __syncthreads();
    }

    // ---- epilogue (R6-identical) ----
#pragma unroll
    for (int h=0; h<MG; h++) {
#pragma unroll
        for (int i=0;i<4;i++) {
            size_t r = (size_t)aRow0 + h*(BM/2) + trow*4 + i;
#pragma unroll
            for (int g=0; g<NG; g++) {
                int c0 = bCol0 + g*(BN/2) + tcol*4;
                float v0,v1,v2,v3;
                unpack2(acc[h*4+i][g*2+0], v0, v1);
                unpack2(acc[h*4+i][g*2+1], v2, v3);
                v0 += bias[c0+0]; v1 += bias[c0+1];
                v2 += bias[c0+2]; v3 += bias[c0+3];
                if (ACT == 1) {
                    v0 = fmaxf(v0,0.f); v1 = fmaxf(v1,0.f);
                    v2 = fmaxf(v2,0.f); v3 = fmaxf(v3,0.f);
                }
                if (VEC) {
                    float4 o; o.x=v0; o.y=v1; o.z=v2; o.w=v3;
                    *(float4*)(C + r*N + c0) = o;
                } else {
                    C[r*N + c0+0]=v0; C[r*N + c0+1]=v1;
                    C[r*N + c0+2]=v2; C[r*N + c0+3]=v3;
                }
            }
        }
    }
}

// =====================================================================
// VQ-score GEMM: packed Kahan dot (compute byte-identical to R4/R6),
// now with 2-stage smem double buffering (load scheduling only).
// S = fl( fl(zn[r] + cn[c]) - 2*dot ) on the reference rounding grid.
// =====================================================================
template<int BM,int BN,int BK,int TM,int TN>
__global__ void __launch_bounds__(256,2)
gemm_vq2_k(const float* __restrict__ A, const float* __restrict__ Bm,
           const float* __restrict__ cn, const float* __restrict__ zn,
           float* __restrict__ C, int M, int N, int K)
{
    constexpr int ANUM = (BM*BK)/(256*4);
    constexpr int BNUM = (BK*BN)/(256*4);
    __shared__ float As[2][BK][BM];
    __shared__ float Bs[2][BK][BN];

    const int tid  = threadIdx.x;
    const int tcol = tid % (BN/TN);
    const int trow = tid / (BN/TN);
    const int aRow0 = blockIdx.y * BM;
    const int bCol0 = blockIdx.x * BN;
    const u64 SGN = 0x8000000080000000ULL;

    u64 s[TM][TN/2], e[TM][TN/2];
#pragma unroll
    for (int i=0;i<TM;i++)
#pragma unroll
        for (int j=0;j<TN/2;j++) { s[i][j]=0ULL; e[i][j]=0ULL; }

    // ---- prologue: tile 0 -> stage 0 ----
#pragma unroll
    for (int it=0; it<ANUM; ++it) {
        int idx4 = (tid + it*256)*4;
        int r = idx4 / BK, c = idx4 % BK;
        float4 v = *(const float4*)(A + (size_t)(aRow0+r)*K + c);
        As[0][c+0][r]=v.x; As[0][c+1][r]=v.y; As[0][c+2][r]=v.z; As[0][c+3][r]=v.w;
    }
#pragma unroll
    for (int it=0; it<BNUM; ++it) {
        int idx4 = (tid + it*256)*4;
        int r = idx4 / BN, c = idx4 % BN;
        *(float4*)&Bs[0][r][c] = *(const float4*)(Bm + (size_t)r*N + bCol0 + c);
    }
    __syncthreads();

    const int NIT = K/BK;
    for (int itk=0; itk<NIT; ++itk) {
        const int cur = itk & 1, nxt = cur ^ 1;
        const int k1 = (itk+1)*BK;
        float4 avp[ANUM], bvp[BNUM];
        if (itk+1 < NIT) {
#pragma unroll
            for (int it=0; it<ANUM; ++it) {
                int idx4 = (tid + it*256)*4;
                int r = idx4 / BK, c = idx4 % BK;
                avp[it] = *(const float4*)(A + (size_t)(aRow0+r)*K + k1 + c);
            }
#pragma unroll
            for (int it=0; it<BNUM; ++it) {
                int idx4 = (tid + it*256)*4;
                int r = idx4 / BN, c = idx4 % BN;
                bvp[it] = *(const float4*)(Bm + (size_t)(k1+r)*N + bCol0 + c);
            }
        }
        // ---- compute stage cur (R4/R6-identical Kahan sequence) ----
#pragma unroll
        for (int kk=0; kk<BK; kk++) {
            u64 ar2[TM], br2[TN/2];
#pragma unroll
            for (int i=0;i<TM;i++) {
                float a = As[cur][kk][trow*TM+i];
                ar2[i] = pack2(a, a);
            }
            {
                ulonglong2 b2 = *(const ulonglong2*)&Bs[cur][kk][tcol*TN];
                br2[0] = b2.x;
                br2[1] = b2.y;
            }
#pragma unroll
            for (int i=0;i<TM;i++)
#pragma unroll
                for (int j=0;j<TN/2;j++) {
                    u64 x  = fmul2(ar2[i], br2[j]);
                    u64 t  = fadd2(s[i][j], x);
                    u64 c1 = fadd2(fadd2(s[i][j], t ^ SGN), x);  // (s-t)+x
                    e[i][j] = fadd2(e[i][j], c1);
                    s[i][j] = t;
                }
        }
        // ---- stage next tile ----
        if (itk+1 < NIT) {
#pragma unroll
            for (int it=0; it<ANUM; ++it) {
                int idx4 = (tid + it*256)*4;
                int r = idx4 / BK, c = idx4 % BK;
                As[nxt][c+0][r]=avp[it].x; As[nxt][c+1][r]=avp[it].y;
                As[nxt][c+2][r]=avp[it].z; As[nxt][c+3][r]=avp[it].w;
            }
#pragma unroll
            for (int it=0; it<BNUM; ++it) {
                int idx4 = (tid + it*256)*4;
                int r = idx4 / BN, c = idx4 % BN;
                *(float4*)&Bs[nxt][r][c] = bvp[it];
            }
        }
        __syncthreads();
    }
#pragma unroll
    for (int i=0;i<TM;i++) {
        size_t r = (size_t)aRow0 + trow*TM + i;
        float zr = zn[r];
#pragma unroll
        for (int j=0;j<TN/2;j++) {
            int c = bCol0 + tcol*TN + 2*j;
            float s0,s1,e0,e1;
            unpack2(s[i][j], s0, s1);
            unpack2(e[i][j], e0, e1);
            float dot0 = __fadd_rn(s0, e0);
            float dot1 = __fadd_rn(s1, e1);
            float t0 = __fadd_rn(zr, cn[c]);
            float t1 = __fadd_rn(zr, cn[c+1]);
            C[r*N + c]   = __fadd_rn(t0, __fmul_rn(-2.f, dot0));
            C[r*N + c+1] = __fadd_rn(t1, __fmul_rn(-2.f, dot1));
        }
    }
}

// ---------------- LayerNorm + ReLU (row of 1024, 256 threads) ----------------
__global__ void ln_relu_k(const float* __restrict__ X, const float* __restrict__ gam,
                          const float* __restrict__ bet, float* __restrict__ Y)
{
    const int row = blockIdx.x;
    const int t   = threadIdx.x;
    __shared__ float red[8];
    __shared__ float s_mu, s_rs;

    float4 v = *(const float4*)(X + (size_t)row*HDIM + t*4);

    float s = __fadd_rn(__fadd_rn(v.x,v.y), __fadd_rn(v.z,v.w));
#pragma unroll
    for (int o=16;o;o>>=1) s = __fadd_rn(s, __shfl_xor_sync(~0u, s, o));
    if ((t&31)==0) red[t>>5] = s;
    __syncthreads();
    if (t==0) {
        float a = __fadd_rn(__fadd_rn(red[0],red[1]), __fadd_rn(red[2],red[3]));
        float b = __fadd_rn(__fadd_rn(red[4],red[5]), __fadd_rn(red[6],red[7]));
        s_mu = __fadd_rn(a,b) * (1.0f/HDIM);
    }
    __syncthreads();
    const float mu = s_mu;

    float dx=__fadd_rn(v.x,-mu), dy=__fadd_rn(v.y,-mu),
          dz=__fadd_rn(v.z,-mu), dw=__fadd_rn(v.w,-mu);
    float sq = __fadd_rn(__fadd_rn(__fmul_rn(dx,dx),__fmul_rn(dy,dy)),
                         __fadd_rn(__fmul_rn(dz,dz),__fmul_rn(dw,dw)));
#pragma unroll
    for (int o=16;o;o>>=1) sq = __fadd_rn(sq, __shfl_xor_sync(~0u, sq, o));
    if ((t&31)==0) red[t>>5] = sq;
    __syncthreads();
    if (t==0) {
        float a = __fadd_rn(__fadd_rn(red[0],red[1]), __fadd_rn(red[2],red[3]));
        float b = __fadd_rn(__fadd_rn(red[4],red[5]), __fadd_rn(red[6],red[7]));
        s_rs = rsqrtf(__fadd_rn(a,b)*(1.0f/HDIM) + 1e-5f);
    }
    __syncthreads();
    const float rs = s_rs;

    float4 g4 = *(const float4*)(gam + t*4);
    float4 b4 = *(const float4*)(bet + t*4);
    float4 o;
    o.x = fmaxf(__fadd_rn(__fmul_rn(__fmul_rn(dx,rs),g4.x), b4.x), 0.f);
    o.y = fmaxf(__fadd_rn(__fmul_rn(__fmul_rn(dy,rs),g4.y), b4.y), 0.f);
    o.z = fmaxf(__fadd_rn(__fmul_rn(__fmul_rn(dz,rs),g4.z), b4.z), 0.f);
    o.w = fmaxf(__fadd_rn(__fmul_rn(__fmul_rn(dw,rs),g4.w), b4.w), 0.f);
    *(float4*)(Y + (size_t)row*HDIM + t*4) = o;
}

// ---------------- |z|^2 per VQ row (warp per row) ----------------
__global__ void znorm_k(const float* __restrict__ z, float* __restrict__ zn)
{
    int row  = blockIdx.x*8 + (threadIdx.x >> 5);
    int lane = threadIdx.x & 31;
    float4 v = *(const float4*)(z + (size_t)row*DDIM + lane*4);
    float s = __fadd_rn(__fadd_rn(__fmul_rn(v.x,v.x), __fmul_rn(v.y,v.y)),
                        __fadd_rn(__fmul_rn(v.z,v.z), __fmul_rn(v.w,v.w)));
#pragma unroll
    for (int o=16;o;o>>=1) s = __fadd_rn(s, __shfl_xor_sync(~0u, s, o));
    if (lane == 0) zn[row] = s;
}

// ---------------- codebook prep: |c_k|^2 (double acc) and transpose ----------------
__global__ void prep_k(const float* __restrict__ cb, float* __restrict__ cn,
                       float* __restrict__ cbT)
{
    int k = threadIdx.x;       // 256 threads, 1 block
    double s = 0.0;
    for (int d0=0; d0<DDIM; d0++) {
        float v = cb[k*DDIM + d0];
        s += (double)v * (double)v;
        cbT[d0*KCODES + k] = v;
    }
    cn[k] = (float)s;
}

__global__ void init_k(float* loss, int* hist)
{
    int t = threadIdx.x;
    if (t == 0) *loss = 0.f;
    if (t < KCODES) hist[t] = 0;
}

// ---------------- argmin per row (warp per row, first-min tie-break) ----------------
__global__ void argmin_k(const float* __restrict__ S, int* __restrict__ idx,
                         float* __restrict__ idx_f)
{
    int row  = blockIdx.x*8 + (threadIdx.x >> 5);
    int lane = threadIdx.x & 31;
    const float* sr = S + (size_t)row*KCODES;
    float bv = 3.4e38f; int bk = 0;
#pragma unroll
    for (int j=0;j<8;j++) {
        int k = lane + j*32;
        float v = sr[k];
        if (v < bv) { bv = v; bk = k; }
    }
#pragma unroll
    for (int o=16;o;o>>=1) {
        float ov = __shfl_xor_sync(~0u, bv, o);
        int   ok = __shfl_xor_sync(~0u, bk, o);
        if (ov < bv || (ov == bv && ok < bk)) { bv = ov; bk = ok; }
    }
    if (lane == 0) { idx[row] = bk; idx_f[row] = (float)bk; }
}

// ------ gather z_q, straight-through zq_st = fl(z + fl(zq - z)), loss, hist ------
__global__ void gather_k(const float* __restrict__ z, const float* __restrict__ cb,
                         const int* __restrict__ idx, float* __restrict__ zq,
                         float* __restrict__ loss, int* __restrict__ hist)
{
    int b = blockIdx.x;
    int t = threadIdx.x;   // 256
    __shared__ int   sidx[GG];
    __shared__ float red[8];
    if (t < GG) {
        int k = idx[b*GG + t];
        sidx[t] = k;
        atomicAdd(&hist[k], 1);
    }
    __syncthreads();
    int g = (t*4) >> 7;
    int e = (t*4) & 127;
    float4 c  = *(const float4*)(cb + (size_t)sidx[g]*DDIM + e);
    float4 zz = *(const float4*)(z  + (size_t)b*GD + t*4);
    float dx=__fadd_rn(c.x,-zz.x), dy=__fadd_rn(c.y,-zz.y),
          dz=__fadd_rn(c.z,-zz.z), dw=__fadd_rn(c.w,-zz.w);
    float4 st;
    st.x = __fadd_rn(zz.x, dx);
    st.y = __fadd_rn(zz.y, dy);
    st.z = __fadd_rn(zz.z, dz);
    st.w = __fadd_rn(zz.w, dw);
    *(float4*)(zq + (size_t)b*GD + t*4) = st;
    float s = dx*dx+dy*dy+dz*dz+dw*dw;
#pragma unroll
    for (int o=16;o;o>>=1) s += __shfl_xor_sync(~0u, s, o);
    if ((t&31)==0) red[t>>5] = s;
    __syncthreads();
    if (t==0) {
        float tot=0.f;
#pragma unroll
        for (int i=0;i<8;i++) tot += red[i];
        atomicAdd(loss, tot);
    }
}

// ---------------- finalize scalars ----------------
__global__ void finalize_k(const int* __restrict__ hist, const float* __restrict__ loss,
                           float* __restrict__ out)
{
    int t = threadIdx.x;   // 256
    __shared__ float red[8];
    float e = (float)hist[t] / (float)BG;
    float s = e * logf(e + 1e-10f);
#pragma unroll
    for (int o=16;o;o>>=1) s += __shfl_xor_sync(~0u, s, o);
    if ((t&31)==0) red[t>>5] = s;
    __syncthreads();
    if (t==0) {
        float tot=0.f;
#pragma unroll
        for (int i=0;i<8;i++) tot += red[i];
        out[PERP_OFF] = expf(-tot);
        out[0] = 1.25f * loss[0] / 33554432.0f;   // (1+BETA)*mean over B*G*D
    }
}

// ---------------- host launcher ----------------
extern "C" void kernel_launch(void* const* d_in, const int* in_sizes, int n_in,
                              void* d_out, int out_size)
{
    const float* x      = (const float*)d_in[0];
    const float* enc_w1 = (const float*)d_in[1];
    const float* enc_b1 = (const float*)d_in[2];
    const float* enc_w2 = (const float*)d_in[3];
    const float* enc_b2 = (const float*)d_in[4];
    const float* ln_g   = (const float*)d_in[5];
    const float* ln_b   = (const float*)d_in[6];
    const float* enc_w3 = (const float*)d_in[7];
    const float* enc_b3 = (const float*)d_in[8];
    const float* enc_w4 = (const float*)d_in[9];
    const float* enc_b4 = (const float*)d_in[10];
    const float* cb     = (const float*)d_in[11];
    const float* dec_w1 = (const float*)d_in[12];
    const float* dec_b1 = (const float*)d_in[13];
    const float* dec_w2 = (const float*)d_in[14];
    const float* dec_b2 = (const float*)d_in[15];
    const float* dec_w3 = (const float*)d_in[16];
    const float* dec_b3 = (const float*)d_in[17];
    float* out = (float*)d_out;

    static float *p_h1=nullptr,*p_t2,*p_h2,*p_z,*p_S,*p_zq,*p_zn,*p_cn,*p_cbT,*p_loss;
    static int *p_idx,*p_hist;
    if (!p_h1) {
        cudaGetSymbolAddress((void**)&p_h1,  g_h1);
        cudaGetSymbolAddress((void**)&p_t2,  g_t2);
        cudaGetSymbolAddress((void**)&p_h2,  g_h2);
        cudaGetSymbolAddress((void**)&p_z,   g_z);
        cudaGetSymbolAddress((void**)&p_S,   g_S);
        cudaGetSymbolAddress((void**)&p_zq,  g_zq);
        cudaGetSymbolAddress((void**)&p_zn,  g_zn);
        cudaGetSymbolAddress((void**)&p_cn,  g_cn);
        cudaGetSymbolAddress((void**)&p_cbT, g_cbT);
        cudaGetSymbolAddress((void**)&p_loss,g_loss);
        cudaGetSymbolAddress((void**)&p_idx, g_idx);
        cudaGetSymbolAddress((void**)&p_hist,g_hist);
    }

    prep_k<<<1,256>>>(cb, p_cn, p_cbT);
    init_k<<<1,256>>>(p_loss, p_hist);

    // ---- encoder (fp32, FFMA2, dbuf) ----
    gemm2_k<128,128,16,8,8,1,1><<<dim3(HDIM/128, B_SZ/128), 256>>>(x,    enc_w1, enc_b1, p_h1, B_SZ, HDIM, STATE_NN);
    gemm2_k<128,128,16,8,8,0,1><<<dim3(HDIM/128, B_SZ/128), 256>>>(p_h1, enc_w2, enc_b2, p_t2, B_SZ, HDIM, HDIM);
    ln_relu_k<<<B_SZ,256>>>(p_t2, ln_g, ln_b, p_h2);
    gemm2_k<128,128,16,8,8,1,1><<<dim3(HDIM/128, B_SZ/128), 256>>>(p_h2, enc_w3, enc_b3, p_h1, B_SZ, HDIM, HDIM);
    gemm2_k<128,128,16,8,8,0,1><<<dim3(DDIM/128, BG/128),   256>>>(p_h1, enc_w4, enc_b4, p_z,  BG,   DDIM, DDIM);

    // ---- VQ: S on the reference rounding grid (R4-exact compute), argmin ----
    znorm_k<<<BG/8,256>>>(p_z, p_zn);
    gemm_vq2_k<128,64,16,8,4><<<dim3(KCODES/64, BG/128), 256>>>(p_z, p_cbT, p_cn, p_zn, p_S, BG, KCODES, DDIM);
    argmin_k<<<BG/8,256>>>(p_S, p_idx, out + IDX_OFF);
    gather_k<<<B_SZ,256>>>(p_z, cb, p_idx, p_zq, p_loss, p_hist);
    finalize_k<<<1,256>>>(p_hist, p_loss, out);

    // ---- decoder (fp32, FFMA2, dbuf) ----
    gemm2_k<128,128,16,8,8,1,1><<<dim3(HDIM/128, B_SZ/128), 256>>>(p_zq, dec_w1, dec_b1, p_h2, B_SZ, HDIM, HDIM);
    gemm2_k<128,128,16,8,8,1,1><<<dim3(HDIM/128, B_SZ/128), 256>>>(p_h2, dec_w2, dec_b2, p_t2, B_SZ, HDIM, HDIM);
    gemm2_k<128, 64,16,8,4,0,0><<<dim3(1,        B_SZ/128), 256>>>(p_t2, dec_w3, dec_b3, out + DEC_OFF, B_SZ, STATE_NN, HDIM);
}

// round 13
// speedup vs baseline: 1.3439x; 1.3439x over previous
#include <cuda_runtime.h>
#include <cuda_bf16.h>
#include <cstdint>
#include <cmath>

#define B_SZ    32768
#define STATE_NN 64
#define HDIM    1024
#define KCODES  256
#define DDIM    128
#define GG      8
#define BG      (B_SZ*GG)
#define GD      (GG*DDIM)
#define DEC_OFF  1
#define PERP_OFF (1 + B_SZ*STATE_NN)
#define IDX_OFF  (2 + B_SZ*STATE_NN)

typedef unsigned long long u64;
typedef __nv_bfloat16 bf16;

// ---------------- device scratch ----------------
__device__ float g_h1[(size_t)B_SZ*HDIM];
__device__ float g_t2[(size_t)B_SZ*HDIM];
__device__ float g_h2[(size_t)B_SZ*HDIM];
__device__ float g_z [(size_t)B_SZ*GD];
__device__ float g_S [(size_t)BG*KCODES];
__device__ float g_zn[BG];
__device__ int   g_idx[BG];
__device__ int   g_hist[KCODES];
__device__ float g_cn[KCODES];
__device__ float g_cbT[DDIM*KCODES];
__device__ float g_loss[1];

// bf16 buffers for the HMMA decoder
__device__ __align__(16) bf16 g_bA0[(size_t)B_SZ*HDIM];
__device__ __align__(16) bf16 g_bA1[(size_t)B_SZ*HDIM];
__device__ __align__(16) bf16 g_bA2[(size_t)B_SZ*HDIM];
__device__ __align__(16) bf16 g_bB0[(size_t)B_SZ*HDIM];
__device__ __align__(16) bf16 g_bB1[(size_t)B_SZ*HDIM];
__device__ __align__(16) bf16 g_bB2[(size_t)B_SZ*HDIM];

#define OFF_D1 0
#define OFF_D2 1048576
#define OFF_D3 2097152
#define WT_TOT 2162688
__device__ __align__(16) bf16 g_wt0[WT_TOT];
__device__ __align__(16) bf16 g_wt1[WT_TOT];
__device__ __align__(16) bf16 g_wt2[WT_TOT];

// ---------------- helpers ----------------
__device__ __forceinline__ u64 pack2(float lo, float hi){
    u64 r; asm("mov.b64 %0, {%1,%2};" : "=l"(r) : "f"(lo), "f"(hi)); return r; }
__device__ __forceinline__ void unpack2(u64 v, float &lo, float &hi){
    asm("mov.b64 {%0,%1}, %2;" : "=f"(lo), "=f"(hi) : "l"(v)); }
__device__ __forceinline__ u64 ffma2(u64 a, u64 b, u64 c){
    u64 d; asm("fma.rn.f32x2 %0, %1, %2, %3;" : "=l"(d) : "l"(a), "l"(b), "l"(c)); return d; }
__device__ __forceinline__ u64 fmul2(u64 a, u64 b){
    u64 d; asm("mul.rn.f32x2 %0, %1, %2;" : "=l"(d) : "l"(a), "l"(b)); return d; }
__device__ __forceinline__ u64 fadd2(u64 a, u64 b){
    u64 d; asm("add.rn.f32x2 %0, %1, %2;" : "=l"(d) : "l"(a), "l"(b)); return d; }
__device__ __forceinline__ uint32_t smem_u32(const void* p){
    uint32_t a; asm("{ .reg .u64 t; cvta.to.shared.u64 t, %1; cvt.u32.u64 %0, t; }" : "=r"(a) : "l"(p));
    return a; }
__device__ __forceinline__ void split3(float v, bf16 &h, bf16 &m, bf16 &l){
    h = __float2bfloat16(v);
    float r1 = v - __bfloat162float(h);
    m = __float2bfloat16(r1);
    l = __float2bfloat16(r1 - __bfloat162float(m)); }
__device__ __forceinline__ void wsplit2(bf16* H, bf16* M, bf16* L, size_t go, float a, float b){
    bf16 h0,m0,l0,h1,m1,l1; split3(a,h0,m0,l0); split3(b,h1,m1,l1);
    __nv_bfloat162 p;
    p.x=h0; p.y=h1; *(__nv_bfloat162*)(H+go)=p;
    p.x=m0; p.y=m1; *(__nv_bfloat162*)(M+go)=p;
    p.x=l0; p.y=l1; *(__nv_bfloat162*)(L+go)=p; }

#define CP16(dst, src) asm volatile("cp.async.cg.shared.global [%0], [%1], 16;" :: "r"(dst), "l"(src) : "memory")
#define CPCOMMIT       asm volatile("cp.async.commit_group;" ::: "memory")
#define CPWAIT0        asm volatile("cp.async.wait_group 0;" ::: "memory")
__device__ __forceinline__ void ldsm4(uint32_t &r0,uint32_t &r1,uint32_t &r2,uint32_t &r3,uint32_t a){
    asm volatile("ldmatrix.sync.aligned.m8n8.x4.shared.b16 {%0,%1,%2,%3}, [%4];"
        : "=r"(r0),"=r"(r1),"=r"(r2),"=r"(r3) : "r"(a)); }
__device__ __forceinline__ void mma16816(float* c, const uint32_t* a, uint32_t b0, uint32_t b1){
    asm volatile("mma.sync.aligned.m16n8k16.row.col.f32.bf16.bf16.f32 "
        "{%0,%1,%2,%3},{%4,%5,%6,%7},{%8,%9},{%0,%1,%2,%3};"
        : "+f"(c[0]),"+f"(c[1]),"+f"(c[2]),"+f"(c[3])
        : "r"(a[0]),"r"(a[1]),"r"(a[2]),"r"(a[3]), "r"(b0),"r"(b1)); }
#define SWO(r,c) ((r)*64 + (((c) ^ (((r)>>1)&3))<<4))

// =====================================================================
// fp32 GEMM (BYTE-IDENTICAL to R8 pass): FFMA2, R6 fragments, dbuf.
// =====================================================================
template<int BM,int BN,int BK,int TM,int TN,int ACT,int VEC>
__global__ void __launch_bounds__(256,2)
gemm2_k(const float* __restrict__ A, const float* __restrict__ Bm,
        const float* __restrict__ bias, float* __restrict__ C,
        int M, int N, int K)
{
    constexpr int MG = TM/4;
    constexpr int NG = TN/4;
    constexpr int ASTEP = (256/BM)*4;
    constexpr int ANUM  = BK/ASTEP;
    constexpr int BNUM  = (BK*BN)/(256*4);

    __shared__ float As[2][BK][BM];
    __shared__ float Bs[2][BK][BN];

    const int tid  = threadIdx.x;
    const int tcol = tid % (BN/TN);
    const int trow = tid / (BN/TN);
    const int aRow0 = blockIdx.y * BM;
    const int bCol0 = blockIdx.x * BN;
    const int lr = tid % BM;
    const int ls = tid / BM;

    u64 acc[TM][TN/2];
#pragma unroll
    for (int i=0;i<TM;i++)
#pragma unroll
        for (int j=0;j<TN/2;j++) acc[i][j] = 0ULL;

#pragma unroll
    for (int i=0;i<ANUM;i++) {
        int c0 = ls*4 + i*ASTEP;
        float4 v = *(const float4*)(A + (size_t)(aRow0+lr)*K + c0);
        As[0][c0+0][lr]=v.x; As[0][c0+1][lr]=v.y;
        As[0][c0+2][lr]=v.z; As[0][c0+3][lr]=v.w;
    }
#pragma unroll
    for (int it=0; it<BNUM; ++it) {
        int idx4 = (tid + it*256)*4;
        int r = idx4 / BN, c = idx4 % BN;
        *(float4*)&Bs[0][r][c] = *(const float4*)(Bm + (size_t)r*N + bCol0 + c);
    }
    __syncthreads();

    const int NIT = K/BK;
    for (int itk=0; itk<NIT; ++itk) {
        const int cur = itk & 1, nxt = cur ^ 1;
        const int k1 = (itk+1)*BK;
        float4 avp[ANUM], bvp[BNUM];
        if (itk+1 < NIT) {
#pragma unroll
            for (int i=0;i<ANUM;i++) {
                int c0 = ls*4 + i*ASTEP;
                avp[i] = *(const float4*)(A + (size_t)(aRow0+lr)*K + k1 + c0);
            }
#pragma unroll
            for (int it=0; it<BNUM; ++it) {
                int idx4 = (tid + it*256)*4;
                int r = idx4 / BN, c = idx4 % BN;
                bvp[it] = *(const float4*)(Bm + (size_t)(k1+r)*N + bCol0 + c);
            }
        }
#pragma unroll
        for (int kk=0; kk<BK; kk++) {
            u64 ar2[TM], br2[TN/2];
#pragma unroll
            for (int h=0; h<MG; h++) {
                float4 av = *(const float4*)&As[cur][kk][h*(BM/2) + trow*4];
                ar2[h*4+0] = pack2(av.x, av.x);
                ar2[h*4+1] = pack2(av.y, av.y);
                ar2[h*4+2] = pack2(av.z, av.z);
                ar2[h*4+3] = pack2(av.w, av.w);
            }
#pragma unroll
            for (int g=0; g<NG; g++) {
                ulonglong2 bv = *(const ulonglong2*)&Bs[cur][kk][g*(BN/2) + tcol*4];
                br2[g*2+0] = bv.x;
                br2[g*2+1] = bv.y;
            }
#pragma unroll
            for (int i=0;i<TM;i++)
#pragma unroll
                for (int j=0;j<TN/2;j++)
                    acc[i][j] = ffma2(ar2[i], br2[j], acc[i][j]);
        }
        if (itk+1 < NIT) {
#pragma unroll
            for (int i=0;i<ANUM;i++) {
                int c0 = ls*4 + i*ASTEP;
                As[nxt][c0+0][lr]=avp[i].x; As[nxt][c0+1][lr]=avp[i].y;
                As[nxt][c0+2][lr]=avp[i].z; As[nxt][c0+3][lr]=avp[i].w;
            }
#pragma unroll
            for (int it=0; it<BNUM; ++it) {
                int idx4 = (tid + it*256)*4;
                int r = idx4 / BN, c = idx4 % BN;
                *(float4*)&Bs[nxt][r][c] = bvp[it];
            }
        }
        __syncthreads();
    }
#pragma unroll
    for (int h=0; h<MG; h++) {
#pragma unroll
        for (int i=0;i<4;i++) {
            size_t r = (size_t)aRow0 + h*(BM/2) + trow*4 + i;
#pragma unroll
            for (int g=0; g<NG; g++) {
                int c0 = bCol0 + g*(BN/2) + tcol*4;
                float v0,v1,v2,v3;
                unpack2(acc[h*4+i][g*2+0], v0, v1);
                unpack2(acc[h*4+i][g*2+1], v2, v3);
                v0 += bias[c0+0]; v1 += bias[c0+1];
                v2 += bias[c0+2]; v3 += bias[c0+3];
                if (ACT == 1) {
                    v0 = fmaxf(v0,0.f); v1 = fmaxf(v1,0.f);
                    v2 = fmaxf(v2,0.f); v3 = fmaxf(v3,0.f);
                }
                if (VEC) {
                    float4 o; o.x=v0; o.y=v1; o.z=v2; o.w=v3;
                    *(float4*)(C + r*N + c0) = o;
                } else {
                    C[r*N + c0+0]=v0; C[r*N + c0+1]=v1;
                    C[r*N + c0+2]=v2; C[r*N + c0+3]=v3;
                }
            }
        }
    }
}

// =====================================================================
// VQ-score GEMM (byte-identical compute to R8 pass).
// =====================================================================
template<int BM,int BN,int BK,int TM,int TN>
__global__ void __launch_bounds__(256,2)
gemm_vq2_k(const float* __restrict__ A, const float* __restrict__ Bm,
           const float* __restrict__ cn, const float* __restrict__ zn,
           float* __restrict__ C, int M, int N, int K)
{
    constexpr int ANUM = (BM*BK)/(256*4);
    constexpr int BNUM = (BK*BN)/(256*4);
    __shared__ float As[2][BK][BM];
    __shared__ float Bs[2][BK][BN];

    const int tid  = threadIdx.x;
    const int tcol = tid % (BN/TN);
    const int trow = tid / (BN/TN);
    const int aRow0 = blockIdx.y * BM;
    const int bCol0 = blockIdx.x * BN;
    const u64 SGN = 0x8000000080000000ULL;

    u64 s[TM][TN/2], e[TM][TN/2];
#pragma unroll
    for (int i=0;i<TM;i++)
#pragma unroll
        for (int j=0;j<TN/2;j++) { s[i][j]=0ULL; e[i][j]=0ULL; }

#pragma unroll
    for (int it=0; it<ANUM; ++it) {
        int idx4 = (tid + it*256)*4;
        int r = idx4 / BK, c = idx4 % BK;
        float4 v = *(const float4*)(A + (size_t)(aRow0+r)*K + c);
        As[0][c+0][r]=v.x; As[0][c+1][r]=v.y; As[0][c+2][r]=v.z; As[0][c+3][r]=v.w;
    }
#pragma unroll
    for (int it=0; it<BNUM; ++it) {
        int idx4 = (tid + it*256)*4;
        int r = idx4 / BN, c = idx4 % BN;
        *(float4*)&Bs[0][r][c] = *(const float4*)(Bm + (size_t)r*N + bCol0 + c);
    }
    __syncthreads();

    const int NIT = K/BK;
    for (int itk=0; itk<NIT; ++itk) {
        const int cur = itk & 1, nxt = cur ^ 1;
        const int k1 = (itk+1)*BK;
        float4 avp[ANUM], bvp[BNUM];
        if (itk+1 < NIT) {
#pragma unroll
            for (int it=0; it<ANUM; ++it) {
                int idx4 = (tid + it*256)*4;
                int r = idx4 / BK, c = idx4 % BK;
                avp[it] = *(const float4*)(A + (size_t)(aRow0+r)*K + k1 + c);
            }
#pragma unroll
            for (int it=0; it<BNUM; ++it) {
                int idx4 = (tid + it*256)*4;
                int r = idx4 / BN, c = idx4 % BN;
                bvp[it] = *(const float4*)(Bm + (size_t)(k1+r)*N + bCol0 + c);
            }
        }
#pragma unroll
        for (int kk=0; kk<BK; kk++) {
            u64 ar2[TM], br2[TN/2];
#pragma unroll
            for (int i=0;i<TM;i++) {
                float a = As[cur][kk][trow*TM+i];
                ar2[i] = pack2(a, a);
            }
            {
                ulonglong2 b2 = *(const ulonglong2*)&Bs[cur][kk][tcol*TN];
                br2[0] = b2.x;
                br2[1] = b2.y;
            }
#pragma unroll
            for (int i=0;i<TM;i++)
#pragma unroll
                for (int j=0;j<TN/2;j++) {
                    u64 x  = fmul2(ar2[i], br2[j]);
                    u64 t  = fadd2(s[i][j], x);
                    u64 c1 = fadd2(fadd2(s[i][j], t ^ SGN), x);
                    e[i][j] = fadd2(e[i][j], c1);
                    s[i][j] = t;
                }
        }
        if (itk+1 < NIT) {
#pragma unroll
            for (int it=0; it<ANUM; ++it) {
                int idx4 = (tid + it*256)*4;
                int r = idx4 / BK, c = idx4 % BK;
                As[nxt][c+0][r]=avp[it].x; As[nxt][c+1][r]=avp[it].y;
                As[nxt][c+2][r]=avp[it].z; As[nxt][c+3][r]=avp[it].w;
            }
#pragma unroll
            for (int it=0; it<BNUM; ++it) {
                int idx4 = (tid + it*256)*4;
                int r = idx4 / BN, c = idx4 % BN;
                *(float4*)&Bs[nxt][r][c] = bvp[it];
            }
        }
        __syncthreads();
    }
#pragma unroll
    for (int i=0;i<TM;i++) {
        size_t r = (size_t)aRow0 + trow*TM + i;
        float zr = zn[r];
#pragma unroll
        for (int j=0;j<TN/2;j++) {
            int c = bCol0 + tcol*TN + 2*j;
            float s0,s1,e0,e1;
            unpack2(s[i][j], s0, s1);
            unpack2(e[i][j], e0, e1);
            float dot0 = __fadd_rn(s0, e0);
            float dot1 = __fadd_rn(s1, e1);
            float t0 = __fadd_rn(zr, cn[c]);
            float t1 = __fadd_rn(zr, cn[c+1]);
            C[r*N + c]   = __fadd_rn(t0, __fmul_rn(-2.f, dot0));
            C[r*N + c+1] = __fadd_rn(t1, __fmul_rn(-2.f, dot1));
        }
    }
}

// =====================================================================
// HMMA decoder GEMM (validated in R11/R12): 3-product bf16 split.
// OUTM: 1 f32 scalar, 2 bf16 h/m/l splits.
// =====================================================================
template<int BN_, int ACT, int OUTM>
__global__ void __launch_bounds__(256,1)
mgemm_k(const bf16* __restrict__ A0,const bf16* __restrict__ A1,const bf16* __restrict__ A2,
        const bf16* __restrict__ Bb0,const bf16* __restrict__ Bb1,const bf16* __restrict__ Bb2,
        const float* __restrict__ bias, float* __restrict__ C,
        bf16* __restrict__ Ch, bf16* __restrict__ Cm, bf16* __restrict__ Cl,
        int Ncols, int K)
{
    constexpr int ALEV = 2;
    constexpr int WM   = (BN_==128)?2:4;
    constexpr int WN   = 8/WM;
    constexpr int MT   = 128/(WM*16);
    constexpr int NTT  = BN_/(WN*8);
    constexpr int ASZ  = 128*64;
    constexpr int BSZ  = BN_*64;
    constexpr int STAGE= 3*ASZ + 3*BSZ;

    extern __shared__ char smem[];
    const uint32_t sb = smem_u32(smem);
    const int tid = threadIdx.x, wid = tid>>5, lane = tid&31;
    const int wm = (WM==2)?(wid>>2):(wid>>1);
    const int wn = (WM==2)?(wid&3):(wid&1);
    const int wmB = wm*MT*16, wnB = wn*NTT*8;
    const int bCol0 = blockIdx.x*BN_;
    const int aRow0 = blockIdx.y*128;

    const bf16* Ap[3]={A0,A1,A2};
    const bf16* Bp[3]={Bb0,Bb1,Bb2};

    float acc[MT][NTT][4];
#pragma unroll
    for (int i=0;i<MT;i++)
#pragma unroll
        for (int j=0;j<NTT;j++)
#pragma unroll
            for (int q=0;q<4;q++) acc[i][j][q]=0.f;

    auto issue = [&](int kb, int st){
        uint32_t base = sb + st*STAGE;
#pragma unroll
        for (int i0=0; i0<ALEV*512; i0+=256){
            int i = i0 + tid;
            int l = i>>9, rem = i&511, r = rem>>2, c = rem&3;
            CP16(base + l*ASZ + SWO(r,c),
                 Ap[l] + (size_t)(aRow0+r)*K + kb + c*8);
        }
#pragma unroll
        for (int i0=0; i0<ALEV*BN_*4; i0+=256){
            int i = i0 + tid;
            int l = i/(BN_*4), rem = i%(BN_*4), r = rem>>2, c = rem&3;
            CP16(base + 3*ASZ + l*BSZ + SWO(r,c),
                 Bp[l] + (size_t)(bCol0+r)*K + kb + c*8);
        }
        CPCOMMIT;
    };

    const int T = K/32;
    issue(0,0);
    for (int t=0; t<T; ++t){
        CPWAIT0;
        __syncthreads();
        if (t+1 < T) issue((t+1)*32, (t+1)&1);
        const uint32_t base = sb + (t&1)*STAGE;
#pragma unroll
        for (int ks=0; ks<2; ++ks){
            uint32_t af[ALEV][MT][4];
#pragma unroll
            for (int l=0;l<ALEV;l++)
#pragma unroll
                for (int mt=0;mt<MT;mt++){
                    int r = wmB + mt*16 + (lane&15);
                    int c = ks*2 + (lane>>4);
                    ldsm4(af[l][mt][0],af[l][mt][1],af[l][mt][2],af[l][mt][3],
                          base + l*ASZ + SWO(r,c));
                }
#pragma unroll
            for (int bl=0; bl<ALEV; ++bl){
                uint32_t bfr[NTT/2][4];
#pragma unroll
                for (int np=0; np<NTT/2; np++){
                    int r = wnB + np*16 + ((lane>>4)<<3) + (lane&7);
                    int c = ks*2 + ((lane>>3)&1);
                    ldsm4(bfr[np][0],bfr[np][1],bfr[np][2],bfr[np][3],
                          base + 3*ASZ + bl*BSZ + SWO(r,c));
                }
                const int na = (bl==0?2:1);
#pragma unroll
                for (int al=0; al<ALEV; ++al){
                    if (al < na){
#pragma unroll
                        for (int mt=0;mt<MT;mt++)
#pragma unroll
                            for (int nt=0;nt<NTT;nt++)
                                mma16816(acc[mt][nt], af[al][mt],
                                         bfr[nt>>1][(nt&1)*2], bfr[nt>>1][(nt&1)*2+1]);
                    }
                }
            }
        }
    }

#pragma unroll
    for (int mt=0;mt<MT;mt++){
        int rbase = aRow0 + wmB + mt*16 + (lane>>2);
#pragma unroll
        for (int half=0; half<2; ++half){
            size_t r = (size_t)rbase + half*8;
#pragma unroll
            for (int nt=0;nt<NTT;nt++){
                int cc = bCol0 + wnB + nt*8 + (lane&3)*2;
                float v0 = acc[mt][nt][half*2+0] + bias[cc];
                float v1 = acc[mt][nt][half*2+1] + bias[cc+1];
                if (ACT==1){ v0 = fmaxf(v0,0.f); v1 = fmaxf(v1,0.f); }
                size_t go = r*(size_t)Ncols + cc;
                if (OUTM==1){ C[go]=v0; C[go+1]=v1; }
                else wsplit2(Ch,Cm,Cl, go, v0, v1);
            }
        }
    }
}

// ---------------- weight transpose+split  W[K,N] -> [N,K] h/m/l ----------------
__global__ void tsplit_k(const float* __restrict__ W, int Kd, int Nd,
                         bf16* __restrict__ dh, bf16* __restrict__ dm, bf16* __restrict__ dl)
{
    int e = blockIdx.x*256 + threadIdx.x;
    if (e >= Kd*Nd) return;
    int k = e / Nd, n = e % Nd;
    bf16 h,m,l; split3(W[e], h,m,l);
    size_t di = (size_t)n*Kd + k;
    dh[di]=h; dm[di]=m; dl[di]=l;
}

// ---------------- LayerNorm + ReLU (fp32 out, R8-identical) ----------------
__global__ void ln_relu_k(const float* __restrict__ X, const float* __restrict__ gam,
                          const float* __restrict__ bet, float* __restrict__ Y)
{
    const int row = blockIdx.x;
    const int t   = threadIdx.x;
    __shared__ float red[8];
    __shared__ float s_mu, s_rs;

    float4 v = *(const float4*)(X + (size_t)row*HDIM + t*4);
    float s = __fadd_rn(__fadd_rn(v.x,v.y), __fadd_rn(v.z,v.w));
#pragma unroll
    for (int o=16;o;o>>=1) s = __fadd_rn(s, __shfl_xor_sync(~0u, s, o));
    if ((t&31)==0) red[t>>5] = s;
    __syncthreads();
    if (t==0) {
        float a = __fadd_rn(__fadd_rn(red[0],red[1]), __fadd_rn(red[2],red[3]));
        float b = __fadd_rn(__fadd_rn(red[4],red[5]), __fadd_rn(red[6],red[7]));
        s_mu = __fadd_rn(a,b) * (1.0f/HDIM);
    }
    __syncthreads();
    const float mu = s_mu;
    float dx=__fadd_rn(v.x,-mu), dy=__fadd_rn(v.y,-mu),
          dz=__fadd_rn(v.z,-mu), dw=__fadd_rn(v.w,-mu);
    float sq = __fadd_rn(__fadd_rn(__fmul_rn(dx,dx),__fmul_rn(dy,dy)),
                         __fadd_rn(__fmul_rn(dz,dz),__fmul_rn(dw,dw)));
#pragma unroll
    for (int o=16;o;o>>=1) sq = __fadd_rn(sq, __shfl_xor_sync(~0u, sq, o));
    if ((t&31)==0) red[t>>5] = sq;
    __syncthreads();
    if (t==0) {
        float a = __fadd_rn(__fadd_rn(red[0],red[1]), __fadd_rn(red[2],red[3]));
        float b = __fadd_rn(__fadd_rn(red[4],red[5]), __fadd_rn(red[6],red[7]));
        s_rs = rsqrtf(__fadd_rn(a,b)*(1.0f/HDIM) + 1e-5f);
    }
    __syncthreads();
    const float rs = s_rs;

    float4 g4 = *(const float4*)(gam + t*4);
    float4 b4 = *(const float4*)(bet + t*4);
    float4 o;
    o.x = fmaxf(__fadd_rn(__fmul_rn(__fmul_rn(dx,rs),g4.x), b4.x), 0.f);
    o.y = fmaxf(__fadd_rn(__fmul_rn(__fmul_rn(dy,rs),g4.y), b4.y), 0.f);
    o.z = fmaxf(__fadd_rn(__fmul_rn(__fmul_rn(dz,rs),g4.z), b4.z), 0.f);
    o.w = fmaxf(__fadd_rn(__fmul_rn(__fmul_rn(dw,rs),g4.w), b4.w), 0.f);
    *(float4*)(Y + (size_t)row*HDIM + t*4) = o;
}

// ---------------- small kernels ----------------
__global__ void znorm_k(const float* __restrict__ z, float* __restrict__ zn)
{
    int row  = blockIdx.x*8 + (threadIdx.x >> 5);
    int lane = threadIdx.x & 31;
    float4 v = *(const float4*)(z + (size_t)row*DDIM + lane*4);
    float s = __fadd_rn(__fadd_rn(__fmul_rn(v.x,v.x), __fmul_rn(v.y,v.y)),
                        __fadd_rn(__fmul_rn(v.z,v.z), __fmul_rn(v.w,v.w)));
#pragma unroll
    for (int o=16;o;o>>=1) s = __fadd_rn(s, __shfl_xor_sync(~0u, s, o));
    if (lane == 0) zn[row] = s;
}
__global__ void prep_k(const float* __restrict__ cb, float* __restrict__ cn,
                       float* __restrict__ cbT)
{
    int k = threadIdx.x;
    double s = 0.0;
    for (int d0=0; d0<DDIM; d0++) {
        float v = cb[k*DDIM + d0];
        s += (double)v * (double)v;
        cbT[d0*KCODES + k] = v;
    }
    cn[k] = (float)s;
}
__global__ void init_k(float* loss, int* hist)
{
    int t = threadIdx.x;
    if (t == 0) *loss = 0.f;
    if (t < KCODES) hist[t] = 0;
}
__global__ void argmin_k(const float* __restrict__ S, int* __restrict__ idx,
                         float* __restrict__ idx_f)
{
    int row  = blockIdx.x*8 + (threadIdx.x >> 5);
    int lane = threadIdx.x & 31;
    const float* sr = S + (size_t)row*KCODES;
    float bv = 3.4e38f; int bk = 0;
#pragma unroll
    for (int j=0;j<8;j++) {
        int k = lane + j*32;
        float v = sr[k];
        if (v < bv) { bv = v; bk = k; }
    }
#pragma unroll
    for (int o=16;o;o>>=1) {
        float ov = __shfl_xor_sync(~0u, bv, o);
        int   ok = __shfl_xor_sync(~0u, bk, o);
        if (ov < bv || (ov == bv && ok < bk)) { bv = ov; bk = ok; }
    }
    if (lane == 0) { idx[row] = bk; idx_f[row] = (float)bk; }
}
__global__ void gather_k(const float* __restrict__ z, const float* __restrict__ cb,
                         const int* __restrict__ idx,
                         bf16* __restrict__ Qh, bf16* __restrict__ Qm, bf16* __restrict__ Ql,
                         float* __restrict__ loss, int* __restrict__ hist)
{
    int b = blockIdx.x;
    int t = threadIdx.x;
    __shared__ int   sidx[GG];
    __shared__ float red[8];
    if (t < GG) {
        int k = idx[b*GG + t];
        sidx[t] = k;
        atomicAdd(&hist[k], 1);
    }
    __syncthreads();
    int g = (t*4) >> 7;
    int e = (t*4) & 127;
    float4 c  = *(const float4*)(cb + (size_t)sidx[g]*DDIM + e);
    float4 zz = *(const float4*)(z  + (size_t)b*GD + t*4);
    float dx=__fadd_rn(c.x,-zz.x), dy=__fadd_rn(c.y,-zz.y),
          dz=__fadd_rn(c.z,-zz.z), dw=__fadd_rn(c.w,-zz.w);
    float st0=__fadd_rn(zz.x,dx), st1=__fadd_rn(zz.y,dy),
          st2=__fadd_rn(zz.z,dz), st3=__fadd_rn(zz.w,dw);
    size_t go = (size_t)b*GD + t*4;
    wsplit2(Qh,Qm,Ql, go,   st0, st1);
    wsplit2(Qh,Qm,Ql, go+2, st2, st3);
    float s = dx*dx+dy*dy+dz*dz+dw*dw;
#pragma unroll
    for (int o=16;o;o>>=1) s += __shfl_xor_sync(~0u, s, o);
    if ((t&31)==0) red[t>>5] = s;
    __syncthreads();
    if (t==0) {
        float tot=0.f;
#pragma unroll
        for (int i=0;i<8;i++) tot += red[i];
        atomicAdd(loss, tot);
    }
}
__global__ void finalize_k(const int* __restrict__ hist, const float* __restrict__ loss,
                           float* __restrict__ out)
{
    int t = threadIdx.x;
    __shared__ float red[8];
    float e = (float)hist[t] / (float)BG;
    float s = e * logf(e + 1e-10f);
#pragma unroll
    for (int o=16;o;o>>=1) s += __shfl_xor_sync(~0u, s, o);
    if ((t&31)==0) red[t>>5] = s;
    __syncthreads();
    if (t==0) {
        float tot=0.f;
#pragma unroll
        for (int i=0;i<8;i++) tot += red[i];
        out[PERP_OFF] = expf(-tot);
        out[0] = 1.25f * loss[0] / 33554432.0f;
    }
}

// ---------------- host launcher ----------------
extern "C" void kernel_launch(void* const* d_in, const int* in_sizes, int n_in,
                              void* d_out, int out_size)
{
    const float* x      = (const float*)d_in[0];
    const float* enc_w1 = (const float*)d_in[1];
    const float* enc_b1 = (const float*)d_in[2];
    const float* enc_w2 = (const float*)d_in[3];
    const float* enc_b2 = (const float*)d_in[4];
    const float* ln_g   = (const float*)d_in[5];
    const float* ln_b   = (const float*)d_in[6];
    const float* enc_w3 = (const float*)d_in[7];
    const float* enc_b3 = (const float*)d_in[8];
    const float* enc_w4 = (const float*)d_in[9];
    const float* enc_b4 = (const float*)d_in[10];
    const float* cb     = (const float*)d_in[11];
    const float* dec_w1 = (const float*)d_in[12];
    const float* dec_b1 = (const float*)d_in[13];
    const float* dec_w2 = (const float*)d_in[14];
    const float* dec_b2 = (const float*)d_in[15];
    const float* dec_w3 = (const float*)d_in[16];
    const float* dec_b3 = (const float*)d_in[17];
    float* out = (float*)d_out;

    static float *p_h1=nullptr,*p_t2,*p_h2,*p_z,*p_S,*p_zn,*p_cn,*p_cbT,*p_loss;
    static int *p_idx,*p_hist;
    static bf16 *pA0,*pA1,*pA2,*pB0,*pB1,*pB2,*pw0,*pw1,*pw2;
    if (!p_h1) {
        cudaGetSymbolAddress((void**)&p_h1,  g_h1);
        cudaGetSymbolAddress((void**)&p_t2,  g_t2);
        cudaGetSymbolAddress((void**)&p_h2,  g_h2);
        cudaGetSymbolAddress((void**)&p_z,   g_z);
        cudaGetSymbolAddress((void**)&p_S,   g_S);
        cudaGetSymbolAddress((void**)&p_zn,  g_zn);
        cudaGetSymbolAddress((void**)&p_cn,  g_cn);
        cudaGetSymbolAddress((void**)&p_cbT, g_cbT);
        cudaGetSymbolAddress((void**)&p_loss,g_loss);
        cudaGetSymbolAddress((void**)&p_idx, g_idx);
        cudaGetSymbolAddress((void**)&p_hist,g_hist);
        cudaGetSymbolAddress((void**)&pA0, g_bA0);
        cudaGetSymbolAddress((void**)&pA1, g_bA1);
        cudaGetSymbolAddress((void**)&pA2, g_bA2);
        cudaGetSymbolAddress((void**)&pB0, g_bB0);
        cudaGetSymbolAddress((void**)&pB1, g_bB1);
        cudaGetSymbolAddress((void**)&pB2, g_bB2);
        cudaGetSymbolAddress((void**)&pw0, g_wt0);
        cudaGetSymbolAddress((void**)&pw1, g_wt1);
        cudaGetSymbolAddress((void**)&pw2, g_wt2);
        cudaFuncSetAttribute(mgemm_k<128,1,2>, cudaFuncAttributeMaxDynamicSharedMemorySize, 98304);
        cudaFuncSetAttribute(mgemm_k< 64,0,1>, cudaFuncAttributeMaxDynamicSharedMemorySize, 73728);
    }
    const int SM128 = 98304, SM64 = 73728;

    prep_k<<<1,256>>>(cb, p_cn, p_cbT);
    init_k<<<1,256>>>(p_loss, p_hist);

    // decoder weight splits
    tsplit_k<<<(1024*1024+255)/256,256>>>(dec_w1, 1024, 1024, pw0+OFF_D1, pw1+OFF_D1, pw2+OFF_D1);
    tsplit_k<<<(1024*1024+255)/256,256>>>(dec_w2, 1024, 1024, pw0+OFF_D2, pw1+OFF_D2, pw2+OFF_D2);
    tsplit_k<<<(1024*64+255)/256,256>>>(dec_w3, 1024, 64, pw0+OFF_D3, pw1+OFF_D3, pw2+OFF_D3);

    // ---- encoder (fp32 FFMA2 dbuf: byte-identical to R8 pass) ----
    gemm2_k<128,128,16,8,8,1,1><<<dim3(HDIM/128, B_SZ/128), 256>>>(x,    enc_w1, enc_b1, p_h1, B_SZ, HDIM, STATE_NN);
    gemm2_k<128,128,16,8,8,0,1><<<dim3(HDIM/128, B_SZ/128), 256>>>(p_h1, enc_w2, enc_b2, p_t2, B_SZ, HDIM, HDIM);
    ln_relu_k<<<B_SZ,256>>>(p_t2, ln_g, ln_b, p_h2);
    gemm2_k<128,128,16,8,8,1,1><<<dim3(HDIM/128, B_SZ/128), 256>>>(p_h2, enc_w3, enc_b3, p_h1, B_SZ, HDIM, HDIM);
    gemm2_k<128,128,16,8,8,0,1><<<dim3(DDIM/128, BG/128),   256>>>(p_h1, enc_w4, enc_b4, p_z,  BG,   DDIM, DDIM);

    // ---- VQ (byte-identical to R8 pass) ----
    znorm_k<<<BG/8,256>>>(p_z, p_zn);
    gemm_vq2_k<128,64,16,8,4><<<dim3(KCODES/64, BG/128), 256>>>(p_z, p_cbT, p_cn, p_zn, p_S, BG, KCODES, DDIM);
    argmin_k<<<BG/8,256>>>(p_S, p_idx, out + IDX_OFF);
    gather_k<<<B_SZ,256>>>(p_z, cb, p_idx, pB0, pB1, pB2, p_loss, p_hist);
    finalize_k<<<1,256>>>(p_hist, p_loss, out);

    // ---- decoder (HMMA 3-product, validated in R11/R12) ----
    mgemm_k<128,1,2><<<dim3(8, B_SZ/128), 256, SM128>>>(pB0,pB1,pB2,
        pw0+OFF_D1,pw1+OFF_D1,pw2+OFF_D1, dec_b1, nullptr, pA0,pA1,pA2, HDIM, HDIM);
    mgemm_k<128,1,2><<<dim3(8, B_SZ/128), 256, SM128>>>(pA0,pA1,pA2,
        pw0+OFF_D2,pw1+OFF_D2,pw2+OFF_D2, dec_b2, nullptr, pB0,pB1,pB2, HDIM, HDIM);
    mgemm_k<64,0,1><<<dim3(1, B_SZ/128), 256, SM64>>>(pB0,pB1,pB2,
        pw0+OFF_D3,pw1+OFF_D3,pw2+OFF_D3, dec_b3, out + DEC_OFF, nullptr,nullptr,nullptr, STATE_NN, HDIM);
}

// round 14
// speedup vs baseline: 1.4358x; 1.0684x over previous
#include <cuda_runtime.h>
#include <cuda_bf16.h>
#include <cstdint>
#include <cmath>

#define B_SZ    32768
#define STATE_NN 64
#define HDIM    1024
#define KCODES  256
#define DDIM    128
#define GG      8
#define BG      (B_SZ*GG)
#define GD      (GG*DDIM)
#define DEC_OFF  1
#define PERP_OFF (1 + B_SZ*STATE_NN)
#define IDX_OFF  (2 + B_SZ*STATE_NN)

typedef unsigned long long u64;
typedef __nv_bfloat16 bf16;

// ---------------- device scratch ----------------
__device__ float g_t2[(size_t)B_SZ*HDIM];
__device__ float g_z [(size_t)B_SZ*GD];
__device__ float g_S [(size_t)BG*KCODES];
__device__ float g_zn[BG];
__device__ int   g_idx[BG];
__device__ int   g_hist[KCODES];
__device__ float g_cn[KCODES];
__device__ float g_cbT[DDIM*KCODES];
__device__ float g_loss[1];

__device__ __align__(16) bf16 g_bA0[(size_t)B_SZ*HDIM];
__device__ __align__(16) bf16 g_bA1[(size_t)B_SZ*HDIM];
__device__ __align__(16) bf16 g_bA2[(size_t)B_SZ*HDIM];
__device__ __align__(16) bf16 g_bB0[(size_t)B_SZ*HDIM];
__device__ __align__(16) bf16 g_bB1[(size_t)B_SZ*HDIM];
__device__ __align__(16) bf16 g_bB2[(size_t)B_SZ*HDIM];
__device__ __align__(16) bf16 g_xs0[(size_t)B_SZ*STATE_NN];
__device__ __align__(16) bf16 g_xs1[(size_t)B_SZ*STATE_NN];
__device__ __align__(16) bf16 g_xs2[(size_t)B_SZ*STATE_NN];

#define OFF_W1 0
#define OFF_W2 65536
#define OFF_W3 1114112
#define OFF_W4 2162688
#define OFF_D1 2179072
#define OFF_D2 3227648
#define OFF_D3 4276224
#define WT_TOT 4341760
__device__ __align__(16) bf16 g_wt0[WT_TOT];
__device__ __align__(16) bf16 g_wt1[WT_TOT];
__device__ __align__(16) bf16 g_wt2[WT_TOT];

// ---------------- helpers ----------------
__device__ __forceinline__ u64 pack2(float lo, float hi){
    u64 r; asm("mov.b64 %0, {%1,%2};" : "=l"(r) : "f"(lo), "f"(hi)); return r; }
__device__ __forceinline__ void unpack2(u64 v, float &lo, float &hi){
    asm("mov.b64 {%0,%1}, %2;" : "=f"(lo), "=f"(hi) : "l"(v)); }
__device__ __forceinline__ u64 fmul2(u64 a, u64 b){
    u64 d; asm("mul.rn.f32x2 %0, %1, %2;" : "=l"(d) : "l"(a), "l"(b)); return d; }
__device__ __forceinline__ u64 fadd2(u64 a, u64 b){
    u64 d; asm("add.rn.f32x2 %0, %1, %2;" : "=l"(d) : "l"(a), "l"(b)); return d; }
__device__ __forceinline__ uint32_t smem_u32(const void* p){
    uint32_t a; asm("{ .reg .u64 t; cvta.to.shared.u64 t, %1; cvt.u32.u64 %0, t; }" : "=r"(a) : "l"(p));
    return a; }
__device__ __forceinline__ void split3(float v, bf16 &h, bf16 &m, bf16 &l){
    h = __float2bfloat16(v);
    float r1 = v - __bfloat162float(h);
    m = __float2bfloat16(r1);
    l = __float2bfloat16(r1 - __bfloat162float(m)); }
__device__ __forceinline__ void wsplit2(bf16* H, bf16* M, bf16* L, size_t go, float a, float b){
    bf16 h0,m0,l0,h1,m1,l1; split3(a,h0,m0,l0); split3(b,h1,m1,l1);
    __nv_bfloat162 p;
    p.x=h0; p.y=h1; *(__nv_bfloat162*)(H+go)=p;
    p.x=m0; p.y=m1; *(__nv_bfloat162*)(M+go)=p;
    p.x=l0; p.y=l1; *(__nv_bfloat162*)(L+go)=p; }

#define CP16(dst, src) asm volatile("cp.async.cg.shared.global [%0], [%1], 16;" :: "r"(dst), "l"(src) : "memory")
#define CPCOMMIT       asm volatile("cp.async.commit_group;" ::: "memory")
#define CPWAIT0        asm volatile("cp.async.wait_group 0;" ::: "memory")
__device__ __forceinline__ void ldsm4(uint32_t &r0,uint32_t &r1,uint32_t &r2,uint32_t &r3,uint32_t a){
    asm volatile("ldmatrix.sync.aligned.m8n8.x4.shared.b16 {%0,%1,%2,%3}, [%4];"
        : "=r"(r0),"=r"(r1),"=r"(r2),"=r"(r3) : "r"(a)); }
__device__ __forceinline__ void mma16816(float* c, const uint32_t* a, uint32_t b0, uint32_t b1){
    asm volatile("mma.sync.aligned.m16n8k16.row.col.f32.bf16.bf16.f32 "
        "{%0,%1,%2,%3},{%4,%5,%6,%7},{%8,%9},{%0,%1,%2,%3};"
        : "+f"(c[0]),"+f"(c[1]),"+f"(c[2]),"+f"(c[3])
        : "r"(a[0]),"r"(a[1]),"r"(a[2]),"r"(a[3]), "r"(b0),"r"(b1)); }
#define SWO(r,c) ((r)*64 + (((c) ^ (((r)>>1)&3))<<4))

// =====================================================================
// ENCODER HMMA GEMM: 6-product bf16 split with SPLIT ACCUMULATORS.
// acc0 <- hh (big terms only);  acc1 <- hm,mh,mm,hl,lh (small terms).
// BN_=64 (register headroom for dual acc).  OUTM: 0 f32, 2 splits.
// =====================================================================
template<int ACT, int OUTM>
__global__ void __launch_bounds__(256,1)
emgemm_k(const bf16* __restrict__ A0,const bf16* __restrict__ A1,const bf16* __restrict__ A2,
         const bf16* __restrict__ Bb0,const bf16* __restrict__ Bb1,const bf16* __restrict__ Bb2,
         const float* __restrict__ bias, float* __restrict__ C,
         bf16* __restrict__ Ch, bf16* __restrict__ Cm, bf16* __restrict__ Cl,
         int Ncols, int K)
{
    constexpr int BN_  = 64;
    constexpr int MT   = 2;              // WM=4
    constexpr int NTT  = 4;              // WN=2
    constexpr int ASZ  = 128*64;
    constexpr int BSZ  = BN_*64;
    constexpr int STAGE= 3*ASZ + 3*BSZ;  // 36864

    extern __shared__ char smem[];
    const uint32_t sb = smem_u32(smem);
    const int tid = threadIdx.x, wid = tid>>5, lane = tid&31;
    const int wm = wid>>1, wn = wid&1;
    const int wmB = wm*32, wnB = wn*32;
    const int bCol0 = blockIdx.x*BN_;
    const int aRow0 = blockIdx.y*128;

    const bf16* Ap[3]={A0,A1,A2};
    const bf16* Bp[3]={Bb0,Bb1,Bb2};

    float acc0[MT][NTT][4], acc1[MT][NTT][4];
#pragma unroll
    for (int i=0;i<MT;i++)
#pragma unroll
        for (int j=0;j<NTT;j++)
#pragma unroll
            for (int q=0;q<4;q++){ acc0[i][j][q]=0.f; acc1[i][j][q]=0.f; }

    auto issue = [&](int kb, int st){
        uint32_t base = sb + st*STAGE;
#pragma unroll
        for (int i0=0; i0<3*512; i0+=256){
            int i = i0 + tid;
            int l = i>>9, rem = i&511, r = rem>>2, c = rem&3;
            CP16(base + l*ASZ + SWO(r,c),
                 Ap[l] + (size_t)(aRow0+r)*K + kb + c*8);
        }
#pragma unroll
        for (int i0=0; i0<3*BN_*4; i0+=256){
            int i = i0 + tid;
            int l = i/(BN_*4), rem = i%(BN_*4), r = rem>>2, c = rem&3;
            CP16(base + 3*ASZ + l*BSZ + SWO(r,c),
                 Bp[l] + (size_t)(bCol0+r)*K + kb + c*8);
        }
        CPCOMMIT;
    };

    const int T = K/32;
    issue(0,0);
    for (int t=0; t<T; ++t){
        CPWAIT0;
        __syncthreads();
        if (t+1 < T) issue((t+1)*32, (t+1)&1);
        const uint32_t base = sb + (t&1)*STAGE;
#pragma unroll
        for (int ks=0; ks<2; ++ks){
            uint32_t af[3][MT][4];
#pragma unroll
            for (int l=0;l<3;l++)
#pragma unroll
                for (int mt=0;mt<MT;mt++){
                    int r = wmB + mt*16 + (lane&15);
                    int c = ks*2 + (lane>>4);
                    ldsm4(af[l][mt][0],af[l][mt][1],af[l][mt][2],af[l][mt][3],
                          base + l*ASZ + SWO(r,c));
                }
#pragma unroll
            for (int bl=0; bl<3; ++bl){
                uint32_t bfr[NTT/2][4];
#pragma unroll
                for (int np=0; np<NTT/2; np++){
                    int r = wnB + np*16 + ((lane>>4)<<3) + (lane&7);
                    int c = ks*2 + ((lane>>3)&1);
                    ldsm4(bfr[np][0],bfr[np][1],bfr[np][2],bfr[np][3],
                          base + 3*ASZ + bl*BSZ + SWO(r,c));
                }
                const int na = (bl==0)?3:(bl==1?2:1);   // 6 products total
#pragma unroll
                for (int al=0; al<3; ++al){
                    if (al < na){
                        float (*acc)[NTT][4] = (al==0 && bl==0) ? acc0 : acc1;
#pragma unroll
                        for (int mt=0;mt<MT;mt++)
#pragma unroll
                            for (int nt=0;nt<NTT;nt++)
                                mma16816(acc[mt][nt], af[al][mt],
                                         bfr[nt>>1][(nt&1)*2], bfr[nt>>1][(nt&1)*2+1]);
                    }
                }
            }
        }
    }

#pragma unroll
    for (int mt=0;mt<MT;mt++){
        int rbase = aRow0 + wmB + mt*16 + (lane>>2);
#pragma unroll
        for (int half=0; half<2; ++half){
            size_t r = (size_t)rbase + half*8;
#pragma unroll
            for (int nt=0;nt<NTT;nt++){
                int cc = bCol0 + wnB + nt*8 + (lane&3)*2;
                float v0 = (acc0[mt][nt][half*2+0] + acc1[mt][nt][half*2+0]) + bias[cc];
                float v1 = (acc0[mt][nt][half*2+1] + acc1[mt][nt][half*2+1]) + bias[cc+1];
                if (ACT==1){ v0 = fmaxf(v0,0.f); v1 = fmaxf(v1,0.f); }
                size_t go = r*(size_t)Ncols + cc;
                if (OUTM==0){ float2 o; o.x=v0; o.y=v1; *(float2*)(C+go)=o; }
                else wsplit2(Ch,Cm,Cl, go, v0, v1);
            }
        }
    }
}

// =====================================================================
// DECODER HMMA GEMM (byte-identical to R13 pass): 3-product split.
// =====================================================================
template<int BN_, int ACT, int OUTM>
__global__ void __launch_bounds__(256,1)
mgemm_k(const bf16* __restrict__ A0,const bf16* __restrict__ A1,const bf16* __restrict__ A2,
        const bf16* __restrict__ Bb0,const bf16* __restrict__ Bb1,const bf16* __restrict__ Bb2,
        const float* __restrict__ bias, float* __restrict__ C,
        bf16* __restrict__ Ch, bf16* __restrict__ Cm, bf16* __restrict__ Cl,
        int Ncols, int K)
{
    constexpr int ALEV = 2;
    constexpr int WM   = (BN_==128)?2:4;
    constexpr int WN   = 8/WM;
    constexpr int MT   = 128/(WM*16);
    constexpr int NTT  = BN_/(WN*8);
    constexpr int ASZ  = 128*64;
    constexpr int BSZ  = BN_*64;
    constexpr int STAGE= 3*ASZ + 3*BSZ;

    extern __shared__ char smem[];
    const uint32_t sb = smem_u32(smem);
    const int tid = threadIdx.x, wid = tid>>5, lane = tid&31;
    const int wm = (WM==2)?(wid>>2):(wid>>1);
    const int wn = (WM==2)?(wid&3):(wid&1);
    const int wmB = wm*MT*16, wnB = wn*NTT*8;
    const int bCol0 = blockIdx.x*BN_;
    const int aRow0 = blockIdx.y*128;

    const bf16* Ap[3]={A0,A1,A2};
    const bf16* Bp[3]={Bb0,Bb1,Bb2};

    float acc[MT][NTT][4];
#pragma unroll
    for (int i=0;i<MT;i++)
#pragma unroll
        for (int j=0;j<NTT;j++)
#pragma unroll
            for (int q=0;q<4;q++) acc[i][j][q]=0.f;

    auto issue = [&](int kb, int st){
        uint32_t base = sb + st*STAGE;
#pragma unroll
        for (int i0=0; i0<ALEV*512; i0+=256){
            int i = i0 + tid;
            int l = i>>9, rem = i&511, r = rem>>2, c = rem&3;
            CP16(base + l*ASZ + SWO(r,c),
                 Ap[l] + (size_t)(aRow0+r)*K + kb + c*8);
        }
#pragma unroll
        for (int i0=0; i0<ALEV*BN_*4; i0+=256){
            int i = i0 + tid;
            int l = i/(BN_*4), rem = i%(BN_*4), r = rem>>2, c = rem&3;
            CP16(base + 3*ASZ + l*BSZ + SWO(r,c),
                 Bp[l] + (size_t)(bCol0+r)*K + kb + c*8);
        }
        CPCOMMIT;
    };

    const int T = K/32;
    issue(0,0);
    for (int t=0; t<T; ++t){
        CPWAIT0;
        __syncthreads();
        if (t+1 < T) issue((t+1)*32, (t+1)&1);
        const uint32_t base = sb + (t&1)*STAGE;
#pragma unroll
        for (int ks=0; ks<2; ++ks){
            uint32_t af[ALEV][MT][4];
#pragma unroll
            for (int l=0;l<ALEV;l++)
#pragma unroll
                for (int mt=0;mt<MT;mt++){
                    int r = wmB + mt*16 + (lane&15);
                    int c = ks*2 + (lane>>4);
                    ldsm4(af[l][mt][0],af[l][mt][1],af[l][mt][2],af[l][mt][3],
                          base + l*ASZ + SWO(r,c));
                }
#pragma unroll
            for (int bl=0; bl<ALEV; ++bl){
                uint32_t bfr[NTT/2][4];
#pragma unroll
                for (int np=0; np<NTT/2; np++){
                    int r = wnB + np*16 + ((lane>>4)<<3) + (lane&7);
                    int c = ks*2 + ((lane>>3)&1);
                    ldsm4(bfr[np][0],bfr[np][1],bfr[np][2],bfr[np][3],
                          base + 3*ASZ + bl*BSZ + SWO(r,c));
                }
                const int na = (bl==0?2:1);
#pragma unroll
                for (int al=0; al<ALEV; ++al){
                    if (al < na){
#pragma unroll
                        for (int mt=0;mt<MT;mt++)
#pragma unroll
                            for (int nt=0;nt<NTT;nt++)
                                mma16816(acc[mt][nt], af[al][mt],
                                         bfr[nt>>1][(nt&1)*2], bfr[nt>>1][(nt&1)*2+1]);
                    }
                }
            }
        }
    }

#pragma unroll
    for (int mt=0;mt<MT;mt++){
        int rbase = aRow0 + wmB + mt*16 + (lane>>2);
#pragma unroll
        for (int half=0; half<2; ++half){
            size_t r = (size_t)rbase + half*8;
#pragma unroll
            for (int nt=0;nt<NTT;nt++){
                int cc = bCol0 + wnB + nt*8 + (lane&3)*2;
                float v0 = acc[mt][nt][half*2+0] + bias[cc];
                float v1 = acc[mt][nt][half*2+1] + bias[cc+1];
                if (ACT==1){ v0 = fmaxf(v0,0.f); v1 = fmaxf(v1,0.f); }
                size_t go = r*(size_t)Ncols + cc;
                if (OUTM==1){ C[go]=v0; C[go+1]=v1; }
                else wsplit2(Ch,Cm,Cl, go, v0, v1);
            }
        }
    }
}

// ---------------- weight transpose+split / x split ----------------
__global__ void tsplit_k(const float* __restrict__ W, int Kd, int Nd,
                         bf16* __restrict__ dh, bf16* __restrict__ dm, bf16* __restrict__ dl)
{
    int e = blockIdx.x*256 + threadIdx.x;
    if (e >= Kd*Nd) return;
    int k = e / Nd, n = e % Nd;
    bf16 h,m,l; split3(W[e], h,m,l);
    size_t di = (size_t)n*Kd + k;
    dh[di]=h; dm[di]=m; dl[di]=l;
}
__global__ void xsplit_k(const float* __restrict__ X, int n,
                         bf16* __restrict__ dh, bf16* __restrict__ dm, bf16* __restrict__ dl)
{
    int e = blockIdx.x*256 + threadIdx.x;
    if (e >= n) return;
    bf16 h,m,l; split3(X[e], h,m,l);
    dh[e]=h; dm[e]=m; dl[e]=l;
}

// ============ VQ-score GEMM (byte-identical compute to R8/R13 pass) ============
template<int BM,int BN,int BK,int TM,int TN>
__global__ void __launch_bounds__(256,2)
gemm_vq2_k(const float* __restrict__ A, const float* __restrict__ Bm,
           const float* __restrict__ cn, const float* __restrict__ zn,
           float* __restrict__ C, int M, int N, int K)
{
    constexpr int ANUM = (BM*BK)/(256*4);
    constexpr int BNUM = (BK*BN)/(256*4);
    __shared__ float As[2][BK][BM];
    __shared__ float Bs[2][BK][BN];

    const int tid  = threadIdx.x;
    const int tcol = tid % (BN/TN);
    const int trow = tid / (BN/TN);
    const int aRow0 = blockIdx.y * BM;
    const int bCol0 = blockIdx.x * BN;
    const u64 SGN = 0x8000000080000000ULL;

    u64 s[TM][TN/2], e[TM][TN/2];
#pragma unroll
    for (int i=0;i<TM;i++)
#pragma unroll
        for (int j=0;j<TN/2;j++) { s[i][j]=0ULL; e[i][j]=0ULL; }

#pragma unroll
    for (int it=0; it<ANUM; ++it) {
        int idx4 = (tid + it*256)*4;
        int r = idx4 / BK, c = idx4 % BK;
        float4 v = *(const float4*)(A + (size_t)(aRow0+r)*K + c);
        As[0][c+0][r]=v.x; As[0][c+1][r]=v.y; As[0][c+2][r]=v.z; As[0][c+3][r]=v.w;
    }
#pragma unroll
    for (int it=0; it<BNUM; ++it) {
        int idx4 = (tid + it*256)*4;
        int r = idx4 / BN, c = idx4 % BN;
        *(float4*)&Bs[0][r][c] = *(const float4*)(Bm + (size_t)r*N + bCol0 + c);
    }
    __syncthreads();

    const int NIT = K/BK;
    for (int itk=0; itk<NIT; ++itk) {
        const int cur = itk & 1, nxt = cur ^ 1;
        const int k1 = (itk+1)*BK;
        float4 avp[ANUM], bvp[BNUM];
        if (itk+1 < NIT) {
#pragma unroll
            for (int it=0; it<ANUM; ++it) {
                int idx4 = (tid + it*256)*4;
                int r = idx4 / BK, c = idx4 % BK;
                avp[it] = *(const float4*)(A + (size_t)(aRow0+r)*K + k1 + c);
            }
#pragma unroll
            for (int it=0; it<BNUM; ++it) {
                int idx4 = (tid + it*256)*4;
                int r = idx4 / BN, c = idx4 % BN;
                bvp[it] = *(const float4*)(Bm + (size_t)(k1+r)*N + bCol0 + c);
            }
        }
#pragma unroll
        for (int kk=0; kk<BK; kk++) {
            u64 ar2[TM], br2[TN/2];
#pragma unroll
            for (int i=0;i<TM;i++) {
                float a = As[cur][kk][trow*TM+i];
                ar2[i] = pack2(a, a);
            }
            {
                ulonglong2 b2 = *(const ulonglong2*)&Bs[cur][kk][tcol*TN];
                br2[0] = b2.x;
                br2[1] = b2.y;
            }
#pragma unroll
            for (int i=0;i<TM;i++)
#pragma unroll
                for (int j=0;j<TN/2;j++) {
                    u64 x  = fmul2(ar2[i], br2[j]);
                    u64 t  = fadd2(s[i][j], x);
                    u64 c1 = fadd2(fadd2(s[i][j], t ^ SGN), x);
                    e[i][j] = fadd2(e[i][j], c1);
                    s[i][j] = t;
                }
        }
        if (itk+1 < NIT) {
#pragma unroll
            for (int it=0; it<ANUM; ++it) {
                int idx4 = (tid + it*256)*4;
                int r = idx4 / BK, c = idx4 % BK;
                As[nxt][c+0][r]=avp[it].x; As[nxt][c+1][r]=avp[it].y;
                As[nxt][c+2][r]=avp[it].z; As[nxt][c+3][r]=avp[it].w;
            }
#pragma unroll
            for (int it=0; it<BNUM; ++it) {
                int idx4 = (tid + it*256)*4;
                int r = idx4 / BN, c = idx4 % BN;
                *(float4*)&Bs[nxt][r][c] = bvp[it];
            }
        }
        __syncthreads();
    }
#pragma unroll
    for (int i=0;i<TM;i++) {
        size_t r = (size_t)aRow0 + trow*TM + i;
        float zr = zn[r];
#pragma unroll
        for (int j=0;j<TN/2;j++) {
            int c = bCol0 + tcol*TN + 2*j;
            float s0,s1,e0,e1;
            unpack2(s[i][j], s0, s1);
            unpack2(e[i][j], e0, e1);
            float dot0 = __fadd_rn(s0, e0);
            float dot1 = __fadd_rn(s1, e1);
            float t0 = __fadd_rn(zr, cn[c]);
            float t1 = __fadd_rn(zr, cn[c+1]);
            C[r*N + c]   = __fadd_rn(t0, __fmul_rn(-2.f, dot0));
            C[r*N + c+1] = __fadd_rn(t1, __fmul_rn(-2.f, dot1));
        }
    }
}

// ---------------- LayerNorm + ReLU -> bf16 splits ----------------
__global__ void ln_relu_k(const float* __restrict__ X, const float* __restrict__ gam,
                          const float* __restrict__ bet,
                          bf16* __restrict__ Yh, bf16* __restrict__ Ym, bf16* __restrict__ Yl)
{
    const int row = blockIdx.x;
    const int t   = threadIdx.x;
    __shared__ float red[8];
    __shared__ float s_mu, s_rs;

    float4 v = *(const float4*)(X + (size_t)row*HDIM + t*4);
    float s = __fadd_rn(__fadd_rn(v.x,v.y), __fadd_rn(v.z,v.w));
#pragma unroll
    for (int o=16;o;o>>=1) s = __fadd_rn(s, __shfl_xor_sync(~0u, s, o));
    if ((t&31)==0) red[t>>5] = s;
    __syncthreads();
    if (t==0) {
        float a = __fadd_rn(__fadd_rn(red[0],red[1]), __fadd_rn(red[2],red[3]));
        float b = __fadd_rn(__fadd_rn(red[4],red[5]), __fadd_rn(red[6],red[7]));
        s_mu = __fadd_rn(a,b) * (1.0f/HDIM);
    }
    __syncthreads();
    const float mu = s_mu;
    float dx=__fadd_rn(v.x,-mu), dy=__fadd_rn(v.y,-mu),
          dz=__fadd_rn(v.z,-mu), dw=__fadd_rn(v.w,-mu);
    float sq = __fadd_rn(__fadd_rn(__fmul_rn(dx,dx),__fmul_rn(dy,dy)),
                         __fadd_rn(__fmul_rn(dz,dz),__fmul_rn(dw,dw)));
#pragma unroll
    for (int o=16;o;o>>=1) sq = __fadd_rn(sq, __shfl_xor_sync(~0u, sq, o));
    if ((t&31)==0) red[t>>5] = sq;
    __syncthreads();
    if (t==0) {
        float a = __fadd_rn(__fadd_rn(red[0],red[1]), __fadd_rn(red[2],red[3]));
        float b = __fadd_rn(__fadd_rn(red[4],red[5]), __fadd_rn(red[6],red[7]));
        s_rs = rsqrtf(__fadd_rn(a,b)*(1.0f/HDIM) + 1e-5f);
    }
    __syncthreads();
    const float rs = s_rs;

    float4 g4 = *(const float4*)(gam + t*4);
    float4 b4 = *(const float4*)(bet + t*4);
    float o0 = fmaxf(__fadd_rn(__fmul_rn(__fmul_rn(dx,rs),g4.x), b4.x), 0.f);
    float o1 = fmaxf(__fadd_rn(__fmul_rn(__fmul_rn(dy,rs),g4.y), b4.y), 0.f);
    float o2 = fmaxf(__fadd_rn(__fmul_rn(__fmul_rn(dz,rs),g4.z), b4.z), 0.f);
    float o3 = fmaxf(__fadd_rn(__fmul_rn(__fmul_rn(dw,rs),g4.w), b4.w), 0.f);
    size_t go = (size_t)row*HDIM + t*4;
    wsplit2(Yh,Ym,Yl, go,   o0, o1);
    wsplit2(Yh,Ym,Yl, go+2, o2, o3);
}

// ---------------- small kernels ----------------
__global__ void znorm_k(const float* __restrict__ z, float* __restrict__ zn)
{
    int row  = blockIdx.x*8 + (threadIdx.x >> 5);
    int lane = threadIdx.x & 31;
    float4 v = *(const float4*)(z + (size_t)row*DDIM + lane*4);
    float s = __fadd_rn(__fadd_rn(__fmul_rn(v.x,v.x), __fmul_rn(v.y,v.y)),
                        __fadd_rn(__fmul_rn(v.z,v.z), __fmul_rn(v.w,v.w)));
#pragma unroll
    for (int o=16;o;o>>=1) s = __fadd_rn(s, __shfl_xor_sync(~0u, s, o));
    if (lane == 0) zn[row] = s;
}
__global__ void prep_k(const float* __restrict__ cb, float* __restrict__ cn,
                       float* __restrict__ cbT)
{
    int k = threadIdx.x;
    double s = 0.0;
    for (int d0=0; d0<DDIM; d0++) {
        float v = cb[k*DDIM + d0];
        s += (double)v * (double)v;
        cbT[d0*KCODES + k] = v;
    }
    cn[k] = (float)s;
}
__global__ void init_k(float* loss, int* hist)
{
    int t = threadIdx.x;
    if (t == 0) *loss = 0.f;
    if (t < KCODES) hist[t] = 0;
}
__global__ void argmin_k(const float* __restrict__ S, int* __restrict__ idx,
                         float* __restrict__ idx_f)
{
    int row  = blockIdx.x*8 + (threadIdx.x >> 5);
    int lane = threadIdx.x & 31;
    const float* sr = S + (size_t)row*KCODES;
    float bv = 3.4e38f; int bk = 0;
#pragma unroll
    for (int j=0;j<8;j++) {
        int k = lane + j*32;
        float v = sr[k];
        if (v < bv) { bv = v; bk = k; }
    }
#pragma unroll
    for (int o=16;o;o>>=1) {
        float ov = __shfl_xor_sync(~0u, bv, o);
        int   ok = __shfl_xor_sync(~0u, bk, o);
        if (ov < bv || (ov == bv && ok < bk)) { bv = ov; bk = ok; }
    }
    if (lane == 0) { idx[row] = bk; idx_f[row] = (float)bk; }
}
__global__ void gather_k(const float* __restrict__ z, const float* __restrict__ cb,
                         const int* __restrict__ idx,
                         bf16* __restrict__ Qh, bf16* __restrict__ Qm, bf16* __restrict__ Ql,
                         float* __restrict__ loss, int* __restrict__ hist)
{
    int b = blockIdx.x;
    int t = threadIdx.x;
    __shared__ int   sidx[GG];
    __shared__ float red[8];
    if (t < GG) {
        int k = idx[b*GG + t];
        sidx[t] = k;
        atomicAdd(&hist[k], 1);
    }
    __syncthreads();
    int g = (t*4) >> 7;
    int e = (t*4) & 127;
    float4 c  = *(const float4*)(cb + (size_t)sidx[g]*DDIM + e);
    float4 zz = *(const float4*)(z  + (size_t)b*GD + t*4);
    float dx=__fadd_rn(c.x,-zz.x), dy=__fadd_rn(c.y,-zz.y),
          dz=__fadd_rn(c.z,-zz.z), dw=__fadd_rn(c.w,-zz.w);
    float st0=__fadd_rn(zz.x,dx), st1=__fadd_rn(zz.y,dy),
          st2=__fadd_rn(zz.z,dz), st3=__fadd_rn(zz.w,dw);
    size_t go = (size_t)b*GD + t*4;
    wsplit2(Qh,Qm,Ql, go,   st0, st1);
    wsplit2(Qh,Qm,Ql, go+2, st2, st3);
    float s = dx*dx+dy*dy+dz*dz+dw*dw;
#pragma unroll
    for (int o=16;o;o>>=1) s += __shfl_xor_sync(~0u, s, o);
    if ((t&31)==0) red[t>>5] = s;
    __syncthreads();
    if (t==0) {
        float tot=0.f;
#pragma unroll
        for (int i=0;i<8;i++) tot += red[i];
        atomicAdd(loss, tot);
    }
}
__global__ void finalize_k(const int* __restrict__ hist, const float* __restrict__ loss,
                           float* __restrict__ out)
{
    int t = threadIdx.x;
    __shared__ float red[8];
    float e = (float)hist[t] / (float)BG;
    float s = e * logf(e + 1e-10f);
#pragma unroll
    for (int o=16;o;o>>=1) s += __shfl_xor_sync(~0u, s, o);
    if ((t&31)==0) red[t>>5] = s;
    __syncthreads();
    if (t==0) {
        float tot=0.f;
#pragma unroll
        for (int i=0;i<8;i++) tot += red[i];
        out[PERP_OFF] = expf(-tot);
        out[0] = 1.25f * loss[0] / 33554432.0f;
    }
}

// ---------------- host launcher ----------------
extern "C" void kernel_launch(void* const* d_in, const int* in_sizes, int n_in,
                              void* d_out, int out_size)
{
    const float* x      = (const float*)d_in[0];
    const float* enc_w1 = (const float*)d_in[1];
    const float* enc_b1 = (const float*)d_in[2];
    const float* enc_w2 = (const float*)d_in[3];
    const float* enc_b2 = (const float*)d_in[4];
    const float* ln_g   = (const float*)d_in[5];
    const float* ln_b   = (const float*)d_in[6];
    const float* enc_w3 = (const float*)d_in[7];
    const float* enc_b3 = (const float*)d_in[8];
    const float* enc_w4 = (const float*)d_in[9];
    const float* enc_b4 = (const float*)d_in[10];
    const float* cb     = (const float*)d_in[11];
    const float* dec_w1 = (const float*)d_in[12];
    const float* dec_b1 = (const float*)d_in[13];
    const float* dec_w2 = (const float*)d_in[14];
    const float* dec_b2 = (const float*)d_in[15];
    const float* dec_w3 = (const float*)d_in[16];
    const float* dec_b3 = (const float*)d_in[17];
    float* out = (float*)d_out;

    static float *p_t2=nullptr,*p_z,*p_S,*p_zn,*p_cn,*p_cbT,*p_loss;
    static int *p_idx,*p_hist;
    static bf16 *pA0,*pA1,*pA2,*pB0,*pB1,*pB2,*px0,*px1,*px2,*pw0,*pw1,*pw2;
    if (!p_t2) {
        cudaGetSymbolAddress((void**)&p_t2,  g_t2);
        cudaGetSymbolAddress((void**)&p_z,   g_z);
        cudaGetSymbolAddress((void**)&p_S,   g_S);
        cudaGetSymbolAddress((void**)&p_zn,  g_zn);
        cudaGetSymbolAddress((void**)&p_cn,  g_cn);
        cudaGetSymbolAddress((void**)&p_cbT, g_cbT);
        cudaGetSymbolAddress((void**)&p_loss,g_loss);
        cudaGetSymbolAddress((void**)&p_idx, g_idx);
        cudaGetSymbolAddress((void**)&p_hist,g_hist);
        cudaGetSymbolAddress((void**)&pA0, g_bA0);
        cudaGetSymbolAddress((void**)&pA1, g_bA1);
        cudaGetSymbolAddress((void**)&pA2, g_bA2);
        cudaGetSymbolAddress((void**)&pB0, g_bB0);
        cudaGetSymbolAddress((void**)&pB1, g_bB1);
        cudaGetSymbolAddress((void**)&pB2, g_bB2);
        cudaGetSymbolAddress((void**)&px0, g_xs0);
        cudaGetSymbolAddress((void**)&px1, g_xs1);
        cudaGetSymbolAddress((void**)&px2, g_xs2);
        cudaGetSymbolAddress((void**)&pw0, g_wt0);
        cudaGetSymbolAddress((void**)&pw1, g_wt1);
        cudaGetSymbolAddress((void**)&pw2, g_wt2);
        cudaFuncSetAttribute(emgemm_k<1,2>, cudaFuncAttributeMaxDynamicSharedMemorySize, 73728);
        cudaFuncSetAttribute(emgemm_k<0,0>, cudaFuncAttributeMaxDynamicSharedMemorySize, 73728);
        cudaFuncSetAttribute(mgemm_k<128,1,2>, cudaFuncAttributeMaxDynamicSharedMemorySize, 98304);
        cudaFuncSetAttribute(mgemm_k< 64,0,1>, cudaFuncAttributeMaxDynamicSharedMemorySize, 73728);
    }
    const int SM128 = 98304, SM64 = 73728;

    prep_k<<<1,256>>>(cb, p_cn, p_cbT);
    init_k<<<1,256>>>(p_loss, p_hist);

    tsplit_k<<<(64*1024+255)/256,256>>>(enc_w1, 64, 1024, pw0+OFF_W1, pw1+OFF_W1, pw2+OFF_W1);
    tsplit_k<<<(1024*1024+255)/256,256>>>(enc_w2, 1024, 1024, pw0+OFF_W2, pw1+OFF_W2, pw2+OFF_W2);
    tsplit_k<<<(1024*1024+255)/256,256>>>(enc_w3, 1024, 1024, pw0+OFF_W3, pw1+OFF_W3, pw2+OFF_W3);
    tsplit_k<<<(128*128+255)/256,256>>>(enc_w4, 128, 128, pw0+OFF_W4, pw1+OFF_W4, pw2+OFF_W4);
    tsplit_k<<<(1024*1024+255)/256,256>>>(dec_w1, 1024, 1024, pw0+OFF_D1, pw1+OFF_D1, pw2+OFF_D1);
    tsplit_k<<<(1024*1024+255)/256,256>>>(dec_w2, 1024, 1024, pw0+OFF_D2, pw1+OFF_D2, pw2+OFF_D2);
    tsplit_k<<<(1024*64+255)/256,256>>>(dec_w3, 1024, 64, pw0+OFF_D3, pw1+OFF_D3, pw2+OFF_D3);
    xsplit_k<<<(B_SZ*STATE_NN+255)/256,256>>>(x, B_SZ*STATE_NN, px0, px1, px2);

    // ---- encoder (HMMA 6-product, split accumulators) ----
    emgemm_k<1,2><<<dim3(16, B_SZ/128), 256, SM64>>>(px0,px1,px2,
        pw0+OFF_W1,pw1+OFF_W1,pw2+OFF_W1, enc_b1, nullptr, pA0,pA1,pA2, HDIM, 64);
    emgemm_k<0,0><<<dim3(16, B_SZ/128), 256, SM64>>>(pA0,pA1,pA2,
        pw0+OFF_W2,pw1+OFF_W2,pw2+OFF_W2, enc_b2, p_t2, nullptr,nullptr,nullptr, HDIM, HDIM);
    ln_relu_k<<<B_SZ,256>>>(p_t2, ln_g, ln_b, pB0, pB1, pB2);
    emgemm_k<1,2><<<dim3(16, B_SZ/128), 256, SM64>>>(pB0,pB1,pB2,
        pw0+OFF_W3,pw1+OFF_W3,pw2+OFF_W3, enc_b3, nullptr, pA0,pA1,pA2, HDIM, HDIM);
    emgemm_k<0,0><<<dim3(2, BG/128), 256, SM64>>>(pA0,pA1,pA2,
        pw0+OFF_W4,pw1+OFF_W4,pw2+OFF_W4, enc_b4, p_z, nullptr,nullptr,nullptr, DDIM, DDIM);

    // ---- VQ (byte-identical to R8/R13 pass) ----
    znorm_k<<<BG/8,256>>>(p_z, p_zn);
    gemm_vq2_k<128,64,16,8,4><<<dim3(KCODES/64, BG/128), 256>>>(p_z, p_cbT, p_cn, p_zn, p_S, BG, KCODES, DDIM);
    argmin_k<<<BG/8,256>>>(p_S, p_idx, out + IDX_OFF);
    gather_k<<<B_SZ,256>>>(p_z, cb, p_idx, pB0, pB1, pB2, p_loss, p_hist);
    finalize_k<<<1,256>>>(p_hist, p_loss, out);

    // ---- decoder (HMMA 3-product, byte-identical to R13 pass) ----
    mgemm_k<128,1,2><<<dim3(8, B_SZ/128), 256, SM128>>>(pB0,pB1,pB2,
        pw0+OFF_D1,pw1+OFF_D1,pw2+OFF_D1, dec_b1, nullptr, pA0,pA1,pA2, HDIM, HDIM);
    mgemm_k<128,1,2><<<dim3(8, B_SZ/128), 256, SM128>>>(pA0,pA1,pA2,
        pw0+OFF_D2,pw1+OFF_D2,pw2+OFF_D2, dec_b2, nullptr, pB0,pB1,pB2, HDIM, HDIM);
    mgemm_k<64,0,1><<<dim3(1, B_SZ/128), 256, SM64>>>(pB0,pB1,pB2,
        pw0+OFF_D3,pw1+OFF_D3,pw2+OFF_D3, dec_b3, out + DEC_OFF, nullptr,nullptr,nullptr, STATE_NN, HDIM);
}

// round 15
// speedup vs baseline: 1.7638x; 1.2285x over previous
#include <cuda_runtime.h>
#include <cuda_bf16.h>
#include <cstdint>
#include <cmath>

#define B_SZ    32768
#define STATE_NN 64
#define HDIM    1024
#define KCODES  256
#define DDIM    128
#define GG      8
#define BG      (B_SZ*GG)
#define GD      (GG*DDIM)
#define DEC_OFF  1
#define PERP_OFF (1 + B_SZ*STATE_NN)
#define IDX_OFF  (2 + B_SZ*STATE_NN)

typedef unsigned long long u64;
typedef __nv_bfloat16 bf16;

// ---------------- device scratch ----------------
__device__ float g_t2[(size_t)B_SZ*HDIM];
__device__ float g_z [(size_t)B_SZ*GD];
__device__ u64   g_key[BG];
__device__ float g_zn[BG];
__device__ int   g_idx[BG];
__device__ int   g_hist[KCODES];
__device__ float g_cn[KCODES];
__device__ float g_cbT[DDIM*KCODES];
__device__ float g_loss[1];

__device__ __align__(16) bf16 g_bA0[(size_t)B_SZ*HDIM];
__device__ __align__(16) bf16 g_bA1[(size_t)B_SZ*HDIM];
__device__ __align__(16) bf16 g_bA2[(size_t)B_SZ*HDIM];
__device__ __align__(16) bf16 g_bB0[(size_t)B_SZ*HDIM];
__device__ __align__(16) bf16 g_bB1[(size_t)B_SZ*HDIM];
__device__ __align__(16) bf16 g_bB2[(size_t)B_SZ*HDIM];
__device__ __align__(16) bf16 g_xs0[(size_t)B_SZ*STATE_NN];
__device__ __align__(16) bf16 g_xs1[(size_t)B_SZ*STATE_NN];
__device__ __align__(16) bf16 g_xs2[(size_t)B_SZ*STATE_NN];

#define OFF_W1 0
#define OFF_W2 65536
#define OFF_W3 1114112
#define OFF_W4 2162688
#define OFF_D1 2179072
#define OFF_D2 3227648
#define OFF_D3 4276224
#define WT_TOT 4341760
__device__ __align__(16) bf16 g_wt0[WT_TOT];
__device__ __align__(16) bf16 g_wt1[WT_TOT];
__device__ __align__(16) bf16 g_wt2[WT_TOT];

// ---------------- helpers ----------------
__device__ __forceinline__ u64 pack2(float lo, float hi){
    u64 r; asm("mov.b64 %0, {%1,%2};" : "=l"(r) : "f"(lo), "f"(hi)); return r; }
__device__ __forceinline__ void unpack2(u64 v, float &lo, float &hi){
    asm("mov.b64 {%0,%1}, %2;" : "=f"(lo), "=f"(hi) : "l"(v)); }
__device__ __forceinline__ u64 ffma2(u64 a, u64 b, u64 c){
    u64 d; asm("fma.rn.f32x2 %0, %1, %2, %3;" : "=l"(d) : "l"(a), "l"(b), "l"(c)); return d; }
__device__ __forceinline__ uint32_t smem_u32(const void* p){
    uint32_t a; asm("{ .reg .u64 t; cvta.to.shared.u64 t, %1; cvt.u32.u64 %0, t; }" : "=r"(a) : "l"(p));
    return a; }
__device__ __forceinline__ void split3(float v, bf16 &h, bf16 &m, bf16 &l){
    h = __float2bfloat16(v);
    float r1 = v - __bfloat162float(h);
    m = __float2bfloat16(r1);
    l = __float2bfloat16(r1 - __bfloat162float(m)); }
__device__ __forceinline__ void wsplit2(bf16* H, bf16* M, bf16* L, size_t go, float a, float b){
    bf16 h0,m0,l0,h1,m1,l1; split3(a,h0,m0,l0); split3(b,h1,m1,l1);
    __nv_bfloat162 p;
    p.x=h0; p.y=h1; *(__nv_bfloat162*)(H+go)=p;
    p.x=m0; p.y=m1; *(__nv_bfloat162*)(M+go)=p;
    p.x=l0; p.y=l1; *(__nv_bfloat162*)(L+go)=p; }
__device__ __forceinline__ uint32_t ford(float v){
    uint32_t b = __float_as_uint(v);
    return (b & 0x80000000u) ? ~b : (b | 0x80000000u); }

#define CP16(dst, src) asm volatile("cp.async.cg.shared.global [%0], [%1], 16;" :: "r"(dst), "l"(src) : "memory")
#define CPCOMMIT       asm volatile("cp.async.commit_group;" ::: "memory")
#define CPWAIT0        asm volatile("cp.async.wait_group 0;" ::: "memory")
__device__ __forceinline__ void ldsm4(uint32_t &r0,uint32_t &r1,uint32_t &r2,uint32_t &r3,uint32_t a){
    asm volatile("ldmatrix.sync.aligned.m8n8.x4.shared.b16 {%0,%1,%2,%3}, [%4];"
        : "=r"(r0),"=r"(r1),"=r"(r2),"=r"(r3) : "r"(a)); }
__device__ __forceinline__ void mma16816(float* c, const uint32_t* a, uint32_t b0, uint32_t b1){
    asm volatile("mma.sync.aligned.m16n8k16.row.col.f32.bf16.bf16.f32 "
        "{%0,%1,%2,%3},{%4,%5,%6,%7},{%8,%9},{%0,%1,%2,%3};"
        : "+f"(c[0]),"+f"(c[1]),"+f"(c[2]),"+f"(c[3])
        : "r"(a[0]),"r"(a[1]),"r"(a[2]),"r"(a[3]), "r"(b0),"r"(b1)); }
#define SWO(r,c) ((r)*64 + (((c) ^ (((r)>>1)&3))<<4))

// =====================================================================
// ENCODER HMMA GEMM (byte-identical to R14 pass): 6-product, split acc.
// =====================================================================
template<int ACT, int OUTM>
__global__ void __launch_bounds__(256,1)
emgemm_k(const bf16* __restrict__ A0,const bf16* __restrict__ A1,const bf16* __restrict__ A2,
         const bf16* __restrict__ Bb0,const bf16* __restrict__ Bb1,const bf16* __restrict__ Bb2,
         const float* __restrict__ bias, float* __restrict__ C,
         bf16* __restrict__ Ch, bf16* __restrict__ Cm, bf16* __restrict__ Cl,
         int Ncols, int K)
{
    constexpr int BN_  = 64;
    constexpr int MT   = 2;
    constexpr int NTT  = 4;
    constexpr int ASZ  = 128*64;
    constexpr int BSZ  = BN_*64;
    constexpr int STAGE= 3*ASZ + 3*BSZ;

    extern __shared__ char smem[];
    const uint32_t sb = smem_u32(smem);
    const int tid = threadIdx.x, wid = tid>>5, lane = tid&31;
    const int wm = wid>>1, wn = wid&1;
    const int wmB = wm*32, wnB = wn*32;
    const int bCol0 = blockIdx.x*BN_;
    const int aRow0 = blockIdx.y*128;

    const bf16* Ap[3]={A0,A1,A2};
    const bf16* Bp[3]={Bb0,Bb1,Bb2};

    float acc0[MT][NTT][4], acc1[MT][NTT][4];
#pragma unroll
    for (int i=0;i<MT;i++)
#pragma unroll
        for (int j=0;j<NTT;j++)
#pragma unroll
            for (int q=0;q<4;q++){ acc0[i][j][q]=0.f; acc1[i][j][q]=0.f; }

    auto issue = [&](int kb, int st){
        uint32_t base = sb + st*STAGE;
#pragma unroll
        for (int i0=0; i0<3*512; i0+=256){
            int i = i0 + tid;
            int l = i>>9, rem = i&511, r = rem>>2, c = rem&3;
            CP16(base + l*ASZ + SWO(r,c),
                 Ap[l] + (size_t)(aRow0+r)*K + kb + c*8);
        }
#pragma unroll
        for (int i0=0; i0<3*BN_*4; i0+=256){
            int i = i0 + tid;
            int l = i/(BN_*4), rem = i%(BN_*4), r = rem>>2, c = rem&3;
            CP16(base + 3*ASZ + l*BSZ + SWO(r,c),
                 Bp[l] + (size_t)(bCol0+r)*K + kb + c*8);
        }
        CPCOMMIT;
    };

    const int T = K/32;
    issue(0,0);
    for (int t=0; t<T; ++t){
        CPWAIT0;
        __syncthreads();
        if (t+1 < T) issue((t+1)*32, (t+1)&1);
        const uint32_t base = sb + (t&1)*STAGE;
#pragma unroll
        for (int ks=0; ks<2; ++ks){
            uint32_t af[3][MT][4];
#pragma unroll
            for (int l=0;l<3;l++)
#pragma unroll
                for (int mt=0;mt<MT;mt++){
                    int r = wmB + mt*16 + (lane&15);
                    int c = ks*2 + (lane>>4);
                    ldsm4(af[l][mt][0],af[l][mt][1],af[l][mt][2],af[l][mt][3],
                          base + l*ASZ + SWO(r,c));
                }
#pragma unroll
            for (int bl=0; bl<3; ++bl){
                uint32_t bfr[NTT/2][4];
#pragma unroll
                for (int np=0; np<NTT/2; np++){
                    int r = wnB + np*16 + ((lane>>4)<<3) + (lane&7);
                    int c = ks*2 + ((lane>>3)&1);
                    ldsm4(bfr[np][0],bfr[np][1],bfr[np][2],bfr[np][3],
                          base + 3*ASZ + bl*BSZ + SWO(r,c));
                }
                const int na = (bl==0)?3:(bl==1?2:1);
#pragma unroll
                for (int al=0; al<3; ++al){
                    if (al < na){
                        float (*acc)[NTT][4] = (al==0 && bl==0) ? acc0 : acc1;
#pragma unroll
                        for (int mt=0;mt<MT;mt++)
#pragma unroll
                            for (int nt=0;nt<NTT;nt++)
                                mma16816(acc[mt][nt], af[al][mt],
                                         bfr[nt>>1][(nt&1)*2], bfr[nt>>1][(nt&1)*2+1]);
                    }
                }
            }
        }
    }

#pragma unroll
    for (int mt=0;mt<MT;mt++){
        int rbase = aRow0 + wmB + mt*16 + (lane>>2);
#pragma unroll
        for (int half=0; half<2; ++half){
            size_t r = (size_t)rbase + half*8;
#pragma unroll
            for (int nt=0;nt<NTT;nt++){
                int cc = bCol0 + wnB + nt*8 + (lane&3)*2;
                float v0 = (acc0[mt][nt][half*2+0] + acc1[mt][nt][half*2+0]) + bias[cc];
                float v1 = (acc0[mt][nt][half*2+1] + acc1[mt][nt][half*2+1]) + bias[cc+1];
                if (ACT==1){ v0 = fmaxf(v0,0.f); v1 = fmaxf(v1,0.f); }
                size_t go = r*(size_t)Ncols + cc;
                if (OUTM==0){ float2 o; o.x=v0; o.y=v1; *(float2*)(C+go)=o; }
                else wsplit2(Ch,Cm,Cl, go, v0, v1);
            }
        }
    }
}

// =====================================================================
// DECODER HMMA GEMM (byte-identical to R13/R14 pass): 3-product split.
// =====================================================================
template<int BN_, int ACT, int OUTM>
__global__ void __launch_bounds__(256,1)
mgemm_k(const bf16* __restrict__ A0,const bf16* __restrict__ A1,const bf16* __restrict__ A2,
        const bf16* __restrict__ Bb0,const bf16* __restrict__ Bb1,const bf16* __restrict__ Bb2,
        const float* __restrict__ bias, float* __restrict__ C,
        bf16* __restrict__ Ch, bf16* __restrict__ Cm, bf16* __restrict__ Cl,
        int Ncols, int K)
{
    constexpr int ALEV = 2;
    constexpr int WM   = (BN_==128)?2:4;
    constexpr int WN   = 8/WM;
    constexpr int MT   = 128/(WM*16);
    constexpr int NTT  = BN_/(WN*8);
    constexpr int ASZ  = 128*64;
    constexpr int BSZ  = BN_*64;
    constexpr int STAGE= 3*ASZ + 3*BSZ;

    extern __shared__ char smem[];
    const uint32_t sb = smem_u32(smem);
    const int tid = threadIdx.x, wid = tid>>5, lane = tid&31;
    const int wm = (WM==2)?(wid>>2):(wid>>1);
    const int wn = (WM==2)?(wid&3):(wid&1);
    const int wmB = wm*MT*16, wnB = wn*NTT*8;
    const int bCol0 = blockIdx.x*BN_;
    const int aRow0 = blockIdx.y*128;

    const bf16* Ap[3]={A0,A1,A2};
    const bf16* Bp[3]={Bb0,Bb1,Bb2};

    float acc[MT][NTT][4];
#pragma unroll
    for (int i=0;i<MT;i++)
#pragma unroll
        for (int j=0;j<NTT;j++)
#pragma unroll
            for (int q=0;q<4;q++) acc[i][j][q]=0.f;

    auto issue = [&](int kb, int st){
        uint32_t base = sb + st*STAGE;
#pragma unroll
        for (int i0=0; i0<ALEV*512; i0+=256){
            int i = i0 + tid;
            int l = i>>9, rem = i&511, r = rem>>2, c = rem&3;
            CP16(base + l*ASZ + SWO(r,c),
                 Ap[l] + (size_t)(aRow0+r)*K + kb + c*8);
        }
#pragma unroll
        for (int i0=0; i0<ALEV*BN_*4; i0+=256){
            int i = i0 + tid;
            int l = i/(BN_*4), rem = i%(BN_*4), r = rem>>2, c = rem&3;
            CP16(base + 3*ASZ + l*BSZ + SWO(r,c),
                 Bp[l] + (size_t)(bCol0+r)*K + kb + c*8);
        }
        CPCOMMIT;
    };

    const int T = K/32;
    issue(0,0);
    for (int t=0; t<T; ++t){
        CPWAIT0;
        __syncthreads();
        if (t+1 < T) issue((t+1)*32, (t+1)&1);
        const uint32_t base = sb + (t&1)*STAGE;
#pragma unroll
        for (int ks=0; ks<2; ++ks){
            uint32_t af[ALEV][MT][4];
#pragma unroll
            for (int l=0;l<ALEV;l++)
#pragma unroll
                for (int mt=0;mt<MT;mt++){
                    int r = wmB + mt*16 + (lane&15);
                    int c = ks*2 + (lane>>4);
                    ldsm4(af[l][mt][0],af[l][mt][1],af[l][mt][2],af[l][mt][3],
                          base + l*ASZ + SWO(r,c));
                }
#pragma unroll
            for (int bl=0; bl<ALEV; ++bl){
                uint32_t bfr[NTT/2][4];
#pragma unroll
                for (int np=0; np<NTT/2; np++){
                    int r = wnB + np*16 + ((lane>>4)<<3) + (lane&7);
                    int c = ks*2 + ((lane>>3)&1);
                    ldsm4(bfr[np][0],bfr[np][1],bfr[np][2],bfr[np][3],
                          base + 3*ASZ + bl*BSZ + SWO(r,c));
                }
                const int na = (bl==0?2:1);
#pragma unroll
                for (int al=0; al<ALEV; ++al){
                    if (al < na){
#pragma unroll
                        for (int mt=0;mt<MT;mt++)
#pragma unroll
                            for (int nt=0;nt<NTT;nt++)
                                mma16816(acc[mt][nt], af[al][mt],
                                         bfr[nt>>1][(nt&1)*2], bfr[nt>>1][(nt&1)*2+1]);
                    }
                }
            }
        }
    }

#pragma unroll
    for (int mt=0;mt<MT;mt++){
        int rbase = aRow0 + wmB + mt*16 + (lane>>2);
#pragma unroll
        for (int half=0; half<2; ++half){
            size_t r = (size_t)rbase + half*8;
#pragma unroll
            for (int nt=0;nt<NTT;nt++){
                int cc = bCol0 + wnB + nt*8 + (lane&3)*2;
                float v0 = acc[mt][nt][half*2+0] + bias[cc];
                float v1 = acc[mt][nt][half*2+1] + bias[cc+1];
                if (ACT==1){ v0 = fmaxf(v0,0.f); v1 = fmaxf(v1,0.f); }
                size_t go = r*(size_t)Ncols + cc;
                if (OUTM==1){ C[go]=v0; C[go+1]=v1; }
                else wsplit2(Ch,Cm,Cl, go, v0, v1);
            }
        }
    }
}

// =====================================================================
// VQ GEMM, plain FFMA2 dot (R8/R6 fragment layout, dbuf) + reference
// grid epilogue + FUSED argmin via order-preserving (S,k) keys.
// BM=128, BN=128, BK=16.  grid = (KCODES/128, BG/128).
// =====================================================================
__global__ void __launch_bounds__(256,2)
gemm_vqf_k(const float* __restrict__ A, const float* __restrict__ Bm,
           const float* __restrict__ cn, const float* __restrict__ zn,
           u64* __restrict__ gkey, int M, int N, int K)
{
    constexpr int BM=128, BN=128, BK=16, TM=8, TN=8;
    constexpr int MG = TM/4;
    constexpr int NG = TN/4;
    constexpr int ASTEP = (256/BM)*4;
    constexpr int ANUM  = BK/ASTEP;
    constexpr int BNUM  = (BK*BN)/(256*4);

    __shared__ float As[2][BK][BM];
    __shared__ float Bs[2][BK][BN];
    __shared__ u64 rowkey[BM];

    const int tid  = threadIdx.x;
    const int tcol = tid % (BN/TN);
    const int trow = tid / (BN/TN);
    const int aRow0 = blockIdx.y * BM;
    const int bCol0 = blockIdx.x * BN;
    const int lr = tid % BM;
    const int ls = tid / BM;

    u64 acc[TM][TN/2];
#pragma unroll
    for (int i=0;i<TM;i++)
#pragma unroll
        for (int j=0;j<TN/2;j++) acc[i][j] = 0ULL;

#pragma unroll
    for (int i=0;i<ANUM;i++) {
        int c0 = ls*4 + i*ASTEP;
        float4 v = *(const float4*)(A + (size_t)(aRow0+lr)*K + c0);
        As[0][c0+0][lr]=v.x; As[0][c0+1][lr]=v.y;
        As[0][c0+2][lr]=v.z; As[0][c0+3][lr]=v.w;
    }
#pragma unroll
    for (int it=0; it<BNUM; ++it) {
        int idx4 = (tid + it*256)*4;
        int r = idx4 / BN, c = idx4 % BN;
        *(float4*)&Bs[0][r][c] = *(const float4*)(Bm + (size_t)r*N + bCol0 + c);
    }
    if (tid < BM) rowkey[tid] = ~0ULL;
    __syncthreads();

    const int NIT = K/BK;
    for (int itk=0; itk<NIT; ++itk) {
        const int cur = itk & 1, nxt = cur ^ 1;
        const int k1 = (itk+1)*BK;
        float4 avp[ANUM], bvp[BNUM];
        if (itk+1 < NIT) {
#pragma unroll
            for (int i=0;i<ANUM;i++) {
                int c0 = ls*4 + i*ASTEP;
                avp[i] = *(const float4*)(A + (size_t)(aRow0+lr)*K + k1 + c0);
            }
#pragma unroll
            for (int it=0; it<BNUM; ++it) {
                int idx4 = (tid + it*256)*4;
                int r = idx4 / BN, c = idx4 % BN;
                bvp[it] = *(const float4*)(Bm + (size_t)(k1+r)*N + bCol0 + c);
            }
        }
#pragma unroll
        for (int kk=0; kk<BK; kk++) {
            u64 ar2[TM], br2[TN/2];
#pragma unroll
            for (int h=0; h<MG; h++) {
                float4 av = *(const float4*)&As[cur][kk][h*(BM/2) + trow*4];
                ar2[h*4+0] = pack2(av.x, av.x);
                ar2[h*4+1] = pack2(av.y, av.y);
                ar2[h*4+2] = pack2(av.z, av.z);
                ar2[h*4+3] = pack2(av.w, av.w);
            }
#pragma unroll
            for (int g=0; g<NG; g++) {
                ulonglong2 bv = *(const ulonglong2*)&Bs[cur][kk][g*(BN/2) + tcol*4];
                br2[g*2+0] = bv.x;
                br2[g*2+1] = bv.y;
            }
#pragma unroll
            for (int i=0;i<TM;i++)
#pragma unroll
                for (int j=0;j<TN/2;j++)
                    acc[i][j] = ffma2(ar2[i], br2[j], acc[i][j]);
        }
        if (itk+1 < NIT) {
#pragma unroll
            for (int i=0;i<ANUM;i++) {
                int c0 = ls*4 + i*ASTEP;
                As[nxt][c0+0][lr]=avp[i].x; As[nxt][c0+1][lr]=avp[i].y;
                As[nxt][c0+2][lr]=avp[i].z; As[nxt][c0+3][lr]=avp[i].w;
            }
#pragma unroll
            for (int it=0; it<BNUM; ++it) {
                int idx4 = (tid + it*256)*4;
                int r = idx4 / BN, c = idx4 % BN;
                *(float4*)&Bs[nxt][r][c] = bvp[it];
            }
        }
        __syncthreads();
    }

    // epilogue: S = fl(fl(zn+cn) - 2*dot), min-key per row, smem+global atomicMin
#pragma unroll
    for (int h=0; h<MG; h++) {
#pragma unroll
        for (int i=0;i<4;i++) {
            int rl = h*(BM/2) + trow*4 + i;
            size_t r = (size_t)aRow0 + rl;
            float zr = zn[r];
            u64 best = ~0ULL;
#pragma unroll
            for (int g=0; g<NG; g++) {
                int c0 = bCol0 + g*(BN/2) + tcol*4;
#pragma unroll
                for (int jp=0; jp<2; ++jp) {
                    float d0, d1;
                    unpack2(acc[h*4+i][g*2+jp], d0, d1);
                    int c = c0 + 2*jp;
                    float t0 = __fadd_rn(zr, cn[c]);
                    float t1 = __fadd_rn(zr, cn[c+1]);
                    float s0 = __fadd_rn(t0, __fmul_rn(-2.f, d0));
                    float s1 = __fadd_rn(t1, __fmul_rn(-2.f, d1));
                    u64 k0 = ((u64)ford(s0) << 32) | (u64)(uint32_t)c;
                    u64 k1 = ((u64)ford(s1) << 32) | (u64)(uint32_t)(c+1);
                    best = min(best, min(k0, k1));
                }
            }
            atomicMin(&rowkey[rl], best);
        }
    }
    __syncthreads();
    if (tid < BM) atomicMin(&gkey[aRow0 + tid], rowkey[tid]);
}

// ---------------- key init + idx extraction ----------------
__global__ void initkey_k(u64* __restrict__ gkey, float* loss, int* hist)
{
    int e = blockIdx.x*256 + threadIdx.x;
    if (e < BG) gkey[e] = ~0ULL;
    if (blockIdx.x == 0) {
        if (threadIdx.x == 0) *loss = 0.f;
        if (threadIdx.x < KCODES) hist[threadIdx.x] = 0;
    }
}
__global__ void idx_k(const u64* __restrict__ gkey, int* __restrict__ idx,
                      float* __restrict__ idx_f)
{
    int e = blockIdx.x*256 + threadIdx.x;
    if (e >= BG) return;
    int k = (int)(gkey[e] & 0xFFFFFFFFu);
    idx[e] = k;
    idx_f[e] = (float)k;
}

// ---------------- weight transpose+split (coalesced stores) ----------------
__global__ void tsplit_k(const float* __restrict__ W, int Kd, int Nd,
                         bf16* __restrict__ dh, bf16* __restrict__ dm, bf16* __restrict__ dl)
{
    int e = blockIdx.x*256 + threadIdx.x;   // output index: e = n*Kd + k
    if (e >= Kd*Nd) return;
    int n = e / Kd, k = e % Kd;
    bf16 h,m,l; split3(W[(size_t)k*Nd + n], h,m,l);
    dh[e]=h; dm[e]=m; dl[e]=l;
}
__global__ void xsplit_k(const float* __restrict__ X, int n,
                         bf16* __restrict__ dh, bf16* __restrict__ dm, bf16* __restrict__ dl)
{
    int e = blockIdx.x*256 + threadIdx.x;
    if (e >= n) return;
    bf16 h,m,l; split3(X[e], h,m,l);
    dh[e]=h; dm[e]=m; dl[e]=l;
}

// ---------------- LayerNorm + ReLU -> bf16 splits (R14-identical) ----------------
__global__ void ln_relu_k(const float* __restrict__ X, const float* __restrict__ gam,
                          const float* __restrict__ bet,
                          bf16* __restrict__ Yh, bf16* __restrict__ Ym, bf16* __restrict__ Yl)
{
    const int row = blockIdx.x;
    const int t   = threadIdx.x;
    __shared__ float red[8];
    __shared__ float s_mu, s_rs;

    float4 v = *(const float4*)(X + (size_t)row*HDIM + t*4);
    float s = __fadd_rn(__fadd_rn(v.x,v.y), __fadd_rn(v.z,v.w));
#pragma unroll
    for (int o=16;o;o>>=1) s = __fadd_rn(s, __shfl_xor_sync(~0u, s, o));
    if ((t&31)==0) red[t>>5] = s;
    __syncthreads();
    if (t==0) {
        float a = __fadd_rn(__fadd_rn(red[0],red[1]), __fadd_rn(red[2],red[3]));
        float b = __fadd_rn(__fadd_rn(red[4],red[5]), __fadd_rn(red[6],red[7]));
        s_mu = __fadd_rn(a,b) * (1.0f/HDIM);
    }
    __syncthreads();
    const float mu = s_mu;
    float dx=__fadd_rn(v.x,-mu), dy=__fadd_rn(v.y,-mu),
          dz=__fadd_rn(v.z,-mu), dw=__fadd_rn(v.w,-mu);
    float sq = __fadd_rn(__fadd_rn(__fmul_rn(dx,dx),__fmul_rn(dy,dy)),
                         __fadd_rn(__fmul_rn(dz,dz),__fmul_rn(dw,dw)));
#pragma unroll
    for (int o=16;o;o>>=1) sq = __fadd_rn(sq, __shfl_xor_sync(~0u, sq, o));
    if ((t&31)==0) red[t>>5] = sq;
    __syncthreads();
    if (t==0) {
        float a = __fadd_rn(__fadd_rn(red[0],red[1]), __fadd_rn(red[2],red[3]));
        float b = __fadd_rn(__fadd_rn(red[4],red[5]), __fadd_rn(red[6],red[7]));
        s_rs = rsqrtf(__fadd_rn(a,b)*(1.0f/HDIM) + 1e-5f);
    }
    __syncthreads();
    const float rs = s_rs;

    float4 g4 = *(const float4*)(gam + t*4);
    float4 b4 = *(const float4*)(bet + t*4);
    float o0 = fmaxf(__fadd_rn(__fmul_rn(__fmul_rn(dx,rs),g4.x), b4.x), 0.f);
    float o1 = fmaxf(__fadd_rn(__fmul_rn(__fmul_rn(dy,rs),g4.y), b4.y), 0.f);
    float o2 = fmaxf(__fadd_rn(__fmul_rn(__fmul_rn(dz,rs),g4.z), b4.z), 0.f);
    float o3 = fmaxf(__fadd_rn(__fmul_rn(__fmul_rn(dw,rs),g4.w), b4.w), 0.f);
    size_t go = (size_t)row*HDIM + t*4;
    wsplit2(Yh,Ym,Yl, go,   o0, o1);
    wsplit2(Yh,Ym,Yl, go+2, o2, o3);
}

// ---------------- small kernels (R14-identical) ----------------
__global__ void znorm_k(const float* __restrict__ z, float* __restrict__ zn)
{
    int row  = blockIdx.x*8 + (threadIdx.x >> 5);
    int lane = threadIdx.x & 31;
    float4 v = *(const float4*)(z + (size_t)row*DDIM + lane*4);
    float s = __fadd_rn(__fadd_rn(__fmul_rn(v.x,v.x), __fmul_rn(v.y,v.y)),
                        __fadd_rn(__fmul_rn(v.z,v.z), __fmul_rn(v.w,v.w)));
#pragma unroll
    for (int o=16;o;o>>=1) s = __fadd_rn(s, __shfl_xor_sync(~0u, s, o));
    if (lane == 0) zn[row] = s;
}
__global__ void prep_k(const float* __restrict__ cb, float* __restrict__ cn,
                       float* __restrict__ cbT)
{
    int k = threadIdx.x;
    double s = 0.0;
    for (int d0=0; d0<DDIM; d0++) {
        float v = cb[k*DDIM + d0];
        s += (double)v * (double)v;
        cbT[d0*KCODES + k] = v;
    }
    cn[k] = (float)s;
}
__global__ void gather_k(const float* __restrict__ z, const float* __restrict__ cb,
                         const int* __restrict__ idx,
                         bf16* __restrict__ Qh, bf16* __restrict__ Qm, bf16* __restrict__ Ql,
                         float* __restrict__ loss, int* __restrict__ hist)
{
    int b = blockIdx.x;
    int t = threadIdx.x;
    __shared__ int   sidx[GG];
    __shared__ float red[8];
    if (t < GG) {
        int k = idx[b*GG + t];
        sidx[t] = k;
        atomicAdd(&hist[k], 1);
    }
    __syncthreads();
    int g = (t*4) >> 7;
    int e = (t*4) & 127;
    float4 c  = *(const float4*)(cb + (size_t)sidx[g]*DDIM + e);
    float4 zz = *(const float4*)(z  + (size_t)b*GD + t*4);
    float dx=__fadd_rn(c.x,-zz.x), dy=__fadd_rn(c.y,-zz.y),
          dz=__fadd_rn(c.z,-zz.z), dw=__fadd_rn(c.w,-zz.w);
    float st0=__fadd_rn(zz.x,dx), st1=__fadd_rn(zz.y,dy),
          st2=__fadd_rn(zz.z,dz), st3=__fadd_rn(zz.w,dw);
    size_t go = (size_t)b*GD + t*4;
    wsplit2(Qh,Qm,Ql, go,   st0, st1);
    wsplit2(Qh,Qm,Ql, go+2, st2, st3);
    float s = dx*dx+dy*dy+dz*dz+dw*dw;
#pragma unroll
    for (int o=16;o;o>>=1) s += __shfl_xor_sync(~0u, s, o);
    if ((t&31)==0) red[t>>5] = s;
    __syncthreads();
    if (t==0) {
        float tot=0.f;
#pragma unroll
        for (int i=0;i<8;i++) tot += red[i];
        atomicAdd(loss, tot);
    }
}
__global__ void finalize_k(const int* __restrict__ hist, const float* __restrict__ loss,
                           float* __restrict__ out)
{
    int t = threadIdx.x;
    __shared__ float red[8];
    float e = (float)hist[t] / (float)BG;
    float s = e * logf(e + 1e-10f);
#pragma unroll
    for (int o=16;o;o>>=1) s += __shfl_xor_sync(~0u, s, o);
    if ((t&31)==0) red[t>>5] = s;
    __syncthreads();
    if (t==0) {
        float tot=0.f;
#pragma unroll
        for (int i=0;i<8;i++) tot += red[i];
        out[PERP_OFF] = expf(-tot);
        out[0] = 1.25f * loss[0] / 33554432.0f;
    }
}

// ---------------- host launcher ----------------
extern "C" void kernel_launch(void* const* d_in, const int* in_sizes, int n_in,
                              void* d_out, int out_size)
{
    const float* x      = (const float*)d_in[0];
    const float* enc_w1 = (const float*)d_in[1];
    const float* enc_b1 = (const float*)d_in[2];
    const float* enc_w2 = (const float*)d_in[3];
    const float* enc_b2 = (const float*)d_in[4];
    const float* ln_g   = (const float*)d_in[5];
    const float* ln_b   = (const float*)d_in[6];
    const float* enc_w3 = (const float*)d_in[7];
    const float* enc_b3 = (const float*)d_in[8];
    const float* enc_w4 = (const float*)d_in[9];
    const float* enc_b4 = (const float*)d_in[10];
    const float* cb     = (const float*)d_in[11];
    const float* dec_w1 = (const float*)d_in[12];
    const float* dec_b1 = (const float*)d_in[13];
    const float* dec_w2 = (const float*)d_in[14];
    const float* dec_b2 = (const float*)d_in[15];
    const float* dec_w3 = (const float*)d_in[16];
    const float* dec_b3 = (const float*)d_in[17];
    float* out = (float*)d_out;

    static float *p_t2=nullptr,*p_z,*p_zn,*p_cn,*p_cbT,*p_loss;
    static u64 *p_key;
    static int *p_idx,*p_hist;
    static bf16 *pA0,*pA1,*pA2,*pB0,*pB1,*pB2,*px0,*px1,*px2,*pw0,*pw1,*pw2;
    if (!p_t2) {
        cudaGetSymbolAddress((void**)&p_t2,  g_t2);
        cudaGetSymbolAddress((void**)&p_z,   g_z);
        cudaGetSymbolAddress((void**)&p_key, g_key);
        cudaGetSymbolAddress((void**)&p_zn,  g_zn);
        cudaGetSymbolAddress((void**)&p_cn,  g_cn);
        cudaGetSymbolAddress((void**)&p_cbT, g_cbT);
        cudaGetSymbolAddress((void**)&p_loss,g_loss);
        cudaGetSymbolAddress((void**)&p_idx, g_idx);
        cudaGetSymbolAddress((void**)&p_hist,g_hist);
        cudaGetSymbolAddress((void**)&pA0, g_bA0);
        cudaGetSymbolAddress((void**)&pA1, g_bA1);
        cudaGetSymbolAddress((void**)&pA2, g_bA2);
        cudaGetSymbolAddress((void**)&pB0, g_bB0);
        cudaGetSymbolAddress((void**)&pB1, g_bB1);
        cudaGetSymbolAddress((void**)&pB2, g_bB2);
        cudaGetSymbolAddress((void**)&px0, g_xs0);
        cudaGetSymbolAddress((void**)&px1, g_xs1);
        cudaGetSymbolAddress((void**)&px2, g_xs2);
        cudaGetSymbolAddress((void**)&pw0, g_wt0);
        cudaGetSymbolAddress((void**)&pw1, g_wt1);
        cudaGetSymbolAddress((void**)&pw2, g_wt2);
        cudaFuncSetAttribute(emgemm_k<1,2>, cudaFuncAttributeMaxDynamicSharedMemorySize, 73728);
        cudaFuncSetAttribute(emgemm_k<0,0>, cudaFuncAttributeMaxDynamicSharedMemorySize, 73728);
        cudaFuncSetAttribute(mgemm_k<128,1,2>, cudaFuncAttributeMaxDynamicSharedMemorySize, 98304);
        cudaFuncSetAttribute(mgemm_k< 64,0,1>, cudaFuncAttributeMaxDynamicSharedMemorySize, 73728);
    }
    const int SM128 = 98304, SM64 = 73728;

    prep_k<<<1,256>>>(cb, p_cn, p_cbT);
    initkey_k<<<BG/256,256>>>(p_key, p_loss, p_hist);

    tsplit_k<<<(64*1024+255)/256,256>>>(enc_w1, 64, 1024, pw0+OFF_W1, pw1+OFF_W1, pw2+OFF_W1);
    tsplit_k<<<(1024*1024+255)/256,256>>>(enc_w2, 1024, 1024, pw0+OFF_W2, pw1+OFF_W2, pw2+OFF_W2);
    tsplit_k<<<(1024*1024+255)/256,256>>>(enc_w3, 1024, 1024, pw0+OFF_W3, pw1+OFF_W3, pw2+OFF_W3);
    tsplit_k<<<(128*128+255)/256,256>>>(enc_w4, 128, 128, pw0+OFF_W4, pw1+OFF_W4, pw2+OFF_W4);
    tsplit_k<<<(1024*1024+255)/256,256>>>(dec_w1, 1024, 1024, pw0+OFF_D1, pw1+OFF_D1, pw2+OFF_D1);
    tsplit_k<<<(1024*1024+255)/256,256>>>(dec_w2, 1024, 1024, pw0+OFF_D2, pw1+OFF_D2, pw2+OFF_D2);
    tsplit_k<<<(1024*64+255)/256,256>>>(dec_w3, 1024, 64, pw0+OFF_D3, pw1+OFF_D3, pw2+OFF_D3);
    xsplit_k<<<(B_SZ*STATE_NN+255)/256,256>>>(x, B_SZ*STATE_NN, px0, px1, px2);

    // ---- encoder (HMMA 6-product split-acc: byte-identical to R14 pass) ----
    emgemm_k<1,2><<<dim3(16, B_SZ/128), 256, SM64>>>(px0,px1,px2,
        pw0+OFF_W1,pw1+OFF_W1,pw2+OFF_W1, enc_b1, nullptr, pA0,pA1,pA2, HDIM, 64);
    emgemm_k<0,0><<<dim3(16, B_SZ/128), 256, SM64>>>(pA0,pA1,pA2,
        pw0+OFF_W2,pw1+OFF_W2,pw2+OFF_W2, enc_b2, p_t2, nullptr,nullptr,nullptr, HDIM, HDIM);
    ln_relu_k<<<B_SZ,256>>>(p_t2, ln_g, ln_b, pB0, pB1, pB2);
    emgemm_k<1,2><<<dim3(16, B_SZ/128), 256, SM64>>>(pB0,pB1,pB2,
        pw0+OFF_W3,pw1+OFF_W3,pw2+OFF_W3, enc_b3, nullptr, pA0,pA1,pA2, HDIM, HDIM);
    emgemm_k<0,0><<<dim3(2, BG/128), 256, SM64>>>(pA0,pA1,pA2,
        pw0+OFF_W4,pw1+OFF_W4,pw2+OFF_W4, enc_b4, p_z, nullptr,nullptr,nullptr, DDIM, DDIM);

    // ---- VQ: plain-FMA dot + reference grid + fused argmin ----
    znorm_k<<<BG/8,256>>>(p_z, p_zn);
    gemm_vqf_k<<<dim3(KCODES/128, BG/128), 256>>>(p_z, p_cbT, p_cn, p_zn, p_key, BG, KCODES, DDIM);
    idx_k<<<BG/256,256>>>(p_key, p_idx, out + IDX_OFF);
    gather_k<<<B_SZ,256>>>(p_z, cb, p_idx, pB0, pB1, pB2, p_loss, p_hist);
    finalize_k<<<1,256>>>(p_hist, p_loss, out);

    // ---- decoder (HMMA 3-product: byte-identical to R13/R14 pass) ----
    mgemm_k<128,1,2><<<dim3(8, B_SZ/128), 256, SM128>>>(pB0,pB1,pB2,
        pw0+OFF_D1,pw1+OFF_D1,pw2+OFF_D1, dec_b1, nullptr, pA0,pA1,pA2, HDIM, HDIM);
    mgemm_k<128,1,2><<<dim3(8, B_SZ/128), 256, SM128>>>(pA0,pA1,pA2,
        pw0+OFF_D2,pw1+OFF_D2,pw2+OFF_D2, dec_b2, nullptr, pB0,pB1,pB2, HDIM, HDIM);
    mgemm_k<64,0,1><<<dim3(1, B_SZ/128), 256, SM64>>>(pB0,pB1,pB2,
        pw0+OFF_D3,pw1+OFF_D3,pw2+OFF_D3, dec_b3, out + DEC_OFF, nullptr,nullptr,nullptr, STATE_NN, HDIM);
}

// round 16
// speedup vs baseline: 1.7754x; 1.0065x over previous
#include <cuda_runtime.h>
#include <cuda_bf16.h>
#include <cstdint>
#include <cmath>

#define B_SZ    32768
#define STATE_NN 64
#define HDIM    1024
#define KCODES  256
#define DDIM    128
#define GG      8
#define BG      (B_SZ*GG)
#define GD      (GG*DDIM)
#define DEC_OFF  1
#define PERP_OFF (1 + B_SZ*STATE_NN)
#define IDX_OFF  (2 + B_SZ*STATE_NN)

typedef unsigned long long u64;
typedef __nv_bfloat16 bf16;

// ---------------- device scratch ----------------
__device__ float g_t2[(size_t)B_SZ*HDIM];
__device__ float g_z [(size_t)B_SZ*GD];
__device__ u64   g_key[BG];
__device__ float g_zn[BG];
__device__ int   g_idx[BG];
__device__ int   g_hist[KCODES];
__device__ float g_cn[KCODES];
__device__ float g_cbT[DDIM*KCODES];
__device__ float g_loss[1];

__device__ __align__(16) bf16 g_bA0[(size_t)B_SZ*HDIM];
__device__ __align__(16) bf16 g_bA1[(size_t)B_SZ*HDIM];
__device__ __align__(16) bf16 g_bA2[(size_t)B_SZ*HDIM];
__device__ __align__(16) bf16 g_bB0[(size_t)B_SZ*HDIM];
__device__ __align__(16) bf16 g_bB1[(size_t)B_SZ*HDIM];
__device__ __align__(16) bf16 g_bB2[(size_t)B_SZ*HDIM];
__device__ __align__(16) bf16 g_xs0[(size_t)B_SZ*STATE_NN];
__device__ __align__(16) bf16 g_xs1[(size_t)B_SZ*STATE_NN];
__device__ __align__(16) bf16 g_xs2[(size_t)B_SZ*STATE_NN];

#define OFF_W1 0
#define OFF_W2 65536
#define OFF_W3 1114112
#define OFF_W4 2162688
#define OFF_D1 2179072
#define OFF_D2 3227648
#define OFF_D3 4276224
#define WT_TOT 4341760
__device__ __align__(16) bf16 g_wt0[WT_TOT];
__device__ __align__(16) bf16 g_wt1[WT_TOT];
__device__ __align__(16) bf16 g_wt2[WT_TOT];

// ---------------- helpers ----------------
__device__ __forceinline__ u64 pack2(float lo, float hi){
    u64 r; asm("mov.b64 %0, {%1,%2};" : "=l"(r) : "f"(lo), "f"(hi)); return r; }
__device__ __forceinline__ void unpack2(u64 v, float &lo, float &hi){
    asm("mov.b64 {%0,%1}, %2;" : "=f"(lo), "=f"(hi) : "l"(v)); }
__device__ __forceinline__ u64 ffma2(u64 a, u64 b, u64 c){
    u64 d; asm("fma.rn.f32x2 %0, %1, %2, %3;" : "=l"(d) : "l"(a), "l"(b), "l"(c)); return d; }
__device__ __forceinline__ uint32_t smem_u32(const void* p){
    uint32_t a; asm("{ .reg .u64 t; cvta.to.shared.u64 t, %1; cvt.u32.u64 %0, t; }" : "=r"(a) : "l"(p));
    return a; }
__device__ __forceinline__ void split3(float v, bf16 &h, bf16 &m, bf16 &l){
    h = __float2bfloat16(v);
    float r1 = v - __bfloat162float(h);
    m = __float2bfloat16(r1);
    l = __float2bfloat16(r1 - __bfloat162float(m)); }
__device__ __forceinline__ void wsplit2(bf16* H, bf16* M, bf16* L, size_t go, float a, float b){
    bf16 h0,m0,l0,h1,m1,l1; split3(a,h0,m0,l0); split3(b,h1,m1,l1);
    __nv_bfloat162 p;
    p.x=h0; p.y=h1; *(__nv_bfloat162*)(H+go)=p;
    p.x=m0; p.y=m1; *(__nv_bfloat162*)(M+go)=p;
    p.x=l0; p.y=l1; *(__nv_bfloat162*)(L+go)=p; }
__device__ __forceinline__ uint32_t ford(float v){
    uint32_t b = __float_as_uint(v);
    return (b & 0x80000000u) ? ~b : (b | 0x80000000u); }

#define CP16(dst, src) asm volatile("cp.async.cg.shared.global [%0], [%1], 16;" :: "r"(dst), "l"(src) : "memory")
#define CPCOMMIT       asm volatile("cp.async.commit_group;" ::: "memory")
#define CPWAIT0        asm volatile("cp.async.wait_group 0;" ::: "memory")
__device__ __forceinline__ void ldsm4(uint32_t &r0,uint32_t &r1,uint32_t &r2,uint32_t &r3,uint32_t a){
    asm volatile("ldmatrix.sync.aligned.m8n8.x4.shared.b16 {%0,%1,%2,%3}, [%4];"
        : "=r"(r0),"=r"(r1),"=r"(r2),"=r"(r3) : "r"(a)); }
__device__ __forceinline__ void mma16816(float* c, const uint32_t* a, uint32_t b0, uint32_t b1){
    asm volatile("mma.sync.aligned.m16n8k16.row.col.f32.bf16.bf16.f32 "
        "{%0,%1,%2,%3},{%4,%5,%6,%7},{%8,%9},{%0,%1,%2,%3};"
        : "+f"(c[0]),"+f"(c[1]),"+f"(c[2]),"+f"(c[3])
        : "r"(a[0]),"r"(a[1]),"r"(a[2]),"r"(a[3]), "r"(b0),"r"(b1)); }
#define SWO(r,c) ((r)*64 + (((c) ^ (((r)>>1)&3))<<4))

// =====================================================================
// ENCODER HMMA GEMM: 6-product split-acc, straight-line (no acc pointers).
// Product order identical to R14/R15 pass: B0:{A0->acc0, A1->acc1, A2->acc1},
// B1:{A0->acc1, A1->acc1}, B2:{A0->acc1}.
// =====================================================================
template<int ACT, int OUTM>
__global__ void __launch_bounds__(256,1)
emgemm_k(const bf16* __restrict__ A0,const bf16* __restrict__ A1,const bf16* __restrict__ A2,
         const bf16* __restrict__ Bb0,const bf16* __restrict__ Bb1,const bf16* __restrict__ Bb2,
         const float* __restrict__ bias, float* __restrict__ C,
         bf16* __restrict__ Ch, bf16* __restrict__ Cm, bf16* __restrict__ Cl,
         int Ncols, int K)
{
    constexpr int BN_  = 64;
    constexpr int MT   = 2;
    constexpr int NTT  = 4;
    constexpr int ASZ  = 128*64;
    constexpr int BSZ  = BN_*64;
    constexpr int STAGE= 3*ASZ + 3*BSZ;

    extern __shared__ char smem[];
    const uint32_t sb = smem_u32(smem);
    const int tid = threadIdx.x, wid = tid>>5, lane = tid&31;
    const int wm = wid>>1, wn = wid&1;
    const int wmB = wm*32, wnB = wn*32;
    const int bCol0 = blockIdx.x*BN_;
    const int aRow0 = blockIdx.y*128;

    const bf16* Ap[3]={A0,A1,A2};
    const bf16* Bp[3]={Bb0,Bb1,Bb2};

    float a0_00[4],a0_01[4],a0_02[4],a0_03[4],a0_10[4],a0_11[4],a0_12[4],a0_13[4];
    float a1_00[4],a1_01[4],a1_02[4],a1_03[4],a1_10[4],a1_11[4],a1_12[4],a1_13[4];
#pragma unroll
    for (int q=0;q<4;q++){
        a0_00[q]=a0_01[q]=a0_02[q]=a0_03[q]=0.f;
        a0_10[q]=a0_11[q]=a0_12[q]=a0_13[q]=0.f;
        a1_00[q]=a1_01[q]=a1_02[q]=a1_03[q]=0.f;
        a1_10[q]=a1_11[q]=a1_12[q]=a1_13[q]=0.f;
    }

    auto issue = [&](int kb, int st){
        uint32_t base = sb + st*STAGE;
#pragma unroll
        for (int i0=0; i0<3*512; i0+=256){
            int i = i0 + tid;
            int l = i>>9, rem = i&511, r = rem>>2, c = rem&3;
            CP16(base + l*ASZ + SWO(r,c),
                 Ap[l] + (size_t)(aRow0+r)*K + kb + c*8);
        }
#pragma unroll
        for (int i0=0; i0<3*BN_*4; i0+=256){
            int i = i0 + tid;
            int l = i/(BN_*4), rem = i%(BN_*4), r = rem>>2, c = rem&3;
            CP16(base + 3*ASZ + l*BSZ + SWO(r,c),
                 Bp[l] + (size_t)(bCol0+r)*K + kb + c*8);
        }
        CPCOMMIT;
    };

// issue one product (A-frag level al) against current B frags into named accs
#define EMM(ACCPFX, AL) \
    mma16816(ACCPFX##_00, af[AL][0], bfr[0][0], bfr[0][1]); \
    mma16816(ACCPFX##_01, af[AL][0], bfr[0][2], bfr[0][3]); \
    mma16816(ACCPFX##_02, af[AL][0], bfr[1][0], bfr[1][1]); \
    mma16816(ACCPFX##_03, af[AL][0], bfr[1][2], bfr[1][3]); \
    mma16816(ACCPFX##_10, af[AL][1], bfr[0][0], bfr[0][1]); \
    mma16816(ACCPFX##_11, af[AL][1], bfr[0][2], bfr[0][3]); \
    mma16816(ACCPFX##_12, af[AL][1], bfr[1][0], bfr[1][1]); \
    mma16816(ACCPFX##_13, af[AL][1], bfr[1][2], bfr[1][3]);

    const int T = K/32;
    issue(0,0);
    for (int t=0; t<T; ++t){
        CPWAIT0;
        __syncthreads();
        if (t+1 < T) issue((t+1)*32, (t+1)&1);
        const uint32_t base = sb + (t&1)*STAGE;
#pragma unroll
        for (int ks=0; ks<2; ++ks){
            uint32_t af[3][MT][4];
#pragma unroll
            for (int l=0;l<3;l++)
#pragma unroll
                for (int mt=0;mt<MT;mt++){
                    int r = wmB + mt*16 + (lane&15);
                    int c = ks*2 + (lane>>4);
                    ldsm4(af[l][mt][0],af[l][mt][1],af[l][mt][2],af[l][mt][3],
                          base + l*ASZ + SWO(r,c));
                }
            uint32_t bfr[NTT/2][4];
            // ---- B level 0 ----
#pragma unroll
            for (int np=0; np<NTT/2; np++){
                int r = wnB + np*16 + ((lane>>4)<<3) + (lane&7);
                int c = ks*2 + ((lane>>3)&1);
                ldsm4(bfr[np][0],bfr[np][1],bfr[np][2],bfr[np][3],
                      base + 3*ASZ + 0*BSZ + SWO(r,c));
            }
            EMM(a0, 0)          // hh -> acc0
            EMM(a1, 1)          // mh -> acc1
            EMM(a1, 2)          // lh -> acc1
            // ---- B level 1 ----
#pragma unroll
            for (int np=0; np<NTT/2; np++){
                int r = wnB + np*16 + ((lane>>4)<<3) + (lane&7);
                int c = ks*2 + ((lane>>3)&1);
                ldsm4(bfr[np][0],bfr[np][1],bfr[np][2],bfr[np][3],
                      base + 3*ASZ + 1*BSZ + SWO(r,c));
            }
            EMM(a1, 0)          // hm -> acc1
            EMM(a1, 1)          // mm -> acc1
            // ---- B level 2 ----
#pragma unroll
            for (int np=0; np<NTT/2; np++){
                int r = wnB + np*16 + ((lane>>4)<<3) + (lane&7);
                int c = ks*2 + ((lane>>3)&1);
                ldsm4(bfr[np][0],bfr[np][1],bfr[np][2],bfr[np][3],
                      base + 3*ASZ + 2*BSZ + SWO(r,c));
            }
            EMM(a1, 0)          // hl -> acc1
        }
    }
#undef EMM

    // epilogue (same math as R14/R15: (acc0+acc1)+bias)
    float* a0p[2][4] = {{a0_00,a0_01,a0_02,a0_03},{a0_10,a0_11,a0_12,a0_13}};
    float* a1p[2][4] = {{a1_00,a1_01,a1_02,a1_03},{a1_10,a1_11,a1_12,a1_13}};
#pragma unroll
    for (int mt=0;mt<MT;mt++){
        int rbase = aRow0 + wmB + mt*16 + (lane>>2);
#pragma unroll
        for (int half=0; half<2; ++half){
            size_t r = (size_t)rbase + half*8;
#pragma unroll
            for (int nt=0;nt<NTT;nt++){
                int cc = bCol0 + wnB + nt*8 + (lane&3)*2;
                float v0 = (a0p[mt][nt][half*2+0] + a1p[mt][nt][half*2+0]) + bias[cc];
                float v1 = (a0p[mt][nt][half*2+1] + a1p[mt][nt][half*2+1]) + bias[cc+1];
                if (ACT==1){ v0 = fmaxf(v0,0.f); v1 = fmaxf(v1,0.f); }
                size_t go = r*(size_t)Ncols + cc;
                if (OUTM==0){ float2 o; o.x=v0; o.y=v1; *(float2*)(C+go)=o; }
                else wsplit2(Ch,Cm,Cl, go, v0, v1);
            }
        }
    }
}

// =====================================================================
// DECODER HMMA GEMM (byte-identical to R13/R14/R15 pass).
// =====================================================================
template<int BN_, int ACT, int OUTM>
__global__ void __launch_bounds__(256,1)
mgemm_k(const bf16* __restrict__ A0,const bf16* __restrict__ A1,const bf16* __restrict__ A2,
        const bf16* __restrict__ Bb0,const bf16* __restrict__ Bb1,const bf16* __restrict__ Bb2,
        const float* __restrict__ bias, float* __restrict__ C,
        bf16* __restrict__ Ch, bf16* __restrict__ Cm, bf16* __restrict__ Cl,
        int Ncols, int K)
{
    constexpr int ALEV = 2;
    constexpr int WM   = (BN_==128)?2:4;
    constexpr int WN   = 8/WM;
    constexpr int MT   = 128/(WM*16);
    constexpr int NTT  = BN_/(WN*8);
    constexpr int ASZ  = 128*64;
    constexpr int BSZ  = BN_*64;
    constexpr int STAGE= 3*ASZ + 3*BSZ;

    extern __shared__ char smem[];
    const uint32_t sb = smem_u32(smem);
    const int tid = threadIdx.x, wid = tid>>5, lane = tid&31;
    const int wm = (WM==2)?(wid>>2):(wid>>1);
    const int wn = (WM==2)?(wid&3):(wid&1);
    const int wmB = wm*MT*16, wnB = wn*NTT*8;
    const int bCol0 = blockIdx.x*BN_;
    const int aRow0 = blockIdx.y*128;

    const bf16* Ap[3]={A0,A1,A2};
    const bf16* Bp[3]={Bb0,Bb1,Bb2};

    float acc[MT][NTT][4];
#pragma unroll
    for (int i=0;i<MT;i++)
#pragma unroll
        for (int j=0;j<NTT;j++)
#pragma unroll
            for (int q=0;q<4;q++) acc[i][j][q]=0.f;

    auto issue = [&](int kb, int st){
        uint32_t base = sb + st*STAGE;
#pragma unroll
        for (int i0=0; i0<ALEV*512; i0+=256){
            int i = i0 + tid;
            int l = i>>9, rem = i&511, r = rem>>2, c = rem&3;
            CP16(base + l*ASZ + SWO(r,c),
                 Ap[l] + (size_t)(aRow0+r)*K + kb + c*8);
        }
#pragma unroll
        for (int i0=0; i0<ALEV*BN_*4; i0+=256){
            int i = i0 + tid;
            int l = i/(BN_*4), rem = i%(BN_*4), r = rem>>2, c = rem&3;
            CP16(base + 3*ASZ + l*BSZ + SWO(r,c),
                 Bp[l] + (size_t)(bCol0+r)*K + kb + c*8);
        }
        CPCOMMIT;
    };

    const int T = K/32;
    issue(0,0);
    for (int t=0; t<T; ++t){
        CPWAIT0;
        __syncthreads();
        if (t+1 < T) issue((t+1)*32, (t+1)&1);
        const uint32_t base = sb + (t&1)*STAGE;
#pragma unroll
        for (int ks=0; ks<2; ++ks){
            uint32_t af[ALEV][MT][4];
#pragma unroll
            for (int l=0;l<ALEV;l++)
#pragma unroll
                for (int mt=0;mt<MT;mt++){
                    int r = wmB + mt*16 + (lane&15);
                    int c = ks*2 + (lane>>4);
                    ldsm4(af[l][mt][0],af[l][mt][1],af[l][mt][2],af[l][mt][3],
                          base + l*ASZ + SWO(r,c));
                }
#pragma unroll
            for (int bl=0; bl<ALEV; ++bl){
                uint32_t bfr[NTT/2][4];
#pragma unroll
                for (int np=0; np<NTT/2; np++){
                    int r = wnB + np*16 + ((lane>>4)<<3) + (lane&7);
                    int c = ks*2 + ((lane>>3)&1);
                    ldsm4(bfr[np][0],bfr[np][1],bfr[np][2],bfr[np][3],
                          base + 3*ASZ + bl*BSZ + SWO(r,c));
                }
                const int na = (bl==0?2:1);
#pragma unroll
                for (int al=0; al<ALEV; ++al){
                    if (al < na){
#pragma unroll
                        for (int mt=0;mt<MT;mt++)
#pragma unroll
                            for (int nt=0;nt<NTT;nt++)
                                mma16816(acc[mt][nt], af[al][mt],
                                         bfr[nt>>1][(nt&1)*2], bfr[nt>>1][(nt&1)*2+1]);
                    }
                }
            }
        }
    }

#pragma unroll
    for (int mt=0;mt<MT;mt++){
        int rbase = aRow0 + wmB + mt*16 + (lane>>2);
#pragma unroll
        for (int half=0; half<2; ++half){
            size_t r = (size_t)rbase + half*8;
#pragma unroll
            for (int nt=0;nt<NTT;nt++){
                int cc = bCol0 + wnB + nt*8 + (lane&3)*2;
                float v0 = acc[mt][nt][half*2+0] + bias[cc];
                float v1 = acc[mt][nt][half*2+1] + bias[cc+1];
                if (ACT==1){ v0 = fmaxf(v0,0.f); v1 = fmaxf(v1,0.f); }
                size_t go = r*(size_t)Ncols + cc;
                if (OUTM==1){ C[go]=v0; C[go+1]=v1; }
                else wsplit2(Ch,Cm,Cl, go, v0, v1);
            }
        }
    }
}

// =====================================================================
// VQ GEMM + fused argmin (R15 semantics; BK 16->32, k-order unchanged).
// =====================================================================
__global__ void __launch_bounds__(256,2)
gemm_vqf_k(const float* __restrict__ A, const float* __restrict__ Bm,
           const float* __restrict__ cn, const float* __restrict__ zn,
           u64* __restrict__ gkey, int M, int N, int K)
{
    constexpr int BM=128, BN=128, BK=32, TM=8, TN=8;
    constexpr int MG = TM/4;
    constexpr int NG = TN/4;
    constexpr int ASTEP = (256/BM)*4;
    constexpr int ANUM  = BK/ASTEP;
    constexpr int BNUM  = (BK*BN)/(256*4);

    __shared__ float As[2][BK][BM];
    __shared__ float Bs[2][BK][BN];
    __shared__ u64 rowkey[BM];

    const int tid  = threadIdx.x;
    const int tcol = tid % (BN/TN);
    const int trow = tid / (BN/TN);
    const int aRow0 = blockIdx.y * BM;
    const int bCol0 = blockIdx.x * BN;
    const int lr = tid % BM;
    const int ls = tid / BM;

    u64 acc[TM][TN/2];
#pragma unroll
    for (int i=0;i<TM;i++)
#pragma unroll
        for (int j=0;j<TN/2;j++) acc[i][j] = 0ULL;

#pragma unroll
    for (int i=0;i<ANUM;i++) {
        int c0 = ls*4 + i*ASTEP;
        float4 v = *(const float4*)(A + (size_t)(aRow0+lr)*K + c0);
        As[0][c0+0][lr]=v.x; As[0][c0+1][lr]=v.y;
        As[0][c0+2][lr]=v.z; As[0][c0+3][lr]=v.w;
    }
#pragma unroll
    for (int it=0; it<BNUM; ++it) {
        int idx4 = (tid + it*256)*4;
        int r = idx4 / BN, c = idx4 % BN;
        *(float4*)&Bs[0][r][c] = *(const float4*)(Bm + (size_t)r*N + bCol0 + c);
    }
    if (tid < BM) rowkey[tid] = ~0ULL;
    __syncthreads();

    const int NIT = K/BK;
    for (int itk=0; itk<NIT; ++itk) {
        const int cur = itk & 1, nxt = cur ^ 1;
        const int k1 = (itk+1)*BK;
        float4 avp[ANUM], bvp[BNUM];
        if (itk+1 < NIT) {
#pragma unroll
            for (int i=0;i<ANUM;i++) {
                int c0 = ls*4 + i*ASTEP;
                avp[i] = *(const float4*)(A + (size_t)(aRow0+lr)*K + k1 + c0);
            }
#pragma unroll
            for (int it=0; it<BNUM; ++it) {
                int idx4 = (tid + it*256)*4;
                int r = idx4 / BN, c = idx4 % BN;
                bvp[it] = *(const float4*)(Bm + (size_t)(k1+r)*N + bCol0 + c);
            }
        }
#pragma unroll
        for (int kk=0; kk<BK; kk++) {
            u64 ar2[TM], br2[TN/2];
#pragma unroll
            for (int h=0; h<MG; h++) {
                float4 av = *(const float4*)&As[cur][kk][h*(BM/2) + trow*4];
                ar2[h*4+0] = pack2(av.x, av.x);
                ar2[h*4+1] = pack2(av.y, av.y);
                ar2[h*4+2] = pack2(av.z, av.z);
                ar2[h*4+3] = pack2(av.w, av.w);
            }
#pragma unroll
            for (int g=0; g<NG; g++) {
                ulonglong2 bv = *(const ulonglong2*)&Bs[cur][kk][g*(BN/2) + tcol*4];
                br2[g*2+0] = bv.x;
                br2[g*2+1] = bv.y;
            }
#pragma unroll
            for (int i=0;i<TM;i++)
#pragma unroll
                for (int j=0;j<TN/2;j++)
                    acc[i][j] = ffma2(ar2[i], br2[j], acc[i][j]);
        }
        if (itk+1 < NIT) {
#pragma unroll
            for (int i=0;i<ANUM;i++) {
                int c0 = ls*4 + i*ASTEP;
                As[nxt][c0+0][lr]=avp[i].x; As[nxt][c0+1][lr]=avp[i].y;
                As[nxt][c0+2][lr]=avp[i].z; As[nxt][c0+3][lr]=avp[i].w;
            }
#pragma unroll
            for (int it=0; it<BNUM; ++it) {
                int idx4 = (tid + it*256)*4;
                int r = idx4 / BN, c = idx4 % BN;
                *(float4*)&Bs[nxt][r][c] = bvp[it];
            }
        }
        __syncthreads();
    }

#pragma unroll
    for (int h=0; h<MG; h++) {
#pragma unroll
        for (int i=0;i<4;i++) {
            int rl = h*(BM/2) + trow*4 + i;
            size_t r = (size_t)aRow0 + rl;
            float zr = zn[r];
            u64 best = ~0ULL;
#pragma unroll
            for (int g=0; g<NG; g++) {
                int c0 = bCol0 + g*(BN/2) + tcol*4;
#pragma unroll
                for (int jp=0; jp<2; ++jp) {
                    float d0, d1;
                    unpack2(acc[h*4+i][g*2+jp], d0, d1);
                    int c = c0 + 2*jp;
                    float t0 = __fadd_rn(zr, cn[c]);
                    float t1 = __fadd_rn(zr, cn[c+1]);
                    float s0 = __fadd_rn(t0, __fmul_rn(-2.f, d0));
                    float s1 = __fadd_rn(t1, __fmul_rn(-2.f, d1));
                    u64 k0 = ((u64)ford(s0) << 32) | (u64)(uint32_t)c;
                    u64 k1 = ((u64)ford(s1) << 32) | (u64)(uint32_t)(c+1);
                    best = min(best, min(k0, k1));
                }
            }
            atomicMin(&rowkey[rl], best);
        }
    }
    __syncthreads();
    if (tid < BM) atomicMin(&gkey[aRow0 + tid], rowkey[tid]);
}

// ---------------- key init + idx extraction ----------------
__global__ void initkey_k(u64* __restrict__ gkey, float* loss, int* hist)
{
    int e = blockIdx.x*256 + threadIdx.x;
    if (e < BG) gkey[e] = ~0ULL;
    if (blockIdx.x == 0) {
        if (threadIdx.x == 0) *loss = 0.f;
        if (threadIdx.x < KCODES) hist[threadIdx.x] = 0;
    }
}
__global__ void idx_k(const u64* __restrict__ gkey, int* __restrict__ idx,
                      float* __restrict__ idx_f)
{
    int e = blockIdx.x*256 + threadIdx.x;
    if (e >= BG) return;
    int k = (int)(gkey[e] & 0xFFFFFFFFu);
    idx[e] = k;
    idx_f[e] = (float)k;
}

// ---------------- weight transpose+split / x split ----------------
__global__ void tsplit_k(const float* __restrict__ W, int Kd, int Nd,
                         bf16* __restrict__ dh, bf16* __restrict__ dm, bf16* __restrict__ dl)
{
    int e = blockIdx.x*256 + threadIdx.x;
    if (e >= Kd*Nd) return;
    int n = e / Kd, k = e % Kd;
    bf16 h,m,l; split3(W[(size_t)k*Nd + n], h,m,l);
    dh[e]=h; dm[e]=m; dl[e]=l;
}
__global__ void xsplit_k(const float* __restrict__ X, int n,
                         bf16* __restrict__ dh, bf16* __restrict__ dm, bf16* __restrict__ dl)
{
    int e = blockIdx.x*256 + threadIdx.x;
    if (e >= n) return;
    bf16 h,m,l; split3(X[e], h,m,l);
    dh[e]=h; dm[e]=m; dl[e]=l;
}

// ---------------- LayerNorm + ReLU -> bf16 splits ----------------
__global__ void ln_relu_k(const float* __restrict__ X, const float* __restrict__ gam,
                          const float* __restrict__ bet,
                          bf16* __restrict__ Yh, bf16* __restrict__ Ym, bf16* __restrict__ Yl)
{
    const int row = blockIdx.x;
    const int t   = threadIdx.x;
    __shared__ float red[8];
    __shared__ float s_mu, s_rs;

    float4 v = *(const float4*)(X + (size_t)row*HDIM + t*4);
    float s = __fadd_rn(__fadd_rn(v.x,v.y), __fadd_rn(v.z,v.w));
#pragma unroll
    for (int o=16;o;o>>=1) s = __fadd_rn(s, __shfl_xor_sync(~0u, s, o));
    if ((t&31)==0) red[t>>5] = s;
    __syncthreads();
    if (t==0) {
        float a = __fadd_rn(__fadd_rn(red[0],red[1]), __fadd_rn(red[2],red[3]));
        float b = __fadd_rn(__fadd_rn(red[4],red[5]), __fadd_rn(red[6],red[7]));
        s_mu = __fadd_rn(a,b) * (1.0f/HDIM);
    }
    __syncthreads();
    const float mu = s_mu;
    float dx=__fadd_rn(v.x,-mu), dy=__fadd_rn(v.y,-mu),
          dz=__fadd_rn(v.z,-mu), dw=__fadd_rn(v.w,-mu);
    float sq = __fadd_rn(__fadd_rn(__fmul_rn(dx,dx),__fmul_rn(dy,dy)),
                         __fadd_rn(__fmul_rn(dz,dz),__fmul_rn(dw,dw)));
#pragma unroll
    for (int o=16;o;o>>=1) sq = __fadd_rn(sq, __shfl_xor_sync(~0u, sq, o));
    if ((t&31)==0) red[t>>5] = sq;
    __syncthreads();
    if (t==0) {
        float a = __fadd_rn(__fadd_rn(red[0],red[1]), __fadd_rn(red[2],red[3]));
        float b = __fadd_rn(__fadd_rn(red[4],red[5]), __fadd_rn(red[6],red[7]));
        s_rs = rsqrtf(__fadd_rn(a,b)*(1.0f/HDIM) + 1e-5f);
    }
    __syncthreads();
    const float rs = s_rs;

    float4 g4 = *(const float4*)(gam + t*4);
    float4 b4 = *(const float4*)(bet + t*4);
    float o0 = fmaxf(__fadd_rn(__fmul_rn(__fmul_rn(dx,rs),g4.x), b4.x), 0.f);
    float o1 = fmaxf(__fadd_rn(__fmul_rn(__fmul_rn(dy,rs),g4.y), b4.y), 0.f);
    float o2 = fmaxf(__fadd_rn(__fmul_rn(__fmul_rn(dz,rs),g4.z), b4.z), 0.f);
    float o3 = fmaxf(__fadd_rn(__fmul_rn(__fmul_rn(dw,rs),g4.w), b4.w), 0.f);
    size_t go = (size_t)row*HDIM + t*4;
    wsplit2(Yh,Ym,Yl, go,   o0, o1);
    wsplit2(Yh,Ym,Yl, go+2, o2, o3);
}

// ---------------- small kernels ----------------
__global__ void znorm_k(const float* __restrict__ z, float* __restrict__ zn)
{
    int row  = blockIdx.x*8 + (threadIdx.x >> 5);
    int lane = threadIdx.x & 31;
    float4 v = *(const float4*)(z + (size_t)row*DDIM + lane*4);
    float s = __fadd_rn(__fadd_rn(__fmul_rn(v.x,v.x), __fmul_rn(v.y,v.y)),
                        __fadd_rn(__fmul_rn(v.z,v.z), __fmul_rn(v.w,v.w)));
#pragma unroll
    for (int o=16;o;o>>=1) s = __fadd_rn(s, __shfl_xor_sync(~0u, s, o));
    if (lane == 0) zn[row] = s;
}
__global__ void prep_k(const float* __restrict__ cb, float* __restrict__ cn,
                       float* __restrict__ cbT)
{
    int k = threadIdx.x;
    double s = 0.0;
    for (int d0=0; d0<DDIM; d0++) {
        float v = cb[k*DDIM + d0];
        s += (double)v * (double)v;
        cbT[d0*KCODES + k] = v;
    }
    cn[k] = (float)s;
}
__global__ void gather_k(const float* __restrict__ z, const float* __restrict__ cb,
                         const int* __restrict__ idx,
                         bf16* __restrict__ Qh, bf16* __restrict__ Qm, bf16* __restrict__ Ql,
                         float* __restrict__ loss, int* __restrict__ hist)
{
    int b = blockIdx.x;
    int t = threadIdx.x;
    __shared__ int   sidx[GG];
    __shared__ float red[8];
    if (t < GG) {
        int k = idx[b*GG + t];
        sidx[t] = k;
        atomicAdd(&hist[k], 1);
    }
    __syncthreads();
    int g = (t*4) >> 7;
    int e = (t*4) & 127;
    float4 c  = *(const float4*)(cb + (size_t)sidx[g]*DDIM + e);
    float4 zz = *(const float4*)(z  + (size_t)b*GD + t*4);
    float dx=__fadd_rn(c.x,-zz.x), dy=__fadd_rn(c.y,-zz.y),
          dz=__fadd_rn(c.z,-zz.z), dw=__fadd_rn(c.w,-zz.w);
    float st0=__fadd_rn(zz.x,dx), st1=__fadd_rn(zz.y,dy),
          st2=__fadd_rn(zz.z,dz), st3=__fadd_rn(zz.w,dw);
    size_t go = (size_t)b*GD + t*4;
    wsplit2(Qh,Qm,Ql, go,   st0, st1);
    wsplit2(Qh,Qm,Ql, go+2, st2, st3);
    float s = dx*dx+dy*dy+dz*dz+dw*dw;
#pragma unroll
    for (int o=16;o;o>>=1) s += __shfl_xor_sync(~0u, s, o);
    if ((t&31)==0) red[t>>5] = s;
    __syncthreads();
    if (t==0) {
        float tot=0.f;
#pragma unroll
        for (int i=0;i<8;i++) tot += red[i];
        atomicAdd(loss, tot);
    }
}
__global__ void finalize_k(const int* __restrict__ hist, const float* __restrict__ loss,
                           float* __restrict__ out)
{
    int t = threadIdx.x;
    __shared__ float red[8];
    float e = (float)hist[t] / (float)BG;
    float s = e * logf(e + 1e-10f);
#pragma unroll
    for (int o=16;o;o>>=1) s += __shfl_xor_sync(~0u, s, o);
    if ((t&31)==0) red[t>>5] = s;
    __syncthreads();
    if (t==0) {
        float tot=0.f;
#pragma unroll
        for (int i=0;i<8;i++) tot += red[i];
        out[PERP_OFF] = expf(-tot);
        out[0] = 1.25f * loss[0] / 33554432.0f;
    }
}

// ---------------- host launcher ----------------
extern "C" void kernel_launch(void* const* d_in, const int* in_sizes, int n_in,
                              void* d_out, int out_size)
{
    const float* x      = (const float*)d_in[0];
    const float* enc_w1 = (const float*)d_in[1];
    const float* enc_b1 = (const float*)d_in[2];
    const float* enc_w2 = (const float*)d_in[3];
    const float* enc_b2 = (const float*)d_in[4];
    const float* ln_g   = (const float*)d_in[5];
    const float* ln_b   = (const float*)d_in[6];
    const float* enc_w3 = (const float*)d_in[7];
    const float* enc_b3 = (const float*)d_in[8];
    const float* enc_w4 = (const float*)d_in[9];
    const float* enc_b4 = (const float*)d_in[10];
    const float* cb     = (const float*)d_in[11];
    const float* dec_w1 = (const float*)d_in[12];
    const float* dec_b1 = (const float*)d_in[13];
    const float* dec_w2 = (const float*)d_in[14];
    const float* dec_b2 = (const float*)d_in[15];
    const float* dec_w3 = (const float*)d_in[16];
    const float* dec_b3 = (const float*)d_in[17];
    float* out = (float*)d_out;

    static float *p_t2=nullptr,*p_z,*p_zn,*p_cn,*p_cbT,*p_loss;
    static u64 *p_key;
    static int *p_idx,*p_hist;
    static bf16 *pA0,*pA1,*pA2,*pB0,*pB1,*pB2,*px0,*px1,*px2,*pw0,*pw1,*pw2;
    if (!p_t2) {
        cudaGetSymbolAddress((void**)&p_t2,  g_t2);
        cudaGetSymbolAddress((void**)&p_z,   g_z);
        cudaGetSymbolAddress((void**)&p_key, g_key);
        cudaGetSymbolAddress((void**)&p_zn,  g_zn);
        cudaGetSymbolAddress((void**)&p_cn,  g_cn);
        cudaGetSymbolAddress((void**)&p_cbT, g_cbT);
        cudaGetSymbolAddress((void**)&p_loss,g_loss);
        cudaGetSymbolAddress((void**)&p_idx, g_idx);
        cudaGetSymbolAddress((void**)&p_hist,g_hist);
        cudaGetSymbolAddress((void**)&pA0, g_bA0);
        cudaGetSymbolAddress((void**)&pA1, g_bA1);
        cudaGetSymbolAddress((void**)&pA2, g_bA2);
        cudaGetSymbolAddress((void**)&pB0, g_bB0);
        cudaGetSymbolAddress((void**)&pB1, g_bB1);
        cudaGetSymbolAddress((void**)&pB2, g_bB2);
        cudaGetSymbolAddress((void**)&px0, g_xs0);
        cudaGetSymbolAddress((void**)&px1, g_xs1);
        cudaGetSymbolAddress((void**)&px2, g_xs2);
        cudaGetSymbolAddress((void**)&pw0, g_wt0);
        cudaGetSymbolAddress((void**)&pw1, g_wt1);
        cudaGetSymbolAddress((void**)&pw2, g_wt2);
        cudaFuncSetAttribute(emgemm_k<1,2>, cudaFuncAttributeMaxDynamicSharedMemorySize, 73728);
        cudaFuncSetAttribute(emgemm_k<0,0>, cudaFuncAttributeMaxDynamicSharedMemorySize, 73728);
        cudaFuncSetAttribute(mgemm_k<128,1,2>, cudaFuncAttributeMaxDynamicSharedMemorySize, 98304);
        cudaFuncSetAttribute(mgemm_k< 64,0,1>, cudaFuncAttributeMaxDynamicSharedMemorySize, 73728);
    }
    const int SM128 = 98304, SM64 = 73728;

    prep_k<<<1,256>>>(cb, p_cn, p_cbT);
    initkey_k<<<BG/256,256>>>(p_key, p_loss, p_hist);

    tsplit_k<<<(64*1024+255)/256,256>>>(enc_w1, 64, 1024, pw0+OFF_W1, pw1+OFF_W1, pw2+OFF_W1);
    tsplit_k<<<(1024*1024+255)/256,256>>>(enc_w2, 1024, 1024, pw0+OFF_W2, pw1+OFF_W2, pw2+OFF_W2);
    tsplit_k<<<(1024*1024+255)/256,256>>>(enc_w3, 1024, 1024, pw0+OFF_W3, pw1+OFF_W3, pw2+OFF_W3);
    tsplit_k<<<(128*128+255)/256,256>>>(enc_w4, 128, 128, pw0+OFF_W4, pw1+OFF_W4, pw2+OFF_W4);
    tsplit_k<<<(1024*1024+255)/256,256>>>(dec_w1, 1024, 1024, pw0+OFF_D1, pw1+OFF_D1, pw2+OFF_D1);
    tsplit_k<<<(1024*1024+255)/256,256>>>(dec_w2, 1024, 1024, pw0+OFF_D2, pw1+OFF_D2, pw2+OFF_D2);
    tsplit_k<<<(1024*64+255)/256,256>>>(dec_w3, 1024, 64, pw0+OFF_D3, pw1+OFF_D3, pw2+OFF_D3);
    xsplit_k<<<(B_SZ*STATE_NN+255)/256,256>>>(x, B_SZ*STATE_NN, px0, px1, px2);

    // ---- encoder (HMMA 6-product split-acc, de-pointered) ----
    emgemm_k<1,2><<<dim3(16, B_SZ/128), 256, SM64>>>(px0,px1,px2,
        pw0+OFF_W1,pw1+OFF_W1,pw2+OFF_W1, enc_b1, nullptr, pA0,pA1,pA2, HDIM, 64);
    emgemm_k<0,0><<<dim3(16, B_SZ/128), 256, SM64>>>(pA0,pA1,pA2,
        pw0+OFF_W2,pw1+OFF_W2,pw2+OFF_W2, enc_b2, p_t2, nullptr,nullptr,nullptr, HDIM, HDIM);
    ln_relu_k<<<B_SZ,256>>>(p_t2, ln_g, ln_b, pB0, pB1, pB2);
    emgemm_k<1,2><<<dim3(16, B_SZ/128), 256, SM64>>>(pB0,pB1,pB2,
        pw0+OFF_W3,pw1+OFF_W3,pw2+OFF_W3, enc_b3, nullptr, pA0,pA1,pA2, HDIM, HDIM);
    emgemm_k<0,0><<<dim3(2, BG/128), 256, SM64>>>(pA0,pA1,pA2,
        pw0+OFF_W4,pw1+OFF_W4,pw2+OFF_W4, enc_b4, p_z, nullptr,nullptr,nullptr, DDIM, DDIM);

    // ---- VQ: plain-FMA dot + reference grid + fused argmin ----
    znorm_k<<<BG/8,256>>>(p_z, p_zn);
    gemm_vqf_k<<<dim3(KCODES/128, BG/128), 256>>>(p_z, p_cbT, p_cn, p_zn, p_key, BG, KCODES, DDIM);
    idx_k<<<BG/256,256>>>(p_key, p_idx, out + IDX_OFF);
    gather_k<<<B_SZ,256>>>(p_z, cb, p_idx, pB0, pB1, pB2, p_loss, p_hist);
    finalize_k<<<1,256>>>(p_hist, p_loss, out);

    // ---- decoder (HMMA 3-product: byte-identical to R13-R15 pass) ----
    mgemm_k<128,1,2><<<dim3(8, B_SZ/128), 256, SM128>>>(pB0,pB1,pB2,
        pw0+OFF_D1,pw1+OFF_D1,pw2+OFF_D1, dec_b1, nullptr, pA0,pA1,pA2, HDIM, HDIM);
    mgemm_k<128,1,2><<<dim3(8, B_SZ/128), 256, SM128>>>(pA0,pA1,pA2,
        pw0+OFF_D2,pw1+OFF_D2,pw2+OFF_D2, dec_b2, nullptr, pB0,pB1,pB2, HDIM, HDIM);
    mgemm_k<64,0,1><<<dim3(1, B_SZ/128), 256, SM64>>>(pB0,pB1,pB2,
        pw0+OFF_D3,pw1+OFF_D3,pw2+OFF_D3, dec_b3, out + DEC_OFF, nullptr,nullptr,nullptr, STATE_NN, HDIM);
}

// round 17
// speedup vs baseline: 2.0645x; 1.1629x over previous
#include <cuda_runtime.h>
#include <cuda_bf16.h>
#include <cstdint>
#include <cmath>

#define B_SZ    32768
#define STATE_NN 64
#define HDIM    1024
#define KCODES  256
#define DDIM    128
#define GG      8
#define BG      (B_SZ*GG)
#define GD      (GG*DDIM)
#define DEC_OFF  1
#define PERP_OFF (1 + B_SZ*STATE_NN)
#define IDX_OFF  (2 + B_SZ*STATE_NN)

typedef unsigned long long u64;
typedef __nv_bfloat16 bf16;

// ---------------- device scratch ----------------
__device__ float g_t2[(size_t)B_SZ*HDIM];
__device__ float g_z [(size_t)B_SZ*GD];
__device__ u64   g_key[BG];
__device__ float g_zn[BG];
__device__ int   g_idx[BG];
__device__ int   g_hist[KCODES];
__device__ float g_cn[KCODES];
__device__ float g_cbT[DDIM*KCODES];
__device__ float g_loss[1];

__device__ __align__(16) bf16 g_bA0[(size_t)B_SZ*HDIM];
__device__ __align__(16) bf16 g_bA1[(size_t)B_SZ*HDIM];
__device__ __align__(16) bf16 g_bA2[(size_t)B_SZ*HDIM];
__device__ __align__(16) bf16 g_bB0[(size_t)B_SZ*HDIM];
__device__ __align__(16) bf16 g_bB1[(size_t)B_SZ*HDIM];
__device__ __align__(16) bf16 g_bB2[(size_t)B_SZ*HDIM];
__device__ __align__(16) bf16 g_xs0[(size_t)B_SZ*STATE_NN];
__device__ __align__(16) bf16 g_xs1[(size_t)B_SZ*STATE_NN];
__device__ __align__(16) bf16 g_xs2[(size_t)B_SZ*STATE_NN];

#define OFF_W1 0
#define OFF_W2 65536
#define OFF_W3 1114112
#define OFF_W4 2162688
#define OFF_D1 2179072
#define OFF_D2 3227648
#define OFF_D3 4276224
#define WT_TOT 4341760
__device__ __align__(16) bf16 g_wt0[WT_TOT];
__device__ __align__(16) bf16 g_wt1[WT_TOT];
__device__ __align__(16) bf16 g_wt2[WT_TOT];

// ---------------- helpers ----------------
__device__ __forceinline__ u64 pack2(float lo, float hi){
    u64 r; asm("mov.b64 %0, {%1,%2};" : "=l"(r) : "f"(lo), "f"(hi)); return r; }
__device__ __forceinline__ void unpack2(u64 v, float &lo, float &hi){
    asm("mov.b64 {%0,%1}, %2;" : "=f"(lo), "=f"(hi) : "l"(v)); }
__device__ __forceinline__ u64 ffma2(u64 a, u64 b, u64 c){
    u64 d; asm("fma.rn.f32x2 %0, %1, %2, %3;" : "=l"(d) : "l"(a), "l"(b), "l"(c)); return d; }
__device__ __forceinline__ uint32_t smem_u32(const void* p){
    uint32_t a; asm("{ .reg .u64 t; cvta.to.shared.u64 t, %1; cvt.u32.u64 %0, t; }" : "=r"(a) : "l"(p));
    return a; }
__device__ __forceinline__ void split3(float v, bf16 &h, bf16 &m, bf16 &l){
    h = __float2bfloat16(v);
    float r1 = v - __bfloat162float(h);
    m = __float2bfloat16(r1);
    l = __float2bfloat16(r1 - __bfloat162float(m)); }
__device__ __forceinline__ void wsplit2(bf16* H, bf16* M, bf16* L, size_t go, float a, float b){
    bf16 h0,m0,l0,h1,m1,l1; split3(a,h0,m0,l0); split3(b,h1,m1,l1);
    __nv_bfloat162 p;
    p.x=h0; p.y=h1; *(__nv_bfloat162*)(H+go)=p;
    p.x=m0; p.y=m1; *(__nv_bfloat162*)(M+go)=p;
    p.x=l0; p.y=l1; *(__nv_bfloat162*)(L+go)=p; }
__device__ __forceinline__ uint32_t ford(float v){
    uint32_t b = __float_as_uint(v);
    return (b & 0x80000000u) ? ~b : (b | 0x80000000u); }

#define CP16(dst, src) asm volatile("cp.async.cg.shared.global [%0], [%1], 16;" :: "r"(dst), "l"(src) : "memory")
#define CPCOMMIT       asm volatile("cp.async.commit_group;" ::: "memory")
#define CPWAIT0        asm volatile("cp.async.wait_group 0;" ::: "memory")
__device__ __forceinline__ void ldsm4(uint32_t &r0,uint32_t &r1,uint32_t &r2,uint32_t &r3,uint32_t a){
    asm volatile("ldmatrix.sync.aligned.m8n8.x4.shared.b16 {%0,%1,%2,%3}, [%4];"
        : "=r"(r0),"=r"(r1),"=r"(r2),"=r"(r3) : "r"(a)); }
__device__ __forceinline__ void mma16816(float* c, const uint32_t* a, uint32_t b0, uint32_t b1){
    asm volatile("mma.sync.aligned.m16n8k16.row.col.f32.bf16.bf16.f32 "
        "{%0,%1,%2,%3},{%4,%5,%6,%7},{%8,%9},{%0,%1,%2,%3};"
        : "+f"(c[0]),"+f"(c[1]),"+f"(c[2]),"+f"(c[3])
        : "r"(a[0]),"r"(a[1]),"r"(a[2]),"r"(a[3]), "r"(b0),"r"(b1)); }
#define SWO(r,c) ((r)*64 + (((c) ^ (((r)>>1)&3))<<4))

// =====================================================================
// ENCODER HMMA GEMM: 6-product split-acc (R14-R16 numerics), occ=2.
// =====================================================================
template<int ACT, int OUTM>
__global__ void __launch_bounds__(256,2)
emgemm_k(const bf16* __restrict__ A0,const bf16* __restrict__ A1,const bf16* __restrict__ A2,
         const bf16* __restrict__ Bb0,const bf16* __restrict__ Bb1,const bf16* __restrict__ Bb2,
         const float* __restrict__ bias, float* __restrict__ C,
         bf16* __restrict__ Ch, bf16* __restrict__ Cm, bf16* __restrict__ Cl,
         int Ncols, int K)
{
    constexpr int BN_  = 64;
    constexpr int MT   = 2;
    constexpr int NTT  = 4;
    constexpr int ASZ  = 128*64;
    constexpr int BSZ  = BN_*64;
    constexpr int STAGE= 3*ASZ + 3*BSZ;

    extern __shared__ char smem[];
    const uint32_t sb = smem_u32(smem);
    const int tid = threadIdx.x, wid = tid>>5, lane = tid&31;
    const int wm = wid>>1, wn = wid&1;
    const int wmB = wm*32, wnB = wn*32;
    const int bCol0 = blockIdx.x*BN_;
    const int aRow0 = blockIdx.y*128;

    const bf16* Ap[3]={A0,A1,A2};
    const bf16* Bp[3]={Bb0,Bb1,Bb2};

    float a0_00[4],a0_01[4],a0_02[4],a0_03[4],a0_10[4],a0_11[4],a0_12[4],a0_13[4];
    float a1_00[4],a1_01[4],a1_02[4],a1_03[4],a1_10[4],a1_11[4],a1_12[4],a1_13[4];
#pragma unroll
    for (int q=0;q<4;q++){
        a0_00[q]=a0_01[q]=a0_02[q]=a0_03[q]=0.f;
        a0_10[q]=a0_11[q]=a0_12[q]=a0_13[q]=0.f;
        a1_00[q]=a1_01[q]=a1_02[q]=a1_03[q]=0.f;
        a1_10[q]=a1_11[q]=a1_12[q]=a1_13[q]=0.f;
    }

    auto issue = [&](int kb, int st){
        uint32_t base = sb + st*STAGE;
#pragma unroll
        for (int i0=0; i0<3*512; i0+=256){
            int i = i0 + tid;
            int l = i>>9, rem = i&511, r = rem>>2, c = rem&3;
            CP16(base + l*ASZ + SWO(r,c),
                 Ap[l] + (size_t)(aRow0+r)*K + kb + c*8);
        }
#pragma unroll
        for (int i0=0; i0<3*BN_*4; i0+=256){
            int i = i0 + tid;
            int l = i/(BN_*4), rem = i%(BN_*4), r = rem>>2, c = rem&3;
            CP16(base + 3*ASZ + l*BSZ + SWO(r,c),
                 Bp[l] + (size_t)(bCol0+r)*K + kb + c*8);
        }
        CPCOMMIT;
    };

#define EMM(ACCPFX, AL) \
    mma16816(ACCPFX##_00, af[AL][0], bfr[0][0], bfr[0][1]); \
    mma16816(ACCPFX##_01, af[AL][0], bfr[0][2], bfr[0][3]); \
    mma16816(ACCPFX##_02, af[AL][0], bfr[1][0], bfr[1][1]); \
    mma16816(ACCPFX##_03, af[AL][0], bfr[1][2], bfr[1][3]); \
    mma16816(ACCPFX##_10, af[AL][1], bfr[0][0], bfr[0][1]); \
    mma16816(ACCPFX##_11, af[AL][1], bfr[0][2], bfr[0][3]); \
    mma16816(ACCPFX##_12, af[AL][1], bfr[1][0], bfr[1][1]); \
    mma16816(ACCPFX##_13, af[AL][1], bfr[1][2], bfr[1][3]);

    const int T = K/32;
    issue(0,0);
    for (int t=0; t<T; ++t){
        CPWAIT0;
        __syncthreads();
        if (t+1 < T) issue((t+1)*32, (t+1)&1);
        const uint32_t base = sb + (t&1)*STAGE;
#pragma unroll
        for (int ks=0; ks<2; ++ks){
            uint32_t af[3][MT][4];
#pragma unroll
            for (int l=0;l<3;l++)
#pragma unroll
                for (int mt=0;mt<MT;mt++){
                    int r = wmB + mt*16 + (lane&15);
                    int c = ks*2 + (lane>>4);
                    ldsm4(af[l][mt][0],af[l][mt][1],af[l][mt][2],af[l][mt][3],
                          base + l*ASZ + SWO(r,c));
                }
            uint32_t bfr[NTT/2][4];
#pragma unroll
            for (int np=0; np<NTT/2; np++){
                int r = wnB + np*16 + ((lane>>4)<<3) + (lane&7);
                int c = ks*2 + ((lane>>3)&1);
                ldsm4(bfr[np][0],bfr[np][1],bfr[np][2],bfr[np][3],
                      base + 3*ASZ + 0*BSZ + SWO(r,c));
            }
            EMM(a0, 0)
            EMM(a1, 1)
            EMM(a1, 2)
#pragma unroll
            for (int np=0; np<NTT/2; np++){
                int r = wnB + np*16 + ((lane>>4)<<3) + (lane&7);
                int c = ks*2 + ((lane>>3)&1);
                ldsm4(bfr[np][0],bfr[np][1],bfr[np][2],bfr[np][3],
                      base + 3*ASZ + 1*BSZ + SWO(r,c));
            }
            EMM(a1, 0)
            EMM(a1, 1)
#pragma unroll
            for (int np=0; np<NTT/2; np++){
                int r = wnB + np*16 + ((lane>>4)<<3) + (lane&7);
                int c = ks*2 + ((lane>>3)&1);
                ldsm4(bfr[np][0],bfr[np][1],bfr[np][2],bfr[np][3],
                      base + 3*ASZ + 2*BSZ + SWO(r,c));
            }
            EMM(a1, 0)
        }
    }
#undef EMM

    float* a0p[2][4] = {{a0_00,a0_01,a0_02,a0_03},{a0_10,a0_11,a0_12,a0_13}};
    float* a1p[2][4] = {{a1_00,a1_01,a1_02,a1_03},{a1_10,a1_11,a1_12,a1_13}};
#pragma unroll
    for (int mt=0;mt<MT;mt++){
        int rbase = aRow0 + wmB + mt*16 + (lane>>2);
#pragma unroll
        for (int half=0; half<2; ++half){
            size_t r = (size_t)rbase + half*8;
#pragma unroll
            for (int nt=0;nt<NTT;nt++){
                int cc = bCol0 + wnB + nt*8 + (lane&3)*2;
                float v0 = (a0p[mt][nt][half*2+0] + a1p[mt][nt][half*2+0]) + bias[cc];
                float v1 = (a0p[mt][nt][half*2+1] + a1p[mt][nt][half*2+1]) + bias[cc+1];
                if (ACT==1){ v0 = fmaxf(v0,0.f); v1 = fmaxf(v1,0.f); }
                size_t go = r*(size_t)Ncols + cc;
                if (OUTM==0){ float2 o; o.x=v0; o.y=v1; *(float2*)(C+go)=o; }
                else wsplit2(Ch,Cm,Cl, go, v0, v1);
            }
        }
    }
}

// =====================================================================
// DECODER HMMA GEMM (R13-R16 numerics), 2-level stages, occ=2.
// =====================================================================
template<int BN_, int ACT, int OUTM>
__global__ void __launch_bounds__(256,2)
mgemm_k(const bf16* __restrict__ A0,const bf16* __restrict__ A1,const bf16* __restrict__ A2,
        const bf16* __restrict__ Bb0,const bf16* __restrict__ Bb1,const bf16* __restrict__ Bb2,
        const float* __restrict__ bias, float* __restrict__ C,
        bf16* __restrict__ Ch, bf16* __restrict__ Cm, bf16* __restrict__ Cl,
        int Ncols, int K)
{
    constexpr int ALEV = 2;
    constexpr int WM   = (BN_==128)?2:4;
    constexpr int WN   = 8/WM;
    constexpr int MT   = 128/(WM*16);
    constexpr int NTT  = BN_/(WN*8);
    constexpr int ASZ  = 128*64;
    constexpr int BSZ  = BN_*64;
    constexpr int STAGE= ALEV*ASZ + ALEV*BSZ;   // only 2 levels resident

    extern __shared__ char smem[];
    const uint32_t sb = smem_u32(smem);
    const int tid = threadIdx.x, wid = tid>>5, lane = tid&31;
    const int wm = (WM==2)?(wid>>2):(wid>>1);
    const int wn = (WM==2)?(wid&3):(wid&1);
    const int wmB = wm*MT*16, wnB = wn*NTT*8;
    const int bCol0 = blockIdx.x*BN_;
    const int aRow0 = blockIdx.y*128;

    const bf16* Ap[3]={A0,A1,A2};
    const bf16* Bp[3]={Bb0,Bb1,Bb2};

    float acc[MT][NTT][4];
#pragma unroll
    for (int i=0;i<MT;i++)
#pragma unroll
        for (int j=0;j<NTT;j++)
#pragma unroll
            for (int q=0;q<4;q++) acc[i][j][q]=0.f;

    auto issue = [&](int kb, int st){
        uint32_t base = sb + st*STAGE;
#pragma unroll
        for (int i0=0; i0<ALEV*512; i0+=256){
            int i = i0 + tid;
            int l = i>>9, rem = i&511, r = rem>>2, c = rem&3;
            CP16(base + l*ASZ + SWO(r,c),
                 Ap[l] + (size_t)(aRow0+r)*K + kb + c*8);
        }
#pragma unroll
        for (int i0=0; i0<ALEV*BN_*4; i0+=256){
            int i = i0 + tid;
            int l = i/(BN_*4), rem = i%(BN_*4), r = rem>>2, c = rem&3;
            CP16(base + ALEV*ASZ + l*BSZ + SWO(r,c),
                 Bp[l] + (size_t)(bCol0+r)*K + kb + c*8);
        }
        CPCOMMIT;
    };

    const int T = K/32;
    issue(0,0);
    for (int t=0; t<T; ++t){
        CPWAIT0;
        __syncthreads();
        if (t+1 < T) issue((t+1)*32, (t+1)&1);
        const uint32_t base = sb + (t&1)*STAGE;
#pragma unroll
        for (int ks=0; ks<2; ++ks){
            uint32_t af[ALEV][MT][4];
#pragma unroll
            for (int l=0;l<ALEV;l++)
#pragma unroll
                for (int mt=0;mt<MT;mt++){
                    int r = wmB + mt*16 + (lane&15);
                    int c = ks*2 + (lane>>4);
                    ldsm4(af[l][mt][0],af[l][mt][1],af[l][mt][2],af[l][mt][3],
                          base + l*ASZ + SWO(r,c));
                }
#pragma unroll
            for (int bl=0; bl<ALEV; ++bl){
                uint32_t bfr[NTT/2][4];
#pragma unroll
                for (int np=0; np<NTT/2; np++){
                    int r = wnB + np*16 + ((lane>>4)<<3) + (lane&7);
                    int c = ks*2 + ((lane>>3)&1);
                    ldsm4(bfr[np][0],bfr[np][1],bfr[np][2],bfr[np][3],
                          base + ALEV*ASZ + bl*BSZ + SWO(r,c));
                }
                const int na = (bl==0?2:1);
#pragma unroll
                for (int al=0; al<ALEV; ++al){
                    if (al < na){
#pragma unroll
                        for (int mt=0;mt<MT;mt++)
#pragma unroll
                            for (int nt=0;nt<NTT;nt++)
                                mma16816(acc[mt][nt], af[al][mt],
                                         bfr[nt>>1][(nt&1)*2], bfr[nt>>1][(nt&1)*2+1]);
                    }
                }
            }
        }
    }

#pragma unroll
    for (int mt=0;mt<MT;mt++){
        int rbase = aRow0 + wmB + mt*16 + (lane>>2);
#pragma unroll
        for (int half=0; half<2; ++half){
            size_t r = (size_t)rbase + half*8;
#pragma unroll
            for (int nt=0;nt<NTT;nt++){
                int cc = bCol0 + wnB + nt*8 + (lane&3)*2;
                float v0 = acc[mt][nt][half*2+0] + bias[cc];
                float v1 = acc[mt][nt][half*2+1] + bias[cc+1];
                if (ACT==1){ v0 = fmaxf(v0,0.f); v1 = fmaxf(v1,0.f); }
                size_t go = r*(size_t)Ncols + cc;
                if (OUTM==1){ C[go]=v0; C[go+1]=v1; }
                else wsplit2(Ch,Cm,Cl, go, v0, v1);
            }
        }
    }
}

// =====================================================================
// VQ GEMM + fused argmin (R15/R16 numerics).
// =====================================================================
__global__ void __launch_bounds__(256,2)
gemm_vqf_k(const float* __restrict__ A, const float* __restrict__ Bm,
           const float* __restrict__ cn, const float* __restrict__ zn,
           u64* __restrict__ gkey, int M, int N, int K)
{
    constexpr int BM=128, BN=128, BK=32, TM=8, TN=8;
    constexpr int MG = TM/4;
    constexpr int NG = TN/4;
    constexpr int ASTEP = (256/BM)*4;
    constexpr int ANUM  = BK/ASTEP;
    constexpr int BNUM  = (BK*BN)/(256*4);

    __shared__ float As[2][BK][BM];
    __shared__ float Bs[2][BK][BN];
    __shared__ u64 rowkey[BM];

    const int tid  = threadIdx.x;
    const int tcol = tid % (BN/TN);
    const int trow = tid / (BN/TN);
    const int aRow0 = blockIdx.y * BM;
    const int bCol0 = blockIdx.x * BN;
    const int lr = tid % BM;
    const int ls = tid / BM;

    u64 acc[TM][TN/2];
#pragma unroll
    for (int i=0;i<TM;i++)
#pragma unroll
        for (int j=0;j<TN/2;j++) acc[i][j] = 0ULL;

#pragma unroll
    for (int i=0;i<ANUM;i++) {
        int c0 = ls*4 + i*ASTEP;
        float4 v = *(const float4*)(A + (size_t)(aRow0+lr)*K + c0);
        As[0][c0+0][lr]=v.x; As[0][c0+1][lr]=v.y;
        As[0][c0+2][lr]=v.z; As[0][c0+3][lr]=v.w;
    }
#pragma unroll
    for (int it=0; it<BNUM; ++it) {
        int idx4 = (tid + it*256)*4;
        int r = idx4 / BN, c = idx4 % BN;
        *(float4*)&Bs[0][r][c] = *(const float4*)(Bm + (size_t)r*N + bCol0 + c);
    }
    if (tid < BM) rowkey[tid] = ~0ULL;
    __syncthreads();

    const int NIT = K/BK;
    for (int itk=0; itk<NIT; ++itk) {
        const int cur = itk & 1, nxt = cur ^ 1;
        const int k1 = (itk+1)*BK;
        float4 avp[ANUM], bvp[BNUM];
        if (itk+1 < NIT) {
#pragma unroll
            for (int i=0;i<ANUM;i++) {
                int c0 = ls*4 + i*ASTEP;
                avp[i] = *(const float4*)(A + (size_t)(aRow0+lr)*K + k1 + c0);
            }
#pragma unroll
            for (int it=0; it<BNUM; ++it) {
                int idx4 = (tid + it*256)*4;
                int r = idx4 / BN, c = idx4 % BN;
                bvp[it] = *(const float4*)(Bm + (size_t)(k1+r)*N + bCol0 + c);
            }
        }
#pragma unroll
        for (int kk=0; kk<BK; kk++) {
            u64 ar2[TM], br2[TN/2];
#pragma unroll
            for (int h=0; h<MG; h++) {
                float4 av = *(const float4*)&As[cur][kk][h*(BM/2) + trow*4];
                ar2[h*4+0] = pack2(av.x, av.x);
                ar2[h*4+1] = pack2(av.y, av.y);
                ar2[h*4+2] = pack2(av.z, av.z);
                ar2[h*4+3] = pack2(av.w, av.w);
            }
#pragma unroll
            for (int g=0; g<NG; g++) {
                ulonglong2 bv = *(const ulonglong2*)&Bs[cur][kk][g*(BN/2) + tcol*4];
                br2[g*2+0] = bv.x;
                br2[g*2+1] = bv.y;
            }
#pragma unroll
            for (int i=0;i<TM;i++)
#pragma unroll
                for (int j=0;j<TN/2;j++)
                    acc[i][j] = ffma2(ar2[i], br2[j], acc[i][j]);
        }
        if (itk+1 < NIT) {
#pragma unroll
            for (int i=0;i<ANUM;i++) {
                int c0 = ls*4 + i*ASTEP;
                As[nxt][c0+0][lr]=avp[i].x; As[nxt][c0+1][lr]=avp[i].y;
                As[nxt][c0+2][lr]=avp[i].z; As[nxt][c0+3][lr]=avp[i].w;
            }
#pragma unroll
            for (int it=0; it<BNUM; ++it) {
                int idx4 = (tid + it*256)*4;
                int r = idx4 / BN, c = idx4 % BN;
                *(float4*)&Bs[nxt][r][c] = bvp[it];
            }
        }
        __syncthreads();
    }

#pragma unroll
    for (int h=0; h<MG; h++) {
#pragma unroll
        for (int i=0;i<4;i++) {
            int rl = h*(BM/2) + trow*4 + i;
            size_t r = (size_t)aRow0 + rl;
            float zr = zn[r];
            u64 best = ~0ULL;
#pragma unroll
            for (int g=0; g<NG; g++) {
                int c0 = bCol0 + g*(BN/2) + tcol*4;
#pragma unroll
                for (int jp=0; jp<2; ++jp) {
                    float d0, d1;
                    unpack2(acc[h*4+i][g*2+jp], d0, d1);
                    int c = c0 + 2*jp;
                    float t0 = __fadd_rn(zr, cn[c]);
                    float t1 = __fadd_rn(zr, cn[c+1]);
                    float s0 = __fadd_rn(t0, __fmul_rn(-2.f, d0));
                    float s1 = __fadd_rn(t1, __fmul_rn(-2.f, d1));
                    u64 k0 = ((u64)ford(s0) << 32) | (u64)(uint32_t)c;
                    u64 k1 = ((u64)ford(s1) << 32) | (u64)(uint32_t)(c+1);
                    best = min(best, min(k0, k1));
                }
            }
            atomicMin(&rowkey[rl], best);
        }
    }
    __syncthreads();
    if (tid < BM) atomicMin(&gkey[aRow0 + tid], rowkey[tid]);
}

// ---------------- key init + idx extraction ----------------
__global__ void initkey_k(u64* __restrict__ gkey, float* loss, int* hist)
{
    int e = blockIdx.x*256 + threadIdx.x;
    if (e < BG) gkey[e] = ~0ULL;
    if (blockIdx.x == 0) {
        if (threadIdx.x == 0) *loss = 0.f;
        if (threadIdx.x < KCODES) hist[threadIdx.x] = 0;
    }
}
__global__ void idx_k(const u64* __restrict__ gkey, int* __restrict__ idx,
                      float* __restrict__ idx_f)
{
    int e = blockIdx.x*256 + threadIdx.x;
    if (e >= BG) return;
    int k = (int)(gkey[e] & 0xFFFFFFFFu);
    idx[e] = k;
    idx_f[e] = (float)k;
}

// ---------------- weight transpose+split / x split ----------------
__global__ void tsplit_k(const float* __restrict__ W, int Kd, int Nd,
                         bf16* __restrict__ dh, bf16* __restrict__ dm, bf16* __restrict__ dl)
{
    int e = blockIdx.x*256 + threadIdx.x;
    if (e >= Kd*Nd) return;
    int n = e / Kd, k = e % Kd;
    bf16 h,m,l; split3(W[(size_t)k*Nd + n], h,m,l);
    dh[e]=h; dm[e]=m; dl[e]=l;
}
__global__ void xsplit_k(const float* __restrict__ X, int n,
                         bf16* __restrict__ dh, bf16* __restrict__ dm, bf16* __restrict__ dl)
{
    int e = blockIdx.x*256 + threadIdx.x;
    if (e >= n) return;
    bf16 h,m,l; split3(X[e], h,m,l);
    dh[e]=h; dm[e]=m; dl[e]=l;
}

// ---------------- LayerNorm + ReLU -> bf16 splits ----------------
__global__ void ln_relu_k(const float* __restrict__ X, const float* __restrict__ gam,
                          const float* __restrict__ bet,
                          bf16* __restrict__ Yh, bf16* __restrict__ Ym, bf16* __restrict__ Yl)
{
    const int row = blockIdx.x;
    const int t   = threadIdx.x;
    __shared__ float red[8];
    __shared__ float s_mu, s_rs;

    float4 v = *(const float4*)(X + (size_t)row*HDIM + t*4);
    float s = __fadd_rn(__fadd_rn(v.x,v.y), __fadd_rn(v.z,v.w));
#pragma unroll
    for (int o=16;o;o>>=1) s = __fadd_rn(s, __shfl_xor_sync(~0u, s, o));
    if ((t&31)==0) red[t>>5] = s;
    __syncthreads();
    if (t==0) {
        float a = __fadd_rn(__fadd_rn(red[0],red[1]), __fadd_rn(red[2],red[3]));
        float b = __fadd_rn(__fadd_rn(red[4],red[5]), __fadd_rn(red[6],red[7]));
        s_mu = __fadd_rn(a,b) * (1.0f/HDIM);
    }
    __syncthreads();
    const float mu = s_mu;
    float dx=__fadd_rn(v.x,-mu), dy=__fadd_rn(v.y,-mu),
          dz=__fadd_rn(v.z,-mu), dw=__fadd_rn(v.w,-mu);
    float sq = __fadd_rn(__fadd_rn(__fmul_rn(dx,dx),__fmul_rn(dy,dy)),
                         __fadd_rn(__fmul_rn(dz,dz),__fmul_rn(dw,dw)));
#pragma unroll
    for (int o=16;o;o>>=1) sq = __fadd_rn(sq, __shfl_xor_sync(~0u, sq, o));
    if ((t&31)==0) red[t>>5] = sq;
    __syncthreads();
    if (t==0) {
        float a = __fadd_rn(__fadd_rn(red[0],red[1]), __fadd_rn(red[2],red[3]));
        float b = __fadd_rn(__fadd_rn(red[4],red[5]), __fadd_rn(red[6],red[7]));
        s_rs = rsqrtf(__fadd_rn(a,b)*(1.0f/HDIM) + 1e-5f);
    }
    __syncthreads();
    const float rs = s_rs;

    float4 g4 = *(const float4*)(gam + t*4);
    float4 b4 = *(const float4*)(bet + t*4);
    float o0 = fmaxf(__fadd_rn(__fmul_rn(__fmul_rn(dx,rs),g4.x), b4.x), 0.f);
    float o1 = fmaxf(__fadd_rn(__fmul_rn(__fmul_rn(dy,rs),g4.y), b4.y), 0.f);
    float o2 = fmaxf(__fadd_rn(__fmul_rn(__fmul_rn(dz,rs),g4.z), b4.z), 0.f);
    float o3 = fmaxf(__fadd_rn(__fmul_rn(__fmul_rn(dw,rs),g4.w), b4.w), 0.f);
    size_t go = (size_t)row*HDIM + t*4;
    wsplit2(Yh,Ym,Yl, go,   o0, o1);
    wsplit2(Yh,Ym,Yl, go+2, o2, o3);
}

// ---------------- small kernels ----------------
__global__ void znorm_k(const float* __restrict__ z, float* __restrict__ zn)
{
    int row  = blockIdx.x*8 + (threadIdx.x >> 5);
    int lane = threadIdx.x & 31;
    float4 v = *(const float4*)(z + (size_t)row*DDIM + lane*4);
    float s = __fadd_rn(__fadd_rn(__fmul_rn(v.x,v.x), __fmul_rn(v.y,v.y)),
                        __fadd_rn(__fmul_rn(v.z,v.z), __fmul_rn(v.w,v.w)));
#pragma unroll
    for (int o=16;o;o>>=1) s = __fadd_rn(s, __shfl_xor_sync(~0u, s, o));
    if (lane == 0) zn[row] = s;
}
__global__ void prep_k(const float* __restrict__ cb, float* __restrict__ cn,
                       float* __restrict__ cbT)
{
    int k = threadIdx.x;
    double s = 0.0;
    for (int d0=0; d0<DDIM; d0++) {
        float v = cb[k*DDIM + d0];
        s += (double)v * (double)v;
        cbT[d0*KCODES + k] = v;
    }
    cn[k] = (float)s;
}
__global__ void gather_k(const float* __restrict__ z, const float* __restrict__ cb,
                         const int* __restrict__ idx,
                         bf16* __restrict__ Qh, bf16* __restrict__ Qm, bf16* __restrict__ Ql,
                         float* __restrict__ loss, int* __restrict__ hist)
{
    int b = blockIdx.x;
    int t = threadIdx.x;
    __shared__ int   sidx[GG];
    __shared__ float red[8];
    if (t < GG) {
        int k = idx[b*GG + t];
        sidx[t] = k;
        atomicAdd(&hist[k], 1);
    }
    __syncthreads();
    int g = (t*4) >> 7;
    int e = (t*4) & 127;
    float4 c  = *(const float4*)(cb + (size_t)sidx[g]*DDIM + e);
    float4 zz = *(const float4*)(z  + (size_t)b*GD + t*4);
    float dx=__fadd_rn(c.x,-zz.x), dy=__fadd_rn(c.y,-zz.y),
          dz=__fadd_rn(c.z,-zz.z), dw=__fadd_rn(c.w,-zz.w);
    float st0=__fadd_rn(zz.x,dx), st1=__fadd_rn(zz.y,dy),
          st2=__fadd_rn(zz.z,dz), st3=__fadd_rn(zz.w,dw);
    size_t go = (size_t)b*GD + t*4;
    wsplit2(Qh,Qm,Ql, go,   st0, st1);
    wsplit2(Qh,Qm,Ql, go+2, st2, st3);
    float s = dx*dx+dy*dy+dz*dz+dw*dw;
#pragma unroll
    for (int o=16;o;o>>=1) s += __shfl_xor_sync(~0u, s, o);
    if ((t&31)==0) red[t>>5] = s;
    __syncthreads();
    if (t==0) {
        float tot=0.f;
#pragma unroll
        for (int i=0;i<8;i++) tot += red[i];
        atomicAdd(loss, tot);
    }
}
__global__ void finalize_k(const int* __restrict__ hist, const float* __restrict__ loss,
                           float* __restrict__ out)
{
    int t = threadIdx.x;
    __shared__ float red[8];
    float e = (float)hist[t] / (float)BG;
    float s = e * logf(e + 1e-10f);
#pragma unroll
    for (int o=16;o;o>>=1) s += __shfl_xor_sync(~0u, s, o);
    if ((t&31)==0) red[t>>5] = s;
    __syncthreads();
    if (t==0) {
        float tot=0.f;
#pragma unroll
        for (int i=0;i<8;i++) tot += red[i];
        out[PERP_OFF] = expf(-tot);
        out[0] = 1.25f * loss[0] / 33554432.0f;
    }
}

// ---------------- host launcher ----------------
extern "C" void kernel_launch(void* const* d_in, const int* in_sizes, int n_in,
                              void* d_out, int out_size)
{
    const float* x      = (const float*)d_in[0];
    const float* enc_w1 = (const float*)d_in[1];
    const float* enc_b1 = (const float*)d_in[2];
    const float* enc_w2 = (const float*)d_in[3];
    const float* enc_b2 = (const float*)d_in[4];
    const float* ln_g   = (const float*)d_in[5];
    const float* ln_b   = (const float*)d_in[6];
    const float* enc_w3 = (const float*)d_in[7];
    const float* enc_b3 = (const float*)d_in[8];
    const float* enc_w4 = (const float*)d_in[9];
    const float* enc_b4 = (const float*)d_in[10];
    const float* cb     = (const float*)d_in[11];
    const float* dec_w1 = (const float*)d_in[12];
    const float* dec_b1 = (const float*)d_in[13];
    const float* dec_w2 = (const float*)d_in[14];
    const float* dec_b2 = (const float*)d_in[15];
    const float* dec_w3 = (const float*)d_in[16];
    const float* dec_b3 = (const float*)d_in[17];
    float* out = (float*)d_out;

    static float *p_t2=nullptr,*p_z,*p_zn,*p_cn,*p_cbT,*p_loss;
    static u64 *p_key;
    static int *p_idx,*p_hist;
    static bf16 *pA0,*pA1,*pA2,*pB0,*pB1,*pB2,*px0,*px1,*px2,*pw0,*pw1,*pw2;
    if (!p_t2) {
        cudaGetSymbolAddress((void**)&p_t2,  g_t2);
        cudaGetSymbolAddress((void**)&p_z,   g_z);
        cudaGetSymbolAddress((void**)&p_key, g_key);
        cudaGetSymbolAddress((void**)&p_zn,  g_zn);
        cudaGetSymbolAddress((void**)&p_cn,  g_cn);
        cudaGetSymbolAddress((void**)&p_cbT, g_cbT);
        cudaGetSymbolAddress((void**)&p_loss,g_loss);
        cudaGetSymbolAddress((void**)&p_idx, g_idx);
        cudaGetSymbolAddress((void**)&p_hist,g_hist);
        cudaGetSymbolAddress((void**)&pA0, g_bA0);
        cudaGetSymbolAddress((void**)&pA1, g_bA1);
        cudaGetSymbolAddress((void**)&pA2, g_bA2);
        cudaGetSymbolAddress((void**)&pB0, g_bB0);
        cudaGetSymbolAddress((void**)&pB1, g_bB1);
        cudaGetSymbolAddress((void**)&pB2, g_bB2);
        cudaGetSymbolAddress((void**)&px0, g_xs0);
        cudaGetSymbolAddress((void**)&px1, g_xs1);
        cudaGetSymbolAddress((void**)&px2, g_xs2);
        cudaGetSymbolAddress((void**)&pw0, g_wt0);
        cudaGetSymbolAddress((void**)&pw1, g_wt1);
        cudaGetSymbolAddress((void**)&pw2, g_wt2);
        cudaFuncSetAttribute(emgemm_k<1,2>, cudaFuncAttributeMaxDynamicSharedMemorySize, 73728);
        cudaFuncSetAttribute(emgemm_k<0,0>, cudaFuncAttributeMaxDynamicSharedMemorySize, 73728);
        cudaFuncSetAttribute(mgemm_k<128,1,2>, cudaFuncAttributeMaxDynamicSharedMemorySize, 65536);
        cudaFuncSetAttribute(mgemm_k< 64,0,1>, cudaFuncAttributeMaxDynamicSharedMemorySize, 49152);
    }
    const int SME = 73728, SMD128 = 65536, SMD64 = 49152;

    prep_k<<<1,256>>>(cb, p_cn, p_cbT);
    initkey_k<<<BG/256,256>>>(p_key, p_loss, p_hist);

    tsplit_k<<<(64*1024+255)/256,256>>>(enc_w1, 64, 1024, pw0+OFF_W1, pw1+OFF_W1, pw2+OFF_W1);
    tsplit_k<<<(1024*1024+255)/256,256>>>(enc_w2, 1024, 1024, pw0+OFF_W2, pw1+OFF_W2, pw2+OFF_W2);
    tsplit_k<<<(1024*1024+255)/256,256>>>(enc_w3, 1024, 1024, pw0+OFF_W3, pw1+OFF_W3, pw2+OFF_W3);
    tsplit_k<<<(128*128+255)/256,256>>>(enc_w4, 128, 128, pw0+OFF_W4, pw1+OFF_W4, pw2+OFF_W4);
    tsplit_k<<<(1024*1024+255)/256,256>>>(dec_w1, 1024, 1024, pw0+OFF_D1, pw1+OFF_D1, pw2+OFF_D1);
    tsplit_k<<<(1024*1024+255)/256,256>>>(dec_w2, 1024, 1024, pw0+OFF_D2, pw1+OFF_D2, pw2+OFF_D2);
    tsplit_k<<<(1024*64+255)/256,256>>>(dec_w3, 1024, 64, pw0+OFF_D3, pw1+OFF_D3, pw2+OFF_D3);
    xsplit_k<<<(B_SZ*STATE_NN+255)/256,256>>>(x, B_SZ*STATE_NN, px0, px1, px2);

    // ---- encoder (HMMA 6-product split-acc, occ=2) ----
    emgemm_k<1,2><<<dim3(16, B_SZ/128), 256, SME>>>(px0,px1,px2,
        pw0+OFF_W1,pw1+OFF_W1,pw2+OFF_W1, enc_b1, nullptr, pA0,pA1,pA2, HDIM, 64);
    emgemm_k<0,0><<<dim3(16, B_SZ/128), 256, SME>>>(pA0,pA1,pA2,
        pw0+OFF_W2,pw1+OFF_W2,pw2+OFF_W2, enc_b2, p_t2, nullptr,nullptr,nullptr, HDIM, HDIM);
    ln_relu_k<<<B_SZ,256>>>(p_t2, ln_g, ln_b, pB0, pB1, pB2);
    emgemm_k<1,2><<<dim3(16, B_SZ/128), 256, SME>>>(pB0,pB1,pB2,
        pw0+OFF_W3,pw1+OFF_W3,pw2+OFF_W3, enc_b3, nullptr, pA0,pA1,pA2, HDIM, HDIM);
    emgemm_k<0,0><<<dim3(2, BG/128), 256, SME>>>(pA0,pA1,pA2,
        pw0+OFF_W4,pw1+OFF_W4,pw2+OFF_W4, enc_b4, p_z, nullptr,nullptr,nullptr, DDIM, DDIM);

    // ---- VQ: plain-FMA dot + reference grid + fused argmin ----
    znorm_k<<<BG/8,256>>>(p_z, p_zn);
    gemm_vqf_k<<<dim3(KCODES/128, BG/128), 256>>>(p_z, p_cbT, p_cn, p_zn, p_key, BG, KCODES, DDIM);
    idx_k<<<BG/256,256>>>(p_key, p_idx, out + IDX_OFF);
    gather_k<<<B_SZ,256>>>(p_z, cb, p_idx, pB0, pB1, pB2, p_loss, p_hist);
    finalize_k<<<1,256>>>(p_hist, p_loss, out);

    // ---- decoder (HMMA 3-product, occ=2) ----
    mgemm_k<128,1,2><<<dim3(8, B_SZ/128), 256, SMD128>>>(pB0,pB1,pB2,
        pw0+OFF_D1,pw1+OFF_D1,pw2+OFF_D1, dec_b1, nullptr, pA0,pA1,pA2, HDIM, HDIM);
    mgemm_k<128,1,2><<<dim3(8, B_SZ/128), 256, SMD128>>>(pA0,pA1,pA2,
        pw0+OFF_D2,pw1+OFF_D2,pw2+OFF_D2, dec_b2, nullptr, pB0,pB1,pB2, HDIM, HDIM);
    mgemm_k<64,0,1><<<dim3(1, B_SZ/128), 256, SMD64>>>(pB0,pB1,pB2,
        pw0+OFF_D3,pw1+OFF_D3,pw2+OFF_D3, dec_b3, out + DEC_OFF, nullptr,nullptr,nullptr, STATE_NN, HDIM);
}